// round 8
// baseline (speedup 1.0000x reference)
#include <cuda_runtime.h>
#include <cuda_bf16.h>
#include <cuda_fp16.h>
#include <mma.h>
#include <cstdint>

using namespace nvcuda;

// Problem constants (fixed by setup_inputs)
#define BB 8
#define HH 64
#define WW 64
#define TT 4096          // HH*WW
#define CC 768
#define MM (BB * TT)     // 32768
#define ELEMS (BB * TT * CC)
#define SEG 64
#define NSEG 64
#define LANES (BB * CC)  // 6144

// Shift table (24 groups of 32 channels)
__constant__ int c_dy[24] = {0, 0, 1, -1, 1, -1, 1, -1, 0, 0, 2, -2, 2, -2, 2, -2, 2, 1, 2, 1, -2, -1, -2, -1};
__constant__ int c_dx[24] = {1, -1, 0, 0, 1, -1, -1, 1, 2, -2, 0, 0, 2, -2, -2, 2, 1, 2, -1, -2, 1, 2, -1, -2};

// Scratch buffers (no cudaMalloc allowed)
__device__ __half g_xsh[ELEMS];
__device__ __half g_prod[ELEMS];
__device__ __half g_w[4][CC * CC];
__device__ float  g_k[ELEMS];
__device__ __half g_v[ELEMS];
__device__ __half g_sr[ELEMS];
__device__ __half g_v1[ELEMS];
__device__ __half g_vf[ELEMS];
// WKV segment summaries + carry-in states
__device__ float g_sp[NSEG][LANES];
__device__ float g_sq[NSEG][LANES];
__device__ float g_so[NSEG][LANES];
__device__ float g_cp[NSEG][LANES];
__device__ float g_cq[NSEG][LANES];
__device__ float g_co[NSEG][LANES];

__device__ __forceinline__ int zig(int t) {
    int r = t >> 6, j = t & 63;
    return (r << 6) + ((r & 1) ? (63 - j) : j);
}

__device__ __forceinline__ void store_h4(__half* dst, float4 v) {
    __half2 a = __floats2half2_rn(v.x, v.y);
    __half2 b = __floats2half2_rn(v.z, v.w);
    *(uint2*)dst = make_uint2(*(unsigned*)&a, *(unsigned*)&b);
}

// ---------------------------------------------------------------------------
// 1) shift (mul_shift) + zigzag reorder + f32->f16 convert, fused gather.
// ---------------------------------------------------------------------------
__global__ void shift_gather_kernel(const float* __restrict__ x, __half* __restrict__ xs)
{
    int gid = blockIdx.x * blockDim.x + threadIdx.x;       // over B*T*(C/4)
    const int CV = CC / 4;
    if (gid >= BB * TT * CV) return;
    int cv = gid % CV;
    int bt = gid / CV;
    int t  = bt % TT;
    int b  = bt / TT;
    int c  = cv * 4;

    int r   = t >> 6;
    int j   = t & 63;
    int col = (r & 1) ? (63 - j) : j;                      // order[t] = (r, col)

    int g   = c >> 5;
    int srow = r - c_dy[g];
    int scol = col - c_dx[g];

    float4 val = make_float4(0.f, 0.f, 0.f, 0.f);
    if ((unsigned)srow < (unsigned)HH && (unsigned)scol < (unsigned)WW) {
        val = *(const float4*)&x[((size_t)b * TT + srow * WW + scol) * CC + c];
    }
    store_h4(&xs[((size_t)b * TT + t) * CC + c], val);
}

// ---------------------------------------------------------------------------
// weight convert: 4 weight matrices f32 -> f16 in one launch
// ---------------------------------------------------------------------------
__global__ void wconv4_kernel(const float* __restrict__ w0, const float* __restrict__ w1,
                              const float* __restrict__ w2, const float* __restrict__ w3,
                              __half* __restrict__ wh)
{
    const int n4 = CC * CC / 4;
    int gid = blockIdx.x * blockDim.x + threadIdx.x;
    if (gid >= 4 * n4) return;
    int which = gid / n4;
    int idx   = gid % n4;
    const float* w = (which == 0) ? w0 : (which == 1) ? w1 : (which == 2) ? w2 : w3;
    store_h4(&wh[(size_t)gid * 4], ((const float4*)w)[idx]);
}

// ---------------------------------------------------------------------------
// elementwise multiply fp16: prod = sr .* vf
// ---------------------------------------------------------------------------
__global__ void ewmul_kernel(const __half* __restrict__ a, const __half* __restrict__ b,
                             __half* __restrict__ o)
{
    int gid = blockIdx.x * blockDim.x + threadIdx.x;       // over ELEMS/8
    if (gid >= ELEMS / 8) return;
    uint4 va = ((const uint4*)a)[gid];
    uint4 vb = ((const uint4*)b)[gid];
    __half2* pa = (__half2*)&va;
    __half2* pb = (__half2*)&vb;
    uint4 vo;
    __half2* po = (__half2*)&vo;
#pragma unroll
    for (int i = 0; i < 4; i++) {
        float2 fa = __half22float2(pa[i]);
        float2 fb = __half22float2(pb[i]);
        po[i] = __floats2half2_rn(fa.x * fb.x, fa.y * fb.y);
    }
    ((uint4*)o)[gid] = vo;
}

// ---------------------------------------------------------------------------
// cp.async helpers
// ---------------------------------------------------------------------------
__device__ __forceinline__ void cp_async16(void* smem, const void* gmem) {
    unsigned int s = (unsigned int)__cvta_generic_to_shared(smem);
    asm volatile("cp.async.cg.shared.global [%0], [%1], 16;\n" :: "r"(s), "l"(gmem));
}
__device__ __forceinline__ void cp_commit() { asm volatile("cp.async.commit_group;\n" ::: "memory"); }
template<int N> __device__ __forceinline__ void cp_wait() { asm volatile("cp.async.wait_group %0;\n" :: "n"(N) : "memory"); }

// ---------------------------------------------------------------------------
// 2) fp16 tensor-core GEMM, 3-stage cp.async pipeline.
//    C[m,n] = sum_k A[m,k] * W[n,k].  BM=128 BN=128 BK=32, 256 thr, 8 warps
//    (4x2), warp tile 32x64, 16x16x16 half frags, f32 accum.
//    EPI: 0 none, 1 sigmoid.  OutT: float (direct) or __half (smem-staged).
// ---------------------------------------------------------------------------
template <int EPI, typename OutT>
__global__ __launch_bounds__(256)
void gemm_fp16_kernel(const __half* __restrict__ A, const __half* __restrict__ Wt,
                      OutT* __restrict__ Co)
{
    constexpr int BM = 128, BN = 128, BK = 32, PAD = 8, STAGES = 3;
    constexpr int LD = BK + PAD;                            // 40 halfs
    constexpr int K = CC, N = CC;
    constexpr int NIT = K / BK;                             // 24

    extern __shared__ char dsm[];
    __half* Asb = (__half*)dsm;                             // STAGES*BM*LD
    __half* Bsb = (__half*)(dsm + STAGES * BM * LD * 2);
    float*  stg = (float*)dsm;                              // epilogue reuse: 128 x 132

    const int m0 = blockIdx.y * BM;
    const int n0 = blockIdx.x * BN;
    const int tid = threadIdx.x;
    const int warp = tid >> 5;
    const int wm = warp >> 1;                               // 0..3 -> 32-row slab
    const int wn = warp & 1;                                // 0..1 -> 64-col slab

    wmma::fragment<wmma::accumulator, 16, 16, 16, float> cf[2][4];
#pragma unroll
    for (int i = 0; i < 2; i++)
#pragma unroll
        for (int jn = 0; jn < 4; jn++)
            wmma::fill_fragment(cf[i][jn], 0.f);

    // loader: A tile 128x32 halfs = 256 x 16B chunks; 2 per thread (A) + 2 (B)
    auto issue_loads = [&](int st, int k0) {
        int row = tid >> 1;                                 // 0..127
        int c8  = (tid & 1) * 8;                            // 0 or 8 (halfs)
        __half* as = Asb + st * BM * LD + row * LD;
        __half* bs = Bsb + st * BM * LD + row * LD;
        const __half* ag = &A[(size_t)(m0 + row) * K + k0];
        const __half* bg = &Wt[(size_t)(n0 + row) * K + k0];
        cp_async16(as + c8,      ag + c8);
        cp_async16(bs + c8,      bg + c8);
        cp_async16(as + c8 + 16, ag + c8 + 16);
        cp_async16(bs + c8 + 16, bg + c8 + 16);
    };

    // prologue: stages 0,1
    issue_loads(0, 0);
    cp_commit();
    issue_loads(1, BK);
    cp_commit();

    for (int ch = 0; ch < NIT; ch++) {
        const int st = ch % 3;
        if (ch + 2 < NIT) {
            issue_loads((ch + 2) % 3, (ch + 2) * BK);
            cp_commit();
            cp_wait<2>();
        } else if (ch + 1 < NIT) {
            cp_wait<1>();
        } else {
            cp_wait<0>();
        }
        __syncthreads();

        const __half* as = Asb + st * BM * LD;
        const __half* bs = Bsb + st * BM * LD;
#pragma unroll
        for (int kk = 0; kk < BK; kk += 16) {
            wmma::fragment<wmma::matrix_a, 16, 16, 16, __half, wmma::row_major> af[2];
            wmma::fragment<wmma::matrix_b, 16, 16, 16, __half, wmma::col_major> bf[4];
#pragma unroll
            for (int i = 0; i < 2; i++)
                wmma::load_matrix_sync(af[i], as + (wm * 32 + i * 16) * LD + kk, LD);
#pragma unroll
            for (int jn = 0; jn < 4; jn++)
                wmma::load_matrix_sync(bf[jn], bs + (wn * 64 + jn * 16) * LD + kk, LD);
#pragma unroll
            for (int i = 0; i < 2; i++)
#pragma unroll
                for (int jn = 0; jn < 4; jn++)
                    wmma::mma_sync(cf[i][jn], af[i], bf[jn], cf[i][jn]);
        }
        __syncthreads();         // protect stage about to be overwritten
    }

    // epilogue
    if (EPI == 1) {
#pragma unroll
        for (int i = 0; i < 2; i++)
#pragma unroll
            for (int jn = 0; jn < 4; jn++)
#pragma unroll
                for (int e = 0; e < cf[i][jn].num_elements; e++)
                    cf[i][jn].x[e] = 1.f / (1.f + __expf(-cf[i][jn].x[e]));
    }

    if constexpr (sizeof(OutT) == 4) {
        // direct f32 store
#pragma unroll
        for (int i = 0; i < 2; i++)
#pragma unroll
            for (int jn = 0; jn < 4; jn++)
                wmma::store_matrix_sync(
                    (float*)&Co[(size_t)(m0 + wm * 32 + i * 16) * N + n0 + wn * 64 + jn * 16],
                    cf[i][jn], N, wmma::mem_row_major);
    } else {
        // stage f32 in smem, convert to f16, vectorized global store
        constexpr int SLD = 132;
#pragma unroll
        for (int i = 0; i < 2; i++)
#pragma unroll
            for (int jn = 0; jn < 4; jn++)
                wmma::store_matrix_sync(
                    &stg[(size_t)(wm * 32 + i * 16) * SLD + wn * 64 + jn * 16],
                    cf[i][jn], SLD, wmma::mem_row_major);
        __syncthreads();
#pragma unroll
        for (int rr = 0; rr < 8; rr++) {
            int row = rr * 16 + (tid >> 4);
            int col = (tid & 15) * 8;
            const float* s = &stg[row * SLD + col];
            __half h[8];
#pragma unroll
            for (int e = 0; e < 8; e++) h[e] = __float2half(s[e]);
            *(uint4*)&Co[(size_t)(m0 + row) * N + n0 + col] = *(uint4*)h;
        }
    }
}

// ---------------------------------------------------------------------------
// 3) WKV, chunked parallel scan. k fp32, v/y fp16.
// ---------------------------------------------------------------------------
template <int PASS>
__global__ __launch_bounds__(128)
void wkv_summary_kernel(const float* __restrict__ kk, const __half* __restrict__ vv,
                        const float* __restrict__ decay)
{
    int lane = blockIdx.x * 128 + threadIdx.x;              // 0..LANES-1
    int seg  = blockIdx.y;
    int b = lane / CC;
    int c = lane % CC;
    const float w = decay[PASS * CC + c] * (1.f / (float)TT);
    const size_t base = (size_t)b * TT * CC + c;

    float p = 0.f, q = 0.f, o = -1e38f;
#pragma unroll 8
    for (int t = 0; t < SEG; t++) {
        int tt = seg * SEG + t;
        int pidx = (PASS == 0) ? tt : zig(tt);
        size_t idx = base + (size_t)pidx * CC;
        float kt = kk[idx];
        float vt = __half2float(vv[idx]);
        float wo  = w + o;
        float no2 = fmaxf(wo, kt);
        float A2  = __expf(wo - no2);
        float B2  = __expf(kt - no2);
        p = A2 * p + B2 * vt;
        q = A2 * q + B2;
        o = no2;
    }
    g_sp[seg][lane] = p;
    g_sq[seg][lane] = q;
    g_so[seg][lane] = o;
}

template <int PASS>
__global__ __launch_bounds__(128)
void wkv_scan_kernel(const float* __restrict__ decay)
{
    int lane = blockIdx.x * 128 + threadIdx.x;
    if (lane >= LANES) return;
    int c = lane % CC;
    const float w  = decay[PASS * CC + c] * (1.f / (float)TT);
    const float wL = w * (float)SEG;

    float p = 0.f, q = 0.f, o = -1e38f;
#pragma unroll
    for (int seg = 0; seg < NSEG; seg++) {
        g_cp[seg][lane] = p;
        g_cq[seg][lane] = q;
        g_co[seg][lane] = o;
        float o1 = o + wL;
        float p2 = g_sp[seg][lane];
        float q2 = g_sq[seg][lane];
        float o2 = g_so[seg][lane];
        float no = fmaxf(o1, o2);
        float e1 = __expf(o1 - no);
        float e2 = __expf(o2 - no);
        p = e1 * p + e2 * p2;
        q = e1 * q + e2 * q2;
        o = no;
    }
}

template <int PASS>
__global__ __launch_bounds__(128)
void wkv_replay_kernel(const float* __restrict__ kk, const __half* __restrict__ vv,
                       const float* __restrict__ decay, const float* __restrict__ first,
                       __half* __restrict__ yo)
{
    int lane = blockIdx.x * 128 + threadIdx.x;
    int seg  = blockIdx.y;
    int b = lane / CC;
    int c = lane % CC;
    const float invT = 1.f / (float)TT;
    const float w = decay[PASS * CC + c] * invT;
    const float u = first[PASS * CC + c] * invT;
    const size_t base = (size_t)b * TT * CC + c;

    float p = g_cp[seg][lane];
    float q = g_cq[seg][lane];
    float o = g_co[seg][lane];

#pragma unroll 8
    for (int t = 0; t < SEG; t++) {
        int tt = seg * SEG + t;
        int pidx = (PASS == 0) ? tt : zig(tt);
        size_t idx = base + (size_t)pidx * CC;
        float kt = kk[idx];
        float vt = __half2float(vv[idx]);

        float uk = u + kt;
        float no = fmaxf(o, uk);
        float Ac = __expf(o - no);
        float Bc = __expf(uk - no);
        float y  = __fdividef(Ac * p + Bc * vt, Ac * q + Bc);
        yo[idx] = __float2half(y);

        float wo  = w + o;
        float no2 = fmaxf(wo, kt);
        float A2  = __expf(wo - no2);
        float B2  = __expf(kt - no2);
        p = A2 * p + B2 * vt;
        q = A2 * q + B2;
        o = no2;
    }
}

// ---------------------------------------------------------------------------
// Launch
// ---------------------------------------------------------------------------
extern "C" void kernel_launch(void* const* d_in, const int* in_sizes, int n_in,
                              void* d_out, int out_size)
{
    const float* x    = (const float*)d_in[0];
    const float* kw   = (const float*)d_in[1];
    const float* vw   = (const float*)d_in[2];
    const float* rw   = (const float*)d_in[3];
    const float* ow   = (const float*)d_in[4];
    const float* sdec = (const float*)d_in[5];
    const float* sfst = (const float*)d_in[6];
    float* out        = (float*)d_out;

    __half *xs, *prod, *wh, *v, *sr, *v1, *vf;
    float *k;
    cudaGetSymbolAddress((void**)&xs,   g_xsh);
    cudaGetSymbolAddress((void**)&prod, g_prod);
    cudaGetSymbolAddress((void**)&wh,   g_w);
    cudaGetSymbolAddress((void**)&k,    g_k);
    cudaGetSymbolAddress((void**)&v,    g_v);
    cudaGetSymbolAddress((void**)&sr,   g_sr);
    cudaGetSymbolAddress((void**)&v1,   g_v1);
    cudaGetSymbolAddress((void**)&vf,   g_vf);

    constexpr int DS = 128 * 132 * 4;   // >= 3-stage pipeline footprint (61440)
    cudaFuncSetAttribute(gemm_fp16_kernel<0, float>,  cudaFuncAttributeMaxDynamicSharedMemorySize, DS);
    cudaFuncSetAttribute(gemm_fp16_kernel<0, __half>, cudaFuncAttributeMaxDynamicSharedMemorySize, DS);
    cudaFuncSetAttribute(gemm_fp16_kernel<1, __half>, cudaFuncAttributeMaxDynamicSharedMemorySize, DS);

    // 1) shift + zigzag gather with fused f16 convert
    {
        int total = BB * TT * (CC / 4);
        shift_gather_kernel<<<(total + 255) / 256, 256>>>(x, xs);
    }
    // weight converts (single launch)
    {
        int total = CC * CC;           // 4 * CC*CC/4
        wconv4_kernel<<<(total + 255) / 256, 256>>>(kw, vw, rw, ow, wh);
    }

    // 2) k (f32 out), v (f16), sr (f16 + sigmoid)
    {
        dim3 grid(CC / 128, MM / 128);
        gemm_fp16_kernel<0, float ><<<grid, 256, DS>>>(xs, wh + 0 * (size_t)CC * CC, k);
        gemm_fp16_kernel<0, __half><<<grid, 256, DS>>>(xs, wh + 1 * (size_t)CC * CC, v);
        gemm_fp16_kernel<1, __half><<<grid, 256, DS>>>(xs, wh + 2 * (size_t)CC * CC, sr);
    }

    // 3) WKV pass 1 (t order) then pass 2 (zigzag involution order)
    {
        dim3 gseg(LANES / 128, NSEG);
        int  gscan = LANES / 128;
        wkv_summary_kernel<0><<<gseg, 128>>>(k, v, sdec);
        wkv_scan_kernel<0><<<gscan, 128>>>(sdec);
        wkv_replay_kernel<0><<<gseg, 128>>>(k, v, sdec, sfst, v1);

        wkv_summary_kernel<1><<<gseg, 128>>>(k, v1, sdec);
        wkv_scan_kernel<1><<<gscan, 128>>>(sdec);
        wkv_replay_kernel<1><<<gseg, 128>>>(k, v1, sdec, sfst, vf);
    }

    // 4) out = (sr .* vf) @ ow^T
    {
        int total = ELEMS / 8;
        ewmul_kernel<<<(total + 255) / 256, 256>>>(sr, vf, prod);
        dim3 grid(CC / 128, MM / 128);
        gemm_fp16_kernel<0, float><<<grid, 256, DS>>>(prod, wh + 3 * (size_t)CC * CC, out);
    }
}

// round 9
// speedup vs baseline: 1.0258x; 1.0258x over previous
#include <cuda_runtime.h>
#include <cuda_bf16.h>
#include <cuda_fp16.h>
#include <mma.h>
#include <cstdint>

using namespace nvcuda;

// Problem constants (fixed by setup_inputs)
#define BB 8
#define HH 64
#define WW 64
#define TT 4096          // HH*WW
#define CC 768
#define MM (BB * TT)     // 32768
#define ELEMS (BB * TT * CC)
#define SEG 64
#define NSEG 64
#define LANES (BB * CC)  // 6144

// Shift table (24 groups of 32 channels)
__constant__ int c_dy[24] = {0, 0, 1, -1, 1, -1, 1, -1, 0, 0, 2, -2, 2, -2, 2, -2, 2, 1, 2, 1, -2, -1, -2, -1};
__constant__ int c_dx[24] = {1, -1, 0, 0, 1, -1, -1, 1, 2, -2, 0, 0, 2, -2, -2, 2, 1, 2, -1, -2, 1, 2, -1, -2};

// Scratch buffers (no cudaMalloc allowed)
__device__ __half g_xsh[ELEMS];
__device__ __half g_prod[ELEMS];
__device__ __half g_w[4][CC * CC];
__device__ float  g_k[ELEMS];
__device__ __half g_v[ELEMS];
__device__ __half g_sr[ELEMS];
__device__ __half g_v1[ELEMS];
__device__ __half g_vf[ELEMS];
// WKV segment summaries + carry-in states
__device__ float g_sp[NSEG][LANES];
__device__ float g_sq[NSEG][LANES];
__device__ float g_so[NSEG][LANES];
__device__ float g_cp[NSEG][LANES];
__device__ float g_cq[NSEG][LANES];
__device__ float g_co[NSEG][LANES];

__device__ __forceinline__ int zig(int t) {
    int r = t >> 6, j = t & 63;
    return (r << 6) + ((r & 1) ? (63 - j) : j);
}

__device__ __forceinline__ void store_h4(__half* dst, float4 v) {
    __half2 a = __floats2half2_rn(v.x, v.y);
    __half2 b = __floats2half2_rn(v.z, v.w);
    *(uint2*)dst = make_uint2(*(unsigned*)&a, *(unsigned*)&b);
}

// ---------------------------------------------------------------------------
// 1) shift (mul_shift) + zigzag reorder + f32->f16 convert, fused gather.
// ---------------------------------------------------------------------------
__global__ void shift_gather_kernel(const float* __restrict__ x, __half* __restrict__ xs)
{
    int gid = blockIdx.x * blockDim.x + threadIdx.x;       // over B*T*(C/4)
    const int CV = CC / 4;
    if (gid >= BB * TT * CV) return;
    int cv = gid % CV;
    int bt = gid / CV;
    int t  = bt % TT;
    int b  = bt / TT;
    int c  = cv * 4;

    int r   = t >> 6;
    int j   = t & 63;
    int col = (r & 1) ? (63 - j) : j;                      // order[t] = (r, col)

    int g   = c >> 5;
    int srow = r - c_dy[g];
    int scol = col - c_dx[g];

    float4 val = make_float4(0.f, 0.f, 0.f, 0.f);
    if ((unsigned)srow < (unsigned)HH && (unsigned)scol < (unsigned)WW) {
        val = *(const float4*)&x[((size_t)b * TT + srow * WW + scol) * CC + c];
    }
    store_h4(&xs[((size_t)b * TT + t) * CC + c], val);
}

// ---------------------------------------------------------------------------
// weight convert: 4 weight matrices f32 -> f16 in one launch
// ---------------------------------------------------------------------------
__global__ void wconv4_kernel(const float* __restrict__ w0, const float* __restrict__ w1,
                              const float* __restrict__ w2, const float* __restrict__ w3,
                              __half* __restrict__ wh)
{
    const int n4 = CC * CC / 4;
    int gid = blockIdx.x * blockDim.x + threadIdx.x;
    if (gid >= 4 * n4) return;
    int which = gid / n4;
    int idx   = gid % n4;
    const float* w = (which == 0) ? w0 : (which == 1) ? w1 : (which == 2) ? w2 : w3;
    store_h4(&wh[(size_t)gid * 4], ((const float4*)w)[idx]);
}

// ---------------------------------------------------------------------------
// elementwise multiply fp16: prod = sr .* vf
// ---------------------------------------------------------------------------
__global__ void ewmul_kernel(const __half* __restrict__ a, const __half* __restrict__ b,
                             __half* __restrict__ o)
{
    int gid = blockIdx.x * blockDim.x + threadIdx.x;       // over ELEMS/8
    if (gid >= ELEMS / 8) return;
    uint4 va = ((const uint4*)a)[gid];
    uint4 vb = ((const uint4*)b)[gid];
    __half2* pa = (__half2*)&va;
    __half2* pb = (__half2*)&vb;
    uint4 vo;
    __half2* po = (__half2*)&vo;
#pragma unroll
    for (int i = 0; i < 4; i++) po[i] = __hmul2(pa[i], pb[i]);
    ((uint4*)o)[gid] = vo;
}

// ---------------------------------------------------------------------------
// cp.async helpers
// ---------------------------------------------------------------------------
__device__ __forceinline__ void cp_async16(void* smem, const void* gmem) {
    unsigned int s = (unsigned int)__cvta_generic_to_shared(smem);
    asm volatile("cp.async.cg.shared.global [%0], [%1], 16;\n" :: "r"(s), "l"(gmem));
}
__device__ __forceinline__ void cp_commit() { asm volatile("cp.async.commit_group;\n" ::: "memory"); }
template<int N> __device__ __forceinline__ void cp_wait() { asm volatile("cp.async.wait_group %0;\n" :: "n"(N) : "memory"); }

// ---------------------------------------------------------------------------
// 2) fp16 tensor-core GEMM, 4-stage cp.async pipeline, ONE sync per k-iter.
//    C[m,n] = sum_k A[m,k] * W[n,k].  BM=128 BN=128 BK=32, 256 thr, 8 warps
//    (4x2), warp tile 32x64, 16x16x16 half frags, f32 accum.
//    Iteration structure: wait(stage ch) -> sync -> prefetch(ch+3, into the
//    buffer freed by the sync) -> compute(ch).
//    EPI: 0 none, 1 sigmoid.  OutT: float (direct) or __half (smem-staged).
// ---------------------------------------------------------------------------
template <int EPI, typename OutT>
__global__ __launch_bounds__(256)
void gemm_fp16_kernel(const __half* __restrict__ A, const __half* __restrict__ Wt,
                      OutT* __restrict__ Co)
{
    constexpr int BM = 128, BN = 128, BK = 32, PAD = 8, STAGES = 4;
    constexpr int LD = BK + PAD;                            // 40 halfs
    constexpr int K = CC, N = CC;
    constexpr int NIT = K / BK;                             // 24

    extern __shared__ char dsm[];
    __half* Asb = (__half*)dsm;                             // STAGES*BM*LD
    __half* Bsb = (__half*)(dsm + STAGES * BM * LD * 2);
    float*  stg = (float*)dsm;                              // epilogue reuse: 128 x 132

    const int m0 = blockIdx.y * BM;
    const int n0 = blockIdx.x * BN;
    const int tid = threadIdx.x;
    const int warp = tid >> 5;
    const int wm = warp >> 1;                               // 0..3 -> 32-row slab
    const int wn = warp & 1;                                // 0..1 -> 64-col slab

    wmma::fragment<wmma::accumulator, 16, 16, 16, float> cf[2][4];
#pragma unroll
    for (int i = 0; i < 2; i++)
#pragma unroll
        for (int jn = 0; jn < 4; jn++)
            wmma::fill_fragment(cf[i][jn], 0.f);

    // loader: A tile 128x32 halfs = 256 x 16B chunks; 2 per thread (A) + 2 (B)
    auto issue_loads = [&](int st, int k0) {
        int row = tid >> 1;                                 // 0..127
        int c8  = (tid & 1) * 8;                            // 0 or 8 (halfs)
        __half* as = Asb + st * BM * LD + row * LD;
        __half* bs = Bsb + st * BM * LD + row * LD;
        const __half* ag = &A[(size_t)(m0 + row) * K + k0];
        const __half* bg = &Wt[(size_t)(n0 + row) * K + k0];
        cp_async16(as + c8,      ag + c8);
        cp_async16(bs + c8,      bg + c8);
        cp_async16(as + c8 + 16, ag + c8 + 16);
        cp_async16(bs + c8 + 16, bg + c8 + 16);
    };

    // prologue: stages 0,1,2 in flight
    issue_loads(0, 0);
    cp_commit();
    issue_loads(1, BK);
    cp_commit();
    issue_loads(2, 2 * BK);
    cp_commit();

    for (int ch = 0; ch < NIT; ch++) {
        const int st = ch % STAGES;
        // stage 'ch' resident after this wait
        if (ch < NIT - 2)      cp_wait<2>();
        else if (ch == NIT - 2) cp_wait<1>();
        else                    cp_wait<0>();
        __syncthreads();        // all warps done with stage (ch-1); its buffer is free

        if (ch + 3 < NIT) {
            issue_loads((ch + 3) % STAGES, (ch + 3) * BK);
            cp_commit();
        }

        const __half* as = Asb + st * BM * LD;
        const __half* bs = Bsb + st * BM * LD;
#pragma unroll
        for (int kk = 0; kk < BK; kk += 16) {
            wmma::fragment<wmma::matrix_a, 16, 16, 16, __half, wmma::row_major> af[2];
            wmma::fragment<wmma::matrix_b, 16, 16, 16, __half, wmma::col_major> bf[4];
#pragma unroll
            for (int i = 0; i < 2; i++)
                wmma::load_matrix_sync(af[i], as + (wm * 32 + i * 16) * LD + kk, LD);
#pragma unroll
            for (int jn = 0; jn < 4; jn++)
                wmma::load_matrix_sync(bf[jn], bs + (wn * 64 + jn * 16) * LD + kk, LD);
#pragma unroll
            for (int i = 0; i < 2; i++)
#pragma unroll
                for (int jn = 0; jn < 4; jn++)
                    wmma::mma_sync(cf[i][jn], af[i], bf[jn], cf[i][jn]);
        }
    }

    // epilogue
    if (EPI == 1) {
#pragma unroll
        for (int i = 0; i < 2; i++)
#pragma unroll
            for (int jn = 0; jn < 4; jn++)
#pragma unroll
                for (int e = 0; e < cf[i][jn].num_elements; e++)
                    cf[i][jn].x[e] = 1.f / (1.f + __expf(-cf[i][jn].x[e]));
    }

    if constexpr (sizeof(OutT) == 4) {
        // direct f32 store
#pragma unroll
        for (int i = 0; i < 2; i++)
#pragma unroll
            for (int jn = 0; jn < 4; jn++)
                wmma::store_matrix_sync(
                    (float*)&Co[(size_t)(m0 + wm * 32 + i * 16) * N + n0 + wn * 64 + jn * 16],
                    cf[i][jn], N, wmma::mem_row_major);
    } else {
        // stage f32 in smem, convert to f16, vectorized global store
        constexpr int SLD = 132;
        __syncthreads();        // smem about to be reused; last compute must finish
#pragma unroll
        for (int i = 0; i < 2; i++)
#pragma unroll
            for (int jn = 0; jn < 4; jn++)
                wmma::store_matrix_sync(
                    &stg[(size_t)(wm * 32 + i * 16) * SLD + wn * 64 + jn * 16],
                    cf[i][jn], SLD, wmma::mem_row_major);
        __syncthreads();
#pragma unroll
        for (int rr = 0; rr < 8; rr++) {
            int row = rr * 16 + (tid >> 4);
            int col = (tid & 15) * 8;
            const float* s = &stg[row * SLD + col];
            __half h[8];
#pragma unroll
            for (int e = 0; e < 8; e++) h[e] = __float2half(s[e]);
            *(uint4*)&Co[(size_t)(m0 + row) * N + n0 + col] = *(uint4*)h;
        }
    }
}

// ---------------------------------------------------------------------------
// 3) WKV, chunked parallel scan. k fp32, v/y fp16.
// ---------------------------------------------------------------------------
template <int PASS>
__global__ __launch_bounds__(128)
void wkv_summary_kernel(const float* __restrict__ kk, const __half* __restrict__ vv,
                        const float* __restrict__ decay)
{
    int lane = blockIdx.x * 128 + threadIdx.x;              // 0..LANES-1
    int seg  = blockIdx.y;
    int b = lane / CC;
    int c = lane % CC;
    const float w = decay[PASS * CC + c] * (1.f / (float)TT);
    const size_t base = (size_t)b * TT * CC + c;

    float p = 0.f, q = 0.f, o = -1e38f;
#pragma unroll 8
    for (int t = 0; t < SEG; t++) {
        int tt = seg * SEG + t;
        int pidx = (PASS == 0) ? tt : zig(tt);
        size_t idx = base + (size_t)pidx * CC;
        float kt = kk[idx];
        float vt = __half2float(vv[idx]);
        float wo  = w + o;
        float no2 = fmaxf(wo, kt);
        float A2  = __expf(wo - no2);
        float B2  = __expf(kt - no2);
        p = A2 * p + B2 * vt;
        q = A2 * q + B2;
        o = no2;
    }
    g_sp[seg][lane] = p;
    g_sq[seg][lane] = q;
    g_so[seg][lane] = o;
}

template <int PASS>
__global__ __launch_bounds__(128)
void wkv_scan_kernel(const float* __restrict__ decay)
{
    int lane = blockIdx.x * 128 + threadIdx.x;
    if (lane >= LANES) return;
    int c = lane % CC;
    const float w  = decay[PASS * CC + c] * (1.f / (float)TT);
    const float wL = w * (float)SEG;

    float p = 0.f, q = 0.f, o = -1e38f;
#pragma unroll
    for (int seg = 0; seg < NSEG; seg++) {
        g_cp[seg][lane] = p;
        g_cq[seg][lane] = q;
        g_co[seg][lane] = o;
        float o1 = o + wL;
        float p2 = g_sp[seg][lane];
        float q2 = g_sq[seg][lane];
        float o2 = g_so[seg][lane];
        float no = fmaxf(o1, o2);
        float e1 = __expf(o1 - no);
        float e2 = __expf(o2 - no);
        p = e1 * p + e2 * p2;
        q = e1 * q + e2 * q2;
        o = no;
    }
}

template <int PASS>
__global__ __launch_bounds__(128)
void wkv_replay_kernel(const float* __restrict__ kk, const __half* __restrict__ vv,
                       const float* __restrict__ decay, const float* __restrict__ first,
                       __half* __restrict__ yo)
{
    int lane = blockIdx.x * 128 + threadIdx.x;
    int seg  = blockIdx.y;
    int b = lane / CC;
    int c = lane % CC;
    const float invT = 1.f / (float)TT;
    const float w = decay[PASS * CC + c] * invT;
    const float u = first[PASS * CC + c] * invT;
    const size_t base = (size_t)b * TT * CC + c;

    float p = g_cp[seg][lane];
    float q = g_cq[seg][lane];
    float o = g_co[seg][lane];

#pragma unroll 8
    for (int t = 0; t < SEG; t++) {
        int tt = seg * SEG + t;
        int pidx = (PASS == 0) ? tt : zig(tt);
        size_t idx = base + (size_t)pidx * CC;
        float kt = kk[idx];
        float vt = __half2float(vv[idx]);

        float uk = u + kt;
        float no = fmaxf(o, uk);
        float Ac = __expf(o - no);
        float Bc = __expf(uk - no);
        float y  = __fdividef(Ac * p + Bc * vt, Ac * q + Bc);
        yo[idx] = __float2half(y);

        float wo  = w + o;
        float no2 = fmaxf(wo, kt);
        float A2  = __expf(wo - no2);
        float B2  = __expf(kt - no2);
        p = A2 * p + B2 * vt;
        q = A2 * q + B2;
        o = no2;
    }
}

// ---------------------------------------------------------------------------
// Launch
// ---------------------------------------------------------------------------
extern "C" void kernel_launch(void* const* d_in, const int* in_sizes, int n_in,
                              void* d_out, int out_size)
{
    const float* x    = (const float*)d_in[0];
    const float* kw   = (const float*)d_in[1];
    const float* vw   = (const float*)d_in[2];
    const float* rw   = (const float*)d_in[3];
    const float* ow   = (const float*)d_in[4];
    const float* sdec = (const float*)d_in[5];
    const float* sfst = (const float*)d_in[6];
    float* out        = (float*)d_out;

    __half *xs, *prod, *wh, *v, *sr, *v1, *vf;
    float *k;
    cudaGetSymbolAddress((void**)&xs,   g_xsh);
    cudaGetSymbolAddress((void**)&prod, g_prod);
    cudaGetSymbolAddress((void**)&wh,   g_w);
    cudaGetSymbolAddress((void**)&k,    g_k);
    cudaGetSymbolAddress((void**)&v,    g_v);
    cudaGetSymbolAddress((void**)&sr,   g_sr);
    cudaGetSymbolAddress((void**)&v1,   g_v1);
    cudaGetSymbolAddress((void**)&vf,   g_vf);

    // dynamic smem: max(4-stage pipeline = 4*20480 = 81920, epilogue 128*132*4 = 67584)
    constexpr int DS = 81920;
    cudaFuncSetAttribute(gemm_fp16_kernel<0, float>,  cudaFuncAttributeMaxDynamicSharedMemorySize, DS);
    cudaFuncSetAttribute(gemm_fp16_kernel<0, __half>, cudaFuncAttributeMaxDynamicSharedMemorySize, DS);
    cudaFuncSetAttribute(gemm_fp16_kernel<1, __half>, cudaFuncAttributeMaxDynamicSharedMemorySize, DS);

    // 1) shift + zigzag gather with fused f16 convert
    {
        int total = BB * TT * (CC / 4);
        shift_gather_kernel<<<(total + 255) / 256, 256>>>(x, xs);
    }
    // weight converts (single launch)
    {
        int total = CC * CC;           // 4 * CC*CC/4
        wconv4_kernel<<<(total + 255) / 256, 256>>>(kw, vw, rw, ow, wh);
    }

    // 2) k (f32 out), v (f16), sr (f16 + sigmoid)
    {
        dim3 grid(CC / 128, MM / 128);
        gemm_fp16_kernel<0, float ><<<grid, 256, DS>>>(xs, wh + 0 * (size_t)CC * CC, k);
        gemm_fp16_kernel<0, __half><<<grid, 256, DS>>>(xs, wh + 1 * (size_t)CC * CC, v);
        gemm_fp16_kernel<1, __half><<<grid, 256, DS>>>(xs, wh + 2 * (size_t)CC * CC, sr);
    }

    // 3) WKV pass 1 (t order) then pass 2 (zigzag involution order)
    {
        dim3 gseg(LANES / 128, NSEG);
        int  gscan = LANES / 128;
        wkv_summary_kernel<0><<<gseg, 128>>>(k, v, sdec);
        wkv_scan_kernel<0><<<gscan, 128>>>(sdec);
        wkv_replay_kernel<0><<<gseg, 128>>>(k, v, sdec, sfst, v1);

        wkv_summary_kernel<1><<<gseg, 128>>>(k, v1, sdec);
        wkv_scan_kernel<1><<<gscan, 128>>>(sdec);
        wkv_replay_kernel<1><<<gseg, 128>>>(k, v1, sdec, sfst, vf);
    }

    // 4) out = (sr .* vf) @ ow^T
    {
        int total = ELEMS / 8;
        ewmul_kernel<<<(total + 255) / 256, 256>>>(sr, vf, prod);
        dim3 grid(CC / 128, MM / 128);
        gemm_fp16_kernel<0, float><<<grid, 256, DS>>>(prod, wh + 3 * (size_t)CC * CC, out);
    }
}

// round 10
// speedup vs baseline: 1.0813x; 1.0541x over previous
#include <cuda_runtime.h>
#include <cuda_bf16.h>
#include <cuda_fp16.h>
#include <mma.h>
#include <cstdint>

using namespace nvcuda;

// Problem constants (fixed by setup_inputs)
#define BB 8
#define HH 64
#define WW 64
#define TT 4096          // HH*WW
#define CC 768
#define MM (BB * TT)     // 32768
#define ELEMS (BB * TT * CC)
#define SEG 64
#define NSEG 64
#define LANES (BB * CC)  // 6144

// Shift table (24 groups of 32 channels)
__constant__ int c_dy[24] = {0, 0, 1, -1, 1, -1, 1, -1, 0, 0, 2, -2, 2, -2, 2, -2, 2, 1, 2, 1, -2, -1, -2, -1};
__constant__ int c_dx[24] = {1, -1, 0, 0, 1, -1, -1, 1, 2, -2, 0, 0, 2, -2, -2, 2, 1, 2, -1, -2, 1, 2, -1, -2};

// Scratch buffers (no cudaMalloc allowed)
__device__ __half g_xsh[ELEMS];
__device__ __half g_prod[ELEMS];
__device__ __half g_w[4][CC * CC];
__device__ float  g_k[ELEMS];
__device__ __half g_v[ELEMS];
__device__ __half g_sr[ELEMS];
__device__ __half g_v1[ELEMS];
__device__ __half g_vf[ELEMS];
// WKV segment summaries + carry-in states
__device__ float g_sp[NSEG][LANES];
__device__ float g_sq[NSEG][LANES];
__device__ float g_so[NSEG][LANES];
__device__ float g_cp[NSEG][LANES];
__device__ float g_cq[NSEG][LANES];
__device__ float g_co[NSEG][LANES];

__device__ __forceinline__ int zig(int t) {
    int r = t >> 6, j = t & 63;
    return (r << 6) + ((r & 1) ? (63 - j) : j);
}

__device__ __forceinline__ void store_h4(__half* dst, float4 v) {
    __half2 a = __floats2half2_rn(v.x, v.y);
    __half2 b = __floats2half2_rn(v.z, v.w);
    *(uint2*)dst = make_uint2(*(unsigned*)&a, *(unsigned*)&b);
}

// ---------------------------------------------------------------------------
// 1) shift (mul_shift) + zigzag reorder + f32->f16 convert, fused gather.
// ---------------------------------------------------------------------------
__global__ void shift_gather_kernel(const float* __restrict__ x, __half* __restrict__ xs)
{
    int gid = blockIdx.x * blockDim.x + threadIdx.x;       // over B*T*(C/4)
    const int CV = CC / 4;
    if (gid >= BB * TT * CV) return;
    int cv = gid % CV;
    int bt = gid / CV;
    int t  = bt % TT;
    int b  = bt / TT;
    int c  = cv * 4;

    int r   = t >> 6;
    int j   = t & 63;
    int col = (r & 1) ? (63 - j) : j;                      // order[t] = (r, col)

    int g   = c >> 5;
    int srow = r - c_dy[g];
    int scol = col - c_dx[g];

    float4 val = make_float4(0.f, 0.f, 0.f, 0.f);
    if ((unsigned)srow < (unsigned)HH && (unsigned)scol < (unsigned)WW) {
        val = *(const float4*)&x[((size_t)b * TT + srow * WW + scol) * CC + c];
    }
    store_h4(&xs[((size_t)b * TT + t) * CC + c], val);
}

// ---------------------------------------------------------------------------
// weight convert: 4 weight matrices f32 -> f16 in one launch
// ---------------------------------------------------------------------------
__global__ void wconv4_kernel(const float* __restrict__ w0, const float* __restrict__ w1,
                              const float* __restrict__ w2, const float* __restrict__ w3,
                              __half* __restrict__ wh)
{
    const int n4 = CC * CC / 4;
    int gid = blockIdx.x * blockDim.x + threadIdx.x;
    if (gid >= 4 * n4) return;
    int which = gid / n4;
    int idx   = gid % n4;
    const float* w = (which == 0) ? w0 : (which == 1) ? w1 : (which == 2) ? w2 : w3;
    store_h4(&wh[(size_t)gid * 4], ((const float4*)w)[idx]);
}

// ---------------------------------------------------------------------------
// elementwise multiply fp16: prod = sr .* vf
// ---------------------------------------------------------------------------
__global__ void ewmul_kernel(const __half* __restrict__ a, const __half* __restrict__ b,
                             __half* __restrict__ o)
{
    int gid = blockIdx.x * blockDim.x + threadIdx.x;       // over ELEMS/8
    if (gid >= ELEMS / 8) return;
    uint4 va = ((const uint4*)a)[gid];
    uint4 vb = ((const uint4*)b)[gid];
    __half2* pa = (__half2*)&va;
    __half2* pb = (__half2*)&vb;
    uint4 vo;
    __half2* po = (__half2*)&vo;
#pragma unroll
    for (int i = 0; i < 4; i++) po[i] = __hmul2(pa[i], pb[i]);
    ((uint4*)o)[gid] = vo;
}

// ---------------------------------------------------------------------------
// cp.async helpers
// ---------------------------------------------------------------------------
__device__ __forceinline__ void cp_async16(void* smem, const void* gmem) {
    unsigned int s = (unsigned int)__cvta_generic_to_shared(smem);
    asm volatile("cp.async.cg.shared.global [%0], [%1], 16;\n" :: "r"(s), "l"(gmem));
}
__device__ __forceinline__ void cp_commit() { asm volatile("cp.async.commit_group;\n" ::: "memory"); }
template<int N> __device__ __forceinline__ void cp_wait() { asm volatile("cp.async.wait_group %0;\n" :: "n"(N) : "memory"); }

// ---------------------------------------------------------------------------
// 2) fp16 tensor-core GEMM, 4-stage cp.async pipeline, 64x64 warp tiles.
//    C[m,n] = sum_k A[m,k] * W[n,k].  BM=128 BN=256 BK=32, 256 thr, 8 warps
//    arranged 2(wm) x 4(wn), warp tile 64x64, 16x16x16 half frags, f32 accum.
//    Fewer fragment loads per MMA (0.5 vs 0.75) -> mainloop no longer
//    smem-read bound.
//    EPI: 0 none, 1 sigmoid.  OutT: float (direct) or __half (smem-staged).
// ---------------------------------------------------------------------------
template <int EPI, typename OutT>
__global__ __launch_bounds__(256, 1)
void gemm_fp16_kernel(const __half* __restrict__ A, const __half* __restrict__ Wt,
                      OutT* __restrict__ Co)
{
    constexpr int BM = 128, BN = 256, BK = 32, PAD = 8, STAGES = 4;
    constexpr int LD = BK + PAD;                            // 40 halfs
    constexpr int K = CC, N = CC;
    constexpr int NIT = K / BK;                             // 24
    constexpr int ASTG = BM * LD;                           // halfs per A stage
    constexpr int BSTG = BN * LD;                           // halfs per B stage

    extern __shared__ char dsm[];
    __half* Asb = (__half*)dsm;                             // STAGES*ASTG halfs
    __half* Bsb = (__half*)(dsm + STAGES * ASTG * 2);

    const int m0 = blockIdx.y * BM;
    const int n0 = blockIdx.x * BN;
    const int tid = threadIdx.x;
    const int warp = tid >> 5;
    const int lid = tid & 31;
    const int wm = warp & 1;                                // 0..1 -> 64-row slab
    const int wn = warp >> 1;                               // 0..3 -> 64-col slab

    wmma::fragment<wmma::accumulator, 16, 16, 16, float> cf[4][4];
#pragma unroll
    for (int i = 0; i < 4; i++)
#pragma unroll
        for (int jn = 0; jn < 4; jn++)
            wmma::fill_fragment(cf[i][jn], 0.f);

    // loader per stage: A 128 rows x 4 chunks = 512; B 256 rows x 4 = 1024.
    // per thread: 2 A chunks + 4 B chunks.
    auto issue_loads = [&](int st, int k0) {
        __half* as = Asb + st * ASTG;
        __half* bs = Bsb + st * BSTG;
#pragma unroll
        for (int i = 0; i < 2; i++) {
            int idx = tid + i * 256;                        // 0..511
            int row = idx >> 2;                             // 0..127
            int c8  = (idx & 3) * 8;
            cp_async16(as + row * LD + c8, &A[(size_t)(m0 + row) * K + k0 + c8]);
        }
#pragma unroll
        for (int i = 0; i < 4; i++) {
            int idx = tid + i * 256;                        // 0..1023
            int row = idx >> 2;                             // 0..255
            int c8  = (idx & 3) * 8;
            cp_async16(bs + row * LD + c8, &Wt[(size_t)(n0 + row) * K + k0 + c8]);
        }
    };

    // prologue: stages 0,1,2 in flight
    issue_loads(0, 0);
    cp_commit();
    issue_loads(1, BK);
    cp_commit();
    issue_loads(2, 2 * BK);
    cp_commit();

    for (int ch = 0; ch < NIT; ch++) {
        const int st = ch % STAGES;
        if (ch < NIT - 2)       cp_wait<2>();
        else if (ch == NIT - 2) cp_wait<1>();
        else                    cp_wait<0>();
        __syncthreads();        // all warps done with stage (ch-1); buffer free

        if (ch + 3 < NIT) {
            issue_loads((ch + 3) % STAGES, (ch + 3) * BK);
            cp_commit();
        }

        const __half* as = Asb + st * ASTG;
        const __half* bs = Bsb + st * BSTG;
#pragma unroll
        for (int kk = 0; kk < BK; kk += 16) {
            wmma::fragment<wmma::matrix_a, 16, 16, 16, __half, wmma::row_major> af[4];
            wmma::fragment<wmma::matrix_b, 16, 16, 16, __half, wmma::col_major> bf[4];
#pragma unroll
            for (int i = 0; i < 4; i++)
                wmma::load_matrix_sync(af[i], as + (wm * 64 + i * 16) * LD + kk, LD);
#pragma unroll
            for (int jn = 0; jn < 4; jn++)
                wmma::load_matrix_sync(bf[jn], bs + (wn * 64 + jn * 16) * LD + kk, LD);
#pragma unroll
            for (int i = 0; i < 4; i++)
#pragma unroll
                for (int jn = 0; jn < 4; jn++)
                    wmma::mma_sync(cf[i][jn], af[i], bf[jn], cf[i][jn]);
        }
    }

    // epilogue
    if (EPI == 1) {
#pragma unroll
        for (int i = 0; i < 4; i++)
#pragma unroll
            for (int jn = 0; jn < 4; jn++)
#pragma unroll
                for (int e = 0; e < cf[i][jn].num_elements; e++)
                    cf[i][jn].x[e] = 1.f / (1.f + __expf(-cf[i][jn].x[e]));
    }

    if constexpr (sizeof(OutT) == 4) {
        // direct f32 stores
#pragma unroll
        for (int i = 0; i < 4; i++)
#pragma unroll
            for (int jn = 0; jn < 4; jn++)
                wmma::store_matrix_sync(
                    (float*)&Co[(size_t)(m0 + wm * 64 + i * 16) * N + n0 + wn * 64 + jn * 16],
                    cf[i][jn], N, wmma::mem_row_major);
    } else {
        // per-warp smem staging: 16 x 68 f32 strip, convert to f16, wide store
        constexpr int SLD = 68;
        __syncthreads();        // pipeline smem reuse: all compute must be done
        float* buf = (float*)dsm + warp * 16 * SLD;
#pragma unroll
        for (int i = 0; i < 4; i++) {
#pragma unroll
            for (int jn = 0; jn < 4; jn++)
                wmma::store_matrix_sync(buf + jn * 16, cf[i][jn], SLD, wmma::mem_row_major);
            __syncwarp();
#pragma unroll
            for (int rr = 0; rr < 4; rr++) {
                int row = rr * 4 + (lid >> 3);              // 0..15
                int col = (lid & 7) * 8;                    // 0..56
                const float* s = buf + row * SLD + col;
                __half h[8];
#pragma unroll
                for (int e = 0; e < 8; e++) h[e] = __float2half(s[e]);
                *(uint4*)&Co[(size_t)(m0 + wm * 64 + i * 16 + row) * N + n0 + wn * 64 + col] = *(uint4*)h;
            }
            __syncwarp();
        }
    }
}

// ---------------------------------------------------------------------------
// 3) WKV, chunked parallel scan. k fp32, v/y fp16.
// ---------------------------------------------------------------------------
template <int PASS>
__global__ __launch_bounds__(128)
void wkv_summary_kernel(const float* __restrict__ kk, const __half* __restrict__ vv,
                        const float* __restrict__ decay)
{
    int lane = blockIdx.x * 128 + threadIdx.x;              // 0..LANES-1
    int seg  = blockIdx.y;
    int b = lane / CC;
    int c = lane % CC;
    const float w = decay[PASS * CC + c] * (1.f / (float)TT);
    const size_t base = (size_t)b * TT * CC + c;

    float p = 0.f, q = 0.f, o = -1e38f;
#pragma unroll 8
    for (int t = 0; t < SEG; t++) {
        int tt = seg * SEG + t;
        int pidx = (PASS == 0) ? tt : zig(tt);
        size_t idx = base + (size_t)pidx * CC;
        float kt = kk[idx];
        float vt = __half2float(vv[idx]);
        float wo  = w + o;
        float no2 = fmaxf(wo, kt);
        float A2  = __expf(wo - no2);
        float B2  = __expf(kt - no2);
        p = A2 * p + B2 * vt;
        q = A2 * q + B2;
        o = no2;
    }
    g_sp[seg][lane] = p;
    g_sq[seg][lane] = q;
    g_so[seg][lane] = o;
}

template <int PASS>
__global__ __launch_bounds__(128)
void wkv_scan_kernel(const float* __restrict__ decay)
{
    int lane = blockIdx.x * 128 + threadIdx.x;
    if (lane >= LANES) return;
    int c = lane % CC;
    const float w  = decay[PASS * CC + c] * (1.f / (float)TT);
    const float wL = w * (float)SEG;

    float p = 0.f, q = 0.f, o = -1e38f;
#pragma unroll
    for (int seg = 0; seg < NSEG; seg++) {
        g_cp[seg][lane] = p;
        g_cq[seg][lane] = q;
        g_co[seg][lane] = o;
        float o1 = o + wL;
        float p2 = g_sp[seg][lane];
        float q2 = g_sq[seg][lane];
        float o2 = g_so[seg][lane];
        float no = fmaxf(o1, o2);
        float e1 = __expf(o1 - no);
        float e2 = __expf(o2 - no);
        p = e1 * p + e2 * p2;
        q = e1 * q + e2 * q2;
        o = no;
    }
}

template <int PASS>
__global__ __launch_bounds__(128)
void wkv_replay_kernel(const float* __restrict__ kk, const __half* __restrict__ vv,
                       const float* __restrict__ decay, const float* __restrict__ first,
                       __half* __restrict__ yo)
{
    int lane = blockIdx.x * 128 + threadIdx.x;
    int seg  = blockIdx.y;
    int b = lane / CC;
    int c = lane % CC;
    const float invT = 1.f / (float)TT;
    const float w = decay[PASS * CC + c] * invT;
    const float u = first[PASS * CC + c] * invT;
    const size_t base = (size_t)b * TT * CC + c;

    float p = g_cp[seg][lane];
    float q = g_cq[seg][lane];
    float o = g_co[seg][lane];

#pragma unroll 8
    for (int t = 0; t < SEG; t++) {
        int tt = seg * SEG + t;
        int pidx = (PASS == 0) ? tt : zig(tt);
        size_t idx = base + (size_t)pidx * CC;
        float kt = kk[idx];
        float vt = __half2float(vv[idx]);

        float uk = u + kt;
        float no = fmaxf(o, uk);
        float Ac = __expf(o - no);
        float Bc = __expf(uk - no);
        float y  = __fdividef(Ac * p + Bc * vt, Ac * q + Bc);
        yo[idx] = __float2half(y);

        float wo  = w + o;
        float no2 = fmaxf(wo, kt);
        float A2  = __expf(wo - no2);
        float B2  = __expf(kt - no2);
        p = A2 * p + B2 * vt;
        q = A2 * q + B2;
        o = no2;
    }
}

// ---------------------------------------------------------------------------
// Launch
// ---------------------------------------------------------------------------
extern "C" void kernel_launch(void* const* d_in, const int* in_sizes, int n_in,
                              void* d_out, int out_size)
{
    const float* x    = (const float*)d_in[0];
    const float* kw   = (const float*)d_in[1];
    const float* vw   = (const float*)d_in[2];
    const float* rw   = (const float*)d_in[3];
    const float* ow   = (const float*)d_in[4];
    const float* sdec = (const float*)d_in[5];
    const float* sfst = (const float*)d_in[6];
    float* out        = (float*)d_out;

    __half *xs, *prod, *wh, *v, *sr, *v1, *vf;
    float *k;
    cudaGetSymbolAddress((void**)&xs,   g_xsh);
    cudaGetSymbolAddress((void**)&prod, g_prod);
    cudaGetSymbolAddress((void**)&wh,   g_w);
    cudaGetSymbolAddress((void**)&k,    g_k);
    cudaGetSymbolAddress((void**)&v,    g_v);
    cudaGetSymbolAddress((void**)&sr,   g_sr);
    cudaGetSymbolAddress((void**)&v1,   g_v1);
    cudaGetSymbolAddress((void**)&vf,   g_vf);

    // dynamic smem: 4 stages * (128 + 256) * 40 halfs = 122880 B
    constexpr int DS = 4 * (128 + 256) * 40 * 2;
    cudaFuncSetAttribute(gemm_fp16_kernel<0, float>,  cudaFuncAttributeMaxDynamicSharedMemorySize, DS);
    cudaFuncSetAttribute(gemm_fp16_kernel<0, __half>, cudaFuncAttributeMaxDynamicSharedMemorySize, DS);
    cudaFuncSetAttribute(gemm_fp16_kernel<1, __half>, cudaFuncAttributeMaxDynamicSharedMemorySize, DS);

    // 1) shift + zigzag gather with fused f16 convert
    {
        int total = BB * TT * (CC / 4);
        shift_gather_kernel<<<(total + 255) / 256, 256>>>(x, xs);
    }
    // weight converts (single launch)
    {
        int total = CC * CC;           // 4 * CC*CC/4
        wconv4_kernel<<<(total + 255) / 256, 256>>>(kw, vw, rw, ow, wh);
    }

    // 2) k (f32 out), v (f16), sr (f16 + sigmoid)
    {
        dim3 grid(CC / 256, MM / 128);
        gemm_fp16_kernel<0, float ><<<grid, 256, DS>>>(xs, wh + 0 * (size_t)CC * CC, k);
        gemm_fp16_kernel<0, __half><<<grid, 256, DS>>>(xs, wh + 1 * (size_t)CC * CC, v);
        gemm_fp16_kernel<1, __half><<<grid, 256, DS>>>(xs, wh + 2 * (size_t)CC * CC, sr);
    }

    // 3) WKV pass 1 (t order) then pass 2 (zigzag involution order)
    {
        dim3 gseg(LANES / 128, NSEG);
        int  gscan = LANES / 128;
        wkv_summary_kernel<0><<<gseg, 128>>>(k, v, sdec);
        wkv_scan_kernel<0><<<gscan, 128>>>(sdec);
        wkv_replay_kernel<0><<<gseg, 128>>>(k, v, sdec, sfst, v1);

        wkv_summary_kernel<1><<<gseg, 128>>>(k, v1, sdec);
        wkv_scan_kernel<1><<<gscan, 128>>>(sdec);
        wkv_replay_kernel<1><<<gseg, 128>>>(k, v1, sdec, sfst, vf);
    }

    // 4) out = (sr .* vf) @ ow^T
    {
        int total = ELEMS / 8;
        ewmul_kernel<<<(total + 255) / 256, 256>>>(sr, vf, prod);
        dim3 grid(CC / 256, MM / 128);
        gemm_fp16_kernel<0, float><<<grid, 256, DS>>>(prod, wh + 3 * (size_t)CC * CC, out);
    }
}

// round 11
// speedup vs baseline: 1.1669x; 1.0791x over previous
#include <cuda_runtime.h>
#include <cuda_bf16.h>
#include <cuda_fp16.h>
#include <mma.h>
#include <cstdint>

using namespace nvcuda;

// Problem constants (fixed by setup_inputs)
#define BB 8
#define HH 64
#define WW 64
#define TT 4096          // HH*WW
#define CC 768
#define MM (BB * TT)     // 32768
#define ELEMS (BB * TT * CC)
#define SEG 64
#define NSEG 64
#define LANES (BB * CC)  // 6144

// Shift table (24 groups of 32 channels)
__constant__ int c_dy[24] = {0, 0, 1, -1, 1, -1, 1, -1, 0, 0, 2, -2, 2, -2, 2, -2, 2, 1, 2, 1, -2, -1, -2, -1};
__constant__ int c_dx[24] = {1, -1, 0, 0, 1, -1, -1, 1, 2, -2, 0, 0, 2, -2, -2, 2, 1, 2, -1, -2, 1, 2, -1, -2};

// Scratch buffers (no cudaMalloc allowed)
__device__ __half g_xsh[ELEMS];
__device__ __half g_prod[ELEMS];
__device__ __half g_w[4][CC * CC];
__device__ float  g_k[ELEMS];
__device__ __half g_v[ELEMS];
__device__ __half g_sr[ELEMS];
__device__ __half g_v1[ELEMS];
__device__ __half g_vf[ELEMS];
// WKV segment summaries + carry-in states
__device__ float g_sp[NSEG][LANES];
__device__ float g_sq[NSEG][LANES];
__device__ float g_so[NSEG][LANES];
__device__ float g_cp[NSEG][LANES];
__device__ float g_cq[NSEG][LANES];
__device__ float g_co[NSEG][LANES];

__device__ __forceinline__ int zig(int t) {
    int r = t >> 6, j = t & 63;
    return (r << 6) + ((r & 1) ? (63 - j) : j);
}

__device__ __forceinline__ void store_h4(__half* dst, float4 v) {
    __half2 a = __floats2half2_rn(v.x, v.y);
    __half2 b = __floats2half2_rn(v.z, v.w);
    *(uint2*)dst = make_uint2(*(unsigned*)&a, *(unsigned*)&b);
}

// ---------------------------------------------------------------------------
// 1) shift (mul_shift) + zigzag reorder + f32->f16 convert, fused gather.
// ---------------------------------------------------------------------------
__global__ void shift_gather_kernel(const float* __restrict__ x, __half* __restrict__ xs)
{
    int gid = blockIdx.x * blockDim.x + threadIdx.x;       // over B*T*(C/4)
    const int CV = CC / 4;
    if (gid >= BB * TT * CV) return;
    int cv = gid % CV;
    int bt = gid / CV;
    int t  = bt % TT;
    int b  = bt / TT;
    int c  = cv * 4;

    int r   = t >> 6;
    int j   = t & 63;
    int col = (r & 1) ? (63 - j) : j;                      // order[t] = (r, col)

    int g   = c >> 5;
    int srow = r - c_dy[g];
    int scol = col - c_dx[g];

    float4 val = make_float4(0.f, 0.f, 0.f, 0.f);
    if ((unsigned)srow < (unsigned)HH && (unsigned)scol < (unsigned)WW) {
        val = *(const float4*)&x[((size_t)b * TT + srow * WW + scol) * CC + c];
    }
    store_h4(&xs[((size_t)b * TT + t) * CC + c], val);
}

// ---------------------------------------------------------------------------
// weight convert: 4 weight matrices f32 -> f16 in one launch
// ---------------------------------------------------------------------------
__global__ void wconv4_kernel(const float* __restrict__ w0, const float* __restrict__ w1,
                              const float* __restrict__ w2, const float* __restrict__ w3,
                              __half* __restrict__ wh)
{
    const int n4 = CC * CC / 4;
    int gid = blockIdx.x * blockDim.x + threadIdx.x;
    if (gid >= 4 * n4) return;
    int which = gid / n4;
    int idx   = gid % n4;
    const float* w = (which == 0) ? w0 : (which == 1) ? w1 : (which == 2) ? w2 : w3;
    store_h4(&wh[(size_t)gid * 4], ((const float4*)w)[idx]);
}

// ---------------------------------------------------------------------------
// elementwise multiply fp16: prod = sr .* vf
// ---------------------------------------------------------------------------
__global__ void ewmul_kernel(const __half* __restrict__ a, const __half* __restrict__ b,
                             __half* __restrict__ o)
{
    int gid = blockIdx.x * blockDim.x + threadIdx.x;       // over ELEMS/8
    if (gid >= ELEMS / 8) return;
    uint4 va = ((const uint4*)a)[gid];
    uint4 vb = ((const uint4*)b)[gid];
    __half2* pa = (__half2*)&va;
    __half2* pb = (__half2*)&vb;
    uint4 vo;
    __half2* po = (__half2*)&vo;
#pragma unroll
    for (int i = 0; i < 4; i++) po[i] = __hmul2(pa[i], pb[i]);
    ((uint4*)o)[gid] = vo;
}

// ---------------------------------------------------------------------------
// cp.async helpers
// ---------------------------------------------------------------------------
__device__ __forceinline__ void cp_async16(void* smem, const void* gmem) {
    unsigned int s = (unsigned int)__cvta_generic_to_shared(smem);
    asm volatile("cp.async.cg.shared.global [%0], [%1], 16;\n" :: "r"(s), "l"(gmem));
}
__device__ __forceinline__ void cp_commit() { asm volatile("cp.async.commit_group;\n" ::: "memory"); }
template<int N> __device__ __forceinline__ void cp_wait() { asm volatile("cp.async.wait_group %0;\n" :: "n"(N) : "memory"); }

// ---------------------------------------------------------------------------
// 2) fp16 tensor-core GEMM, 4-stage cp.async pipeline, 64x64 warp tiles,
//    BK=64 (one __syncthreads per 4 kk-steps; 12 iterations total).
//    C[m,n] = sum_k A[m,k] * W[n,k].  BM=128 BN=256, 256 thr, 8 warps (2x4).
//    smem: 4 stages x (128+256) x 72 halfs = 221184 B (fits 227KB opt-in).
//    EPI: 0 none, 1 sigmoid.  OutT: float (direct) or __half (smem-staged).
// ---------------------------------------------------------------------------
template <int EPI, typename OutT>
__global__ __launch_bounds__(256, 1)
void gemm_fp16_kernel(const __half* __restrict__ A, const __half* __restrict__ Wt,
                      OutT* __restrict__ Co)
{
    constexpr int BM = 128, BN = 256, BK = 64, PAD = 8, STAGES = 4;
    constexpr int LD = BK + PAD;                            // 72 halfs (144B rows)
    constexpr int K = CC, N = CC;
    constexpr int NIT = K / BK;                             // 12
    constexpr int ASTG = BM * LD;                           // halfs per A stage
    constexpr int BSTG = BN * LD;                           // halfs per B stage

    extern __shared__ char dsm[];
    __half* Asb = (__half*)dsm;                             // STAGES*ASTG halfs
    __half* Bsb = (__half*)(dsm + STAGES * ASTG * 2);

    const int m0 = blockIdx.y * BM;
    const int n0 = blockIdx.x * BN;
    const int tid = threadIdx.x;
    const int warp = tid >> 5;
    const int lid = tid & 31;
    const int wm = warp & 1;                                // 0..1 -> 64-row slab
    const int wn = warp >> 1;                               // 0..3 -> 64-col slab

    wmma::fragment<wmma::accumulator, 16, 16, 16, float> cf[4][4];
#pragma unroll
    for (int i = 0; i < 4; i++)
#pragma unroll
        for (int jn = 0; jn < 4; jn++)
            wmma::fill_fragment(cf[i][jn], 0.f);

    // loader per stage: A 128 rows x 8 chunks = 1024; B 256 rows x 8 = 2048.
    // per thread: 4 A chunks + 8 B chunks (16B each).
    auto issue_loads = [&](int st, int k0) {
        __half* as = Asb + st * ASTG;
        __half* bs = Bsb + st * BSTG;
#pragma unroll
        for (int i = 0; i < 4; i++) {
            int idx = tid + i * 256;                        // 0..1023
            int row = idx >> 3;                             // 0..127
            int c8  = (idx & 7) * 8;
            cp_async16(as + row * LD + c8, &A[(size_t)(m0 + row) * K + k0 + c8]);
        }
#pragma unroll
        for (int i = 0; i < 8; i++) {
            int idx = tid + i * 256;                        // 0..2047
            int row = idx >> 3;                             // 0..255
            int c8  = (idx & 7) * 8;
            cp_async16(bs + row * LD + c8, &Wt[(size_t)(n0 + row) * K + k0 + c8]);
        }
    };

    // prologue: stages 0,1,2 in flight
    issue_loads(0, 0);
    cp_commit();
    issue_loads(1, BK);
    cp_commit();
    issue_loads(2, 2 * BK);
    cp_commit();

    for (int ch = 0; ch < NIT; ch++) {
        const int st = ch % STAGES;
        if (ch < NIT - 2)       cp_wait<2>();
        else if (ch == NIT - 2) cp_wait<1>();
        else                    cp_wait<0>();
        __syncthreads();        // all warps done with stage (ch-1); buffer free

        if (ch + 3 < NIT) {
            issue_loads((ch + 3) % STAGES, (ch + 3) * BK);
            cp_commit();
        }

        const __half* as = Asb + st * ASTG;
        const __half* bs = Bsb + st * BSTG;
#pragma unroll
        for (int kk = 0; kk < BK; kk += 16) {
            wmma::fragment<wmma::matrix_a, 16, 16, 16, __half, wmma::row_major> af[4];
            wmma::fragment<wmma::matrix_b, 16, 16, 16, __half, wmma::col_major> bf[4];
#pragma unroll
            for (int i = 0; i < 4; i++)
                wmma::load_matrix_sync(af[i], as + (wm * 64 + i * 16) * LD + kk, LD);
#pragma unroll
            for (int jn = 0; jn < 4; jn++)
                wmma::load_matrix_sync(bf[jn], bs + (wn * 64 + jn * 16) * LD + kk, LD);
#pragma unroll
            for (int i = 0; i < 4; i++)
#pragma unroll
                for (int jn = 0; jn < 4; jn++)
                    wmma::mma_sync(cf[i][jn], af[i], bf[jn], cf[i][jn]);
        }
    }

    // epilogue
    if (EPI == 1) {
#pragma unroll
        for (int i = 0; i < 4; i++)
#pragma unroll
            for (int jn = 0; jn < 4; jn++)
#pragma unroll
                for (int e = 0; e < cf[i][jn].num_elements; e++)
                    cf[i][jn].x[e] = 1.f / (1.f + __expf(-cf[i][jn].x[e]));
    }

    if constexpr (sizeof(OutT) == 4) {
        // direct f32 stores
#pragma unroll
        for (int i = 0; i < 4; i++)
#pragma unroll
            for (int jn = 0; jn < 4; jn++)
                wmma::store_matrix_sync(
                    (float*)&Co[(size_t)(m0 + wm * 64 + i * 16) * N + n0 + wn * 64 + jn * 16],
                    cf[i][jn], N, wmma::mem_row_major);
    } else {
        // per-warp smem staging: 16 x 68 f32 strip, convert to f16, wide store
        constexpr int SLD = 68;
        __syncthreads();        // pipeline smem reuse: all compute must be done
        float* buf = (float*)dsm + warp * 16 * SLD;
#pragma unroll
        for (int i = 0; i < 4; i++) {
#pragma unroll
            for (int jn = 0; jn < 4; jn++)
                wmma::store_matrix_sync(buf + jn * 16, cf[i][jn], SLD, wmma::mem_row_major);
            __syncwarp();
#pragma unroll
            for (int rr = 0; rr < 4; rr++) {
                int row = rr * 4 + (lid >> 3);              // 0..15
                int col = (lid & 7) * 8;                    // 0..56
                const float* s = buf + row * SLD + col;
                __half h[8];
#pragma unroll
                for (int e = 0; e < 8; e++) h[e] = __float2half(s[e]);
                *(uint4*)&Co[(size_t)(m0 + wm * 64 + i * 16 + row) * N + n0 + wn * 64 + col] = *(uint4*)h;
            }
            __syncwarp();
        }
    }
}

// ---------------------------------------------------------------------------
// 3) WKV, chunked parallel scan. k fp32, v/y fp16.
// ---------------------------------------------------------------------------
template <int PASS>
__global__ __launch_bounds__(128)
void wkv_summary_kernel(const float* __restrict__ kk, const __half* __restrict__ vv,
                        const float* __restrict__ decay)
{
    int lane = blockIdx.x * 128 + threadIdx.x;              // 0..LANES-1
    int seg  = blockIdx.y;
    int b = lane / CC;
    int c = lane % CC;
    const float w = decay[PASS * CC + c] * (1.f / (float)TT);
    const size_t base = (size_t)b * TT * CC + c;

    float p = 0.f, q = 0.f, o = -1e38f;
#pragma unroll 8
    for (int t = 0; t < SEG; t++) {
        int tt = seg * SEG + t;
        int pidx = (PASS == 0) ? tt : zig(tt);
        size_t idx = base + (size_t)pidx * CC;
        float kt = kk[idx];
        float vt = __half2float(vv[idx]);
        float wo  = w + o;
        float no2 = fmaxf(wo, kt);
        float A2  = __expf(wo - no2);
        float B2  = __expf(kt - no2);
        p = A2 * p + B2 * vt;
        q = A2 * q + B2;
        o = no2;
    }
    g_sp[seg][lane] = p;
    g_sq[seg][lane] = q;
    g_so[seg][lane] = o;
}

template <int PASS>
__global__ __launch_bounds__(128)
void wkv_scan_kernel(const float* __restrict__ decay)
{
    int lane = blockIdx.x * 128 + threadIdx.x;
    if (lane >= LANES) return;
    int c = lane % CC;
    const float w  = decay[PASS * CC + c] * (1.f / (float)TT);
    const float wL = w * (float)SEG;

    float p = 0.f, q = 0.f, o = -1e38f;
#pragma unroll
    for (int seg = 0; seg < NSEG; seg++) {
        g_cp[seg][lane] = p;
        g_cq[seg][lane] = q;
        g_co[seg][lane] = o;
        float o1 = o + wL;
        float p2 = g_sp[seg][lane];
        float q2 = g_sq[seg][lane];
        float o2 = g_so[seg][lane];
        float no = fmaxf(o1, o2);
        float e1 = __expf(o1 - no);
        float e2 = __expf(o2 - no);
        p = e1 * p + e2 * p2;
        q = e1 * q + e2 * q2;
        o = no;
    }
}

template <int PASS>
__global__ __launch_bounds__(128)
void wkv_replay_kernel(const float* __restrict__ kk, const __half* __restrict__ vv,
                       const float* __restrict__ decay, const float* __restrict__ first,
                       __half* __restrict__ yo)
{
    int lane = blockIdx.x * 128 + threadIdx.x;
    int seg  = blockIdx.y;
    int b = lane / CC;
    int c = lane % CC;
    const float invT = 1.f / (float)TT;
    const float w = decay[PASS * CC + c] * invT;
    const float u = first[PASS * CC + c] * invT;
    const size_t base = (size_t)b * TT * CC + c;

    float p = g_cp[seg][lane];
    float q = g_cq[seg][lane];
    float o = g_co[seg][lane];

#pragma unroll 8
    for (int t = 0; t < SEG; t++) {
        int tt = seg * SEG + t;
        int pidx = (PASS == 0) ? tt : zig(tt);
        size_t idx = base + (size_t)pidx * CC;
        float kt = kk[idx];
        float vt = __half2float(vv[idx]);

        float uk = u + kt;
        float no = fmaxf(o, uk);
        float Ac = __expf(o - no);
        float Bc = __expf(uk - no);
        float y  = __fdividef(Ac * p + Bc * vt, Ac * q + Bc);
        yo[idx] = __float2half(y);

        float wo  = w + o;
        float no2 = fmaxf(wo, kt);
        float A2  = __expf(wo - no2);
        float B2  = __expf(kt - no2);
        p = A2 * p + B2 * vt;
        q = A2 * q + B2;
        o = no2;
    }
}

// ---------------------------------------------------------------------------
// Launch
// ---------------------------------------------------------------------------
extern "C" void kernel_launch(void* const* d_in, const int* in_sizes, int n_in,
                              void* d_out, int out_size)
{
    const float* x    = (const float*)d_in[0];
    const float* kw   = (const float*)d_in[1];
    const float* vw   = (const float*)d_in[2];
    const float* rw   = (const float*)d_in[3];
    const float* ow   = (const float*)d_in[4];
    const float* sdec = (const float*)d_in[5];
    const float* sfst = (const float*)d_in[6];
    float* out        = (float*)d_out;

    __half *xs, *prod, *wh, *v, *sr, *v1, *vf;
    float *k;
    cudaGetSymbolAddress((void**)&xs,   g_xsh);
    cudaGetSymbolAddress((void**)&prod, g_prod);
    cudaGetSymbolAddress((void**)&wh,   g_w);
    cudaGetSymbolAddress((void**)&k,    g_k);
    cudaGetSymbolAddress((void**)&v,    g_v);
    cudaGetSymbolAddress((void**)&sr,   g_sr);
    cudaGetSymbolAddress((void**)&v1,   g_v1);
    cudaGetSymbolAddress((void**)&vf,   g_vf);

    // dynamic smem: 4 stages * (128 + 256) * 72 halfs * 2B = 221184 B
    constexpr int DS = 4 * (128 + 256) * 72 * 2;
    cudaFuncSetAttribute(gemm_fp16_kernel<0, float>,  cudaFuncAttributeMaxDynamicSharedMemorySize, DS);
    cudaFuncSetAttribute(gemm_fp16_kernel<0, __half>, cudaFuncAttributeMaxDynamicSharedMemorySize, DS);
    cudaFuncSetAttribute(gemm_fp16_kernel<1, __half>, cudaFuncAttributeMaxDynamicSharedMemorySize, DS);

    // 1) shift + zigzag gather with fused f16 convert
    {
        int total = BB * TT * (CC / 4);
        shift_gather_kernel<<<(total + 255) / 256, 256>>>(x, xs);
    }
    // weight converts (single launch)
    {
        int total = CC * CC;           // 4 * CC*CC/4
        wconv4_kernel<<<(total + 255) / 256, 256>>>(kw, vw, rw, ow, wh);
    }

    // 2) k (f32 out), v (f16), sr (f16 + sigmoid)
    {
        dim3 grid(CC / 256, MM / 128);
        gemm_fp16_kernel<0, float ><<<grid, 256, DS>>>(xs, wh + 0 * (size_t)CC * CC, k);
        gemm_fp16_kernel<0, __half><<<grid, 256, DS>>>(xs, wh + 1 * (size_t)CC * CC, v);
        gemm_fp16_kernel<1, __half><<<grid, 256, DS>>>(xs, wh + 2 * (size_t)CC * CC, sr);
    }

    // 3) WKV pass 1 (t order) then pass 2 (zigzag involution order)
    {
        dim3 gseg(LANES / 128, NSEG);
        int  gscan = LANES / 128;
        wkv_summary_kernel<0><<<gseg, 128>>>(k, v, sdec);
        wkv_scan_kernel<0><<<gscan, 128>>>(sdec);
        wkv_replay_kernel<0><<<gseg, 128>>>(k, v, sdec, sfst, v1);

        wkv_summary_kernel<1><<<gseg, 128>>>(k, v1, sdec);
        wkv_scan_kernel<1><<<gscan, 128>>>(sdec);
        wkv_replay_kernel<1><<<gseg, 128>>>(k, v1, sdec, sfst, vf);
    }

    // 4) out = (sr .* vf) @ ow^T
    {
        int total = ELEMS / 8;
        ewmul_kernel<<<(total + 255) / 256, 256>>>(sr, vf, prod);
        dim3 grid(CC / 256, MM / 128);
        gemm_fp16_kernel<0, float><<<grid, 256, DS>>>(prod, wh + 3 * (size_t)CC * CC, out);
    }
}

// round 12
// speedup vs baseline: 1.3044x; 1.1179x over previous
#include <cuda_runtime.h>
#include <cuda_bf16.h>
#include <cuda_fp16.h>
#include <mma.h>
#include <cstdint>

using namespace nvcuda;

// Problem constants (fixed by setup_inputs)
#define BB 8
#define HH 64
#define WW 64
#define TT 4096          // HH*WW
#define CC 768
#define MM (BB * TT)     // 32768
#define ELEMS (BB * TT * CC)
#define SEG 64
#define NSEG 64
#define LANES (BB * CC)  // 6144

// Shift table (24 groups of 32 channels)
__constant__ int c_dy[24] = {0, 0, 1, -1, 1, -1, 1, -1, 0, 0, 2, -2, 2, -2, 2, -2, 2, 1, 2, 1, -2, -1, -2, -1};
__constant__ int c_dx[24] = {1, -1, 0, 0, 1, -1, -1, 1, 2, -2, 0, 0, 2, -2, -2, 2, 1, 2, -1, -2, 1, 2, -1, -2};

// Scratch buffers (no cudaMalloc allowed)
__device__ __half g_xsh[ELEMS];
__device__ __half g_prod[ELEMS];
__device__ __half g_w[4][CC * CC];
__device__ float  g_k[ELEMS];
__device__ __half g_v[ELEMS];
__device__ __half g_sr[ELEMS];
__device__ __half g_v1[ELEMS];
__device__ __half g_vf[ELEMS];
// WKV segment summaries + carry-in states
__device__ float g_sp[NSEG][LANES];
__device__ float g_sq[NSEG][LANES];
__device__ float g_so[NSEG][LANES];
__device__ float g_cp[NSEG][LANES];
__device__ float g_cq[NSEG][LANES];
__device__ float g_co[NSEG][LANES];

__device__ __forceinline__ int zig(int t) {
    int r = t >> 6, j = t & 63;
    return (r << 6) + ((r & 1) ? (63 - j) : j);
}

__device__ __forceinline__ void store_h4(__half* dst, float4 v) {
    __half2 a = __floats2half2_rn(v.x, v.y);
    __half2 b = __floats2half2_rn(v.z, v.w);
    *(uint2*)dst = make_uint2(*(unsigned*)&a, *(unsigned*)&b);
}

// ---------------------------------------------------------------------------
// 1) shift (mul_shift) + zigzag reorder + f32->f16 convert, fused gather.
// ---------------------------------------------------------------------------
__global__ void shift_gather_kernel(const float* __restrict__ x, __half* __restrict__ xs)
{
    int gid = blockIdx.x * blockDim.x + threadIdx.x;       // over B*T*(C/4)
    const int CV = CC / 4;
    if (gid >= BB * TT * CV) return;
    int cv = gid % CV;
    int bt = gid / CV;
    int t  = bt % TT;
    int b  = bt / TT;
    int c  = cv * 4;

    int r   = t >> 6;
    int j   = t & 63;
    int col = (r & 1) ? (63 - j) : j;                      // order[t] = (r, col)

    int g   = c >> 5;
    int srow = r - c_dy[g];
    int scol = col - c_dx[g];

    float4 val = make_float4(0.f, 0.f, 0.f, 0.f);
    if ((unsigned)srow < (unsigned)HH && (unsigned)scol < (unsigned)WW) {
        val = *(const float4*)&x[((size_t)b * TT + srow * WW + scol) * CC + c];
    }
    store_h4(&xs[((size_t)b * TT + t) * CC + c], val);
}

// ---------------------------------------------------------------------------
// weight convert: 4 weight matrices f32 -> f16 in one launch
// ---------------------------------------------------------------------------
__global__ void wconv4_kernel(const float* __restrict__ w0, const float* __restrict__ w1,
                              const float* __restrict__ w2, const float* __restrict__ w3,
                              __half* __restrict__ wh)
{
    const int n4 = CC * CC / 4;
    int gid = blockIdx.x * blockDim.x + threadIdx.x;
    if (gid >= 4 * n4) return;
    int which = gid / n4;
    int idx   = gid % n4;
    const float* w = (which == 0) ? w0 : (which == 1) ? w1 : (which == 2) ? w2 : w3;
    store_h4(&wh[(size_t)gid * 4], ((const float4*)w)[idx]);
}

// ---------------------------------------------------------------------------
// elementwise multiply fp16: prod = sr .* vf
// ---------------------------------------------------------------------------
__global__ void ewmul_kernel(const __half* __restrict__ a, const __half* __restrict__ b,
                             __half* __restrict__ o)
{
    int gid = blockIdx.x * blockDim.x + threadIdx.x;       // over ELEMS/8
    if (gid >= ELEMS / 8) return;
    uint4 va = ((const uint4*)a)[gid];
    uint4 vb = ((const uint4*)b)[gid];
    __half2* pa = (__half2*)&va;
    __half2* pb = (__half2*)&vb;
    uint4 vo;
    __half2* po = (__half2*)&vo;
#pragma unroll
    for (int i = 0; i < 4; i++) po[i] = __hmul2(pa[i], pb[i]);
    ((uint4*)o)[gid] = vo;
}

// ---------------------------------------------------------------------------
// cp.async helpers
// ---------------------------------------------------------------------------
__device__ __forceinline__ void cp_async16(void* smem, const void* gmem) {
    unsigned int s = (unsigned int)__cvta_generic_to_shared(smem);
    asm volatile("cp.async.cg.shared.global [%0], [%1], 16;\n" :: "r"(s), "l"(gmem));
}
__device__ __forceinline__ void cp_commit() { asm volatile("cp.async.commit_group;\n" ::: "memory"); }
template<int N> __device__ __forceinline__ void cp_wait() { asm volatile("cp.async.wait_group %0;\n" :: "n"(N) : "memory"); }

// ---------------------------------------------------------------------------
// 2) fp16 tensor-core GEMM, 3-stage cp.async pipeline, 64x64 warp tiles,
//    BK=64, BM=128 BN=128, 128 threads (4 warps, 2x2) -> 2 CTAs per SM so
//    boundary phases of the two CTAs interleave on the SMSPs.
//    smem: 3 stages x (128+128) x 72 halfs x 2B = 110592 B (2 CTAs fit).
//    EPI: 0 none, 1 sigmoid.  OutT: float (direct) or __half (smem-staged).
// ---------------------------------------------------------------------------
template <int EPI, typename OutT>
__global__ __launch_bounds__(128, 2)
void gemm_fp16_kernel(const __half* __restrict__ A, const __half* __restrict__ Wt,
                      OutT* __restrict__ Co)
{
    constexpr int BM = 128, BN = 128, BK = 64, PAD = 8, STAGES = 3;
    constexpr int LD = BK + PAD;                            // 72 halfs (144B rows)
    constexpr int K = CC, N = CC;
    constexpr int NIT = K / BK;                             // 12
    constexpr int ASTG = BM * LD;                           // halfs per A stage
    constexpr int BSTG = BN * LD;                           // halfs per B stage

    extern __shared__ char dsm[];
    __half* Asb = (__half*)dsm;                             // STAGES*ASTG halfs
    __half* Bsb = (__half*)(dsm + STAGES * ASTG * 2);

    const int m0 = blockIdx.y * BM;
    const int n0 = blockIdx.x * BN;
    const int tid = threadIdx.x;
    const int warp = tid >> 5;
    const int lid = tid & 31;
    const int wm = warp & 1;                                // 0..1 -> 64-row slab
    const int wn = warp >> 1;                               // 0..1 -> 64-col slab

    wmma::fragment<wmma::accumulator, 16, 16, 16, float> cf[4][4];
#pragma unroll
    for (int i = 0; i < 4; i++)
#pragma unroll
        for (int jn = 0; jn < 4; jn++)
            wmma::fill_fragment(cf[i][jn], 0.f);

    // loader per stage: A 128 rows x 8 chunks = 1024; B 128 rows x 8 = 1024.
    // 128 threads: 8 A chunks + 8 B chunks per thread (16B each).
    auto issue_loads = [&](int st, int k0) {
        __half* as = Asb + st * ASTG;
        __half* bs = Bsb + st * BSTG;
#pragma unroll
        for (int i = 0; i < 8; i++) {
            int idx = tid + i * 128;                        // 0..1023
            int row = idx >> 3;                             // 0..127
            int c8  = (idx & 7) * 8;
            cp_async16(as + row * LD + c8, &A[(size_t)(m0 + row) * K + k0 + c8]);
        }
#pragma unroll
        for (int i = 0; i < 8; i++) {
            int idx = tid + i * 128;
            int row = idx >> 3;
            int c8  = (idx & 7) * 8;
            cp_async16(bs + row * LD + c8, &Wt[(size_t)(n0 + row) * K + k0 + c8]);
        }
    };

    // prologue: stages 0,1 in flight
    issue_loads(0, 0);
    cp_commit();
    issue_loads(1, BK);
    cp_commit();

    for (int ch = 0; ch < NIT; ch++) {
        const int st = ch % STAGES;
        if (ch < NIT - 1) cp_wait<1>();     // stage ch resident; ch+1 may fly
        else              cp_wait<0>();
        __syncthreads();        // all warps done with stage (ch-1); buffer free

        if (ch + 2 < NIT) {
            issue_loads((ch + 2) % STAGES, (ch + 2) * BK);
            cp_commit();
        }

        const __half* as = Asb + st * ASTG;
        const __half* bs = Bsb + st * BSTG;
#pragma unroll
        for (int kk = 0; kk < BK; kk += 16) {
            wmma::fragment<wmma::matrix_a, 16, 16, 16, __half, wmma::row_major> af[4];
            wmma::fragment<wmma::matrix_b, 16, 16, 16, __half, wmma::col_major> bf[4];
#pragma unroll
            for (int i = 0; i < 4; i++)
                wmma::load_matrix_sync(af[i], as + (wm * 64 + i * 16) * LD + kk, LD);
#pragma unroll
            for (int jn = 0; jn < 4; jn++)
                wmma::load_matrix_sync(bf[jn], bs + (wn * 64 + jn * 16) * LD + kk, LD);
#pragma unroll
            for (int i = 0; i < 4; i++)
#pragma unroll
                for (int jn = 0; jn < 4; jn++)
                    wmma::mma_sync(cf[i][jn], af[i], bf[jn], cf[i][jn]);
        }
    }

    // epilogue
    if (EPI == 1) {
#pragma unroll
        for (int i = 0; i < 4; i++)
#pragma unroll
            for (int jn = 0; jn < 4; jn++)
#pragma unroll
                for (int e = 0; e < cf[i][jn].num_elements; e++)
                    cf[i][jn].x[e] = 1.f / (1.f + __expf(-cf[i][jn].x[e]));
    }

    if constexpr (sizeof(OutT) == 4) {
        // direct f32 stores
#pragma unroll
        for (int i = 0; i < 4; i++)
#pragma unroll
            for (int jn = 0; jn < 4; jn++)
                wmma::store_matrix_sync(
                    (float*)&Co[(size_t)(m0 + wm * 64 + i * 16) * N + n0 + wn * 64 + jn * 16],
                    cf[i][jn], N, wmma::mem_row_major);
    } else {
        // per-warp smem staging: 16 x 68 f32 strip, convert to f16, wide store
        constexpr int SLD = 68;
        __syncthreads();        // pipeline smem reuse: all compute must be done
        float* buf = (float*)dsm + warp * 16 * SLD;
#pragma unroll
        for (int i = 0; i < 4; i++) {
#pragma unroll
            for (int jn = 0; jn < 4; jn++)
                wmma::store_matrix_sync(buf + jn * 16, cf[i][jn], SLD, wmma::mem_row_major);
            __syncwarp();
#pragma unroll
            for (int rr = 0; rr < 4; rr++) {
                int row = rr * 4 + (lid >> 3);              // 0..15
                int col = (lid & 7) * 8;                    // 0..56
                const float* s = buf + row * SLD + col;
                __half h[8];
#pragma unroll
                for (int e = 0; e < 8; e++) h[e] = __float2half(s[e]);
                *(uint4*)&Co[(size_t)(m0 + wm * 64 + i * 16 + row) * N + n0 + wn * 64 + col] = *(uint4*)h;
            }
            __syncwarp();
        }
    }
}

// ---------------------------------------------------------------------------
// 3) WKV, chunked parallel scan. k fp32, v/y fp16.
// ---------------------------------------------------------------------------
template <int PASS>
__global__ __launch_bounds__(128)
void wkv_summary_kernel(const float* __restrict__ kk, const __half* __restrict__ vv,
                        const float* __restrict__ decay)
{
    int lane = blockIdx.x * 128 + threadIdx.x;              // 0..LANES-1
    int seg  = blockIdx.y;
    int b = lane / CC;
    int c = lane % CC;
    const float w = decay[PASS * CC + c] * (1.f / (float)TT);
    const size_t base = (size_t)b * TT * CC + c;

    float p = 0.f, q = 0.f, o = -1e38f;
#pragma unroll 8
    for (int t = 0; t < SEG; t++) {
        int tt = seg * SEG + t;
        int pidx = (PASS == 0) ? tt : zig(tt);
        size_t idx = base + (size_t)pidx * CC;
        float kt = kk[idx];
        float vt = __half2float(vv[idx]);
        float wo  = w + o;
        float no2 = fmaxf(wo, kt);
        float A2  = __expf(wo - no2);
        float B2  = __expf(kt - no2);
        p = A2 * p + B2 * vt;
        q = A2 * q + B2;
        o = no2;
    }
    g_sp[seg][lane] = p;
    g_sq[seg][lane] = q;
    g_so[seg][lane] = o;
}

template <int PASS>
__global__ __launch_bounds__(128)
void wkv_scan_kernel(const float* __restrict__ decay)
{
    int lane = blockIdx.x * 128 + threadIdx.x;
    if (lane >= LANES) return;
    int c = lane % CC;
    const float w  = decay[PASS * CC + c] * (1.f / (float)TT);
    const float wL = w * (float)SEG;

    float p = 0.f, q = 0.f, o = -1e38f;
#pragma unroll
    for (int seg = 0; seg < NSEG; seg++) {
        g_cp[seg][lane] = p;
        g_cq[seg][lane] = q;
        g_co[seg][lane] = o;
        float o1 = o + wL;
        float p2 = g_sp[seg][lane];
        float q2 = g_sq[seg][lane];
        float o2 = g_so[seg][lane];
        float no = fmaxf(o1, o2);
        float e1 = __expf(o1 - no);
        float e2 = __expf(o2 - no);
        p = e1 * p + e2 * p2;
        q = e1 * q + e2 * q2;
        o = no;
    }
}

template <int PASS>
__global__ __launch_bounds__(128)
void wkv_replay_kernel(const float* __restrict__ kk, const __half* __restrict__ vv,
                       const float* __restrict__ decay, const float* __restrict__ first,
                       __half* __restrict__ yo)
{
    int lane = blockIdx.x * 128 + threadIdx.x;
    int seg  = blockIdx.y;
    int b = lane / CC;
    int c = lane % CC;
    const float invT = 1.f / (float)TT;
    const float w = decay[PASS * CC + c] * invT;
    const float u = first[PASS * CC + c] * invT;
    const size_t base = (size_t)b * TT * CC + c;

    float p = g_cp[seg][lane];
    float q = g_cq[seg][lane];
    float o = g_co[seg][lane];

#pragma unroll 8
    for (int t = 0; t < SEG; t++) {
        int tt = seg * SEG + t;
        int pidx = (PASS == 0) ? tt : zig(tt);
        size_t idx = base + (size_t)pidx * CC;
        float kt = kk[idx];
        float vt = __half2float(vv[idx]);

        float uk = u + kt;
        float no = fmaxf(o, uk);
        float Ac = __expf(o - no);
        float Bc = __expf(uk - no);
        float y  = __fdividef(Ac * p + Bc * vt, Ac * q + Bc);
        yo[idx] = __float2half(y);

        float wo  = w + o;
        float no2 = fmaxf(wo, kt);
        float A2  = __expf(wo - no2);
        float B2  = __expf(kt - no2);
        p = A2 * p + B2 * vt;
        q = A2 * q + B2;
        o = no2;
    }
}

// ---------------------------------------------------------------------------
// Launch
// ---------------------------------------------------------------------------
extern "C" void kernel_launch(void* const* d_in, const int* in_sizes, int n_in,
                              void* d_out, int out_size)
{
    const float* x    = (const float*)d_in[0];
    const float* kw   = (const float*)d_in[1];
    const float* vw   = (const float*)d_in[2];
    const float* rw   = (const float*)d_in[3];
    const float* ow   = (const float*)d_in[4];
    const float* sdec = (const float*)d_in[5];
    const float* sfst = (const float*)d_in[6];
    float* out        = (float*)d_out;

    __half *xs, *prod, *wh, *v, *sr, *v1, *vf;
    float *k;
    cudaGetSymbolAddress((void**)&xs,   g_xsh);
    cudaGetSymbolAddress((void**)&prod, g_prod);
    cudaGetSymbolAddress((void**)&wh,   g_w);
    cudaGetSymbolAddress((void**)&k,    g_k);
    cudaGetSymbolAddress((void**)&v,    g_v);
    cudaGetSymbolAddress((void**)&sr,   g_sr);
    cudaGetSymbolAddress((void**)&v1,   g_v1);
    cudaGetSymbolAddress((void**)&vf,   g_vf);

    // dynamic smem: 3 stages * (128 + 128) * 72 halfs * 2B = 110592 B
    constexpr int DS = 3 * (128 + 128) * 72 * 2;
    cudaFuncSetAttribute(gemm_fp16_kernel<0, float>,  cudaFuncAttributeMaxDynamicSharedMemorySize, DS);
    cudaFuncSetAttribute(gemm_fp16_kernel<0, __half>, cudaFuncAttributeMaxDynamicSharedMemorySize, DS);
    cudaFuncSetAttribute(gemm_fp16_kernel<1, __half>, cudaFuncAttributeMaxDynamicSharedMemorySize, DS);

    // 1) shift + zigzag gather with fused f16 convert
    {
        int total = BB * TT * (CC / 4);
        shift_gather_kernel<<<(total + 255) / 256, 256>>>(x, xs);
    }
    // weight converts (single launch)
    {
        int total = CC * CC;           // 4 * CC*CC/4
        wconv4_kernel<<<(total + 255) / 256, 256>>>(kw, vw, rw, ow, wh);
    }

    // 2) k (f32 out), v (f16), sr (f16 + sigmoid)
    {
        dim3 grid(CC / 128, MM / 128);
        gemm_fp16_kernel<0, float ><<<grid, 128, DS>>>(xs, wh + 0 * (size_t)CC * CC, k);
        gemm_fp16_kernel<0, __half><<<grid, 128, DS>>>(xs, wh + 1 * (size_t)CC * CC, v);
        gemm_fp16_kernel<1, __half><<<grid, 128, DS>>>(xs, wh + 2 * (size_t)CC * CC, sr);
    }

    // 3) WKV pass 1 (t order) then pass 2 (zigzag involution order)
    {
        dim3 gseg(LANES / 128, NSEG);
        int  gscan = LANES / 128;
        wkv_summary_kernel<0><<<gseg, 128>>>(k, v, sdec);
        wkv_scan_kernel<0><<<gscan, 128>>>(sdec);
        wkv_replay_kernel<0><<<gseg, 128>>>(k, v, sdec, sfst, v1);

        wkv_summary_kernel<1><<<gseg, 128>>>(k, v1, sdec);
        wkv_scan_kernel<1><<<gscan, 128>>>(sdec);
        wkv_replay_kernel<1><<<gseg, 128>>>(k, v1, sdec, sfst, vf);
    }

    // 4) out = (sr .* vf) @ ow^T
    {
        int total = ELEMS / 8;
        ewmul_kernel<<<(total + 255) / 256, 256>>>(sr, vf, prod);
        dim3 grid(CC / 128, MM / 128);
        gemm_fp16_kernel<0, float><<<grid, 128, DS>>>(prod, wh + 3 * (size_t)CC * CC, out);
    }
}

// round 13
// speedup vs baseline: 1.3784x; 1.0567x over previous
#include <cuda_runtime.h>
#include <cuda_bf16.h>
#include <cuda_fp16.h>
#include <mma.h>
#include <cstdint>

using namespace nvcuda;

// Problem constants (fixed by setup_inputs)
#define BB 8
#define HH 64
#define WW 64
#define TT 4096          // HH*WW
#define CC 768
#define MM (BB * TT)     // 32768
#define ELEMS (BB * TT * CC)
#define SEG 64
#define NSEG 64
#define LANES (BB * CC)  // 6144

// Shift table (24 groups of 32 channels)
__constant__ int c_dy[24] = {0, 0, 1, -1, 1, -1, 1, -1, 0, 0, 2, -2, 2, -2, 2, -2, 2, 1, 2, 1, -2, -1, -2, -1};
__constant__ int c_dx[24] = {1, -1, 0, 0, 1, -1, -1, 1, 2, -2, 0, 0, 2, -2, -2, 2, 1, 2, -1, -2, 1, 2, -1, -2};

// Scratch buffers (no cudaMalloc allowed)
__device__ __half g_xsh[ELEMS];
__device__ __half g_prod[ELEMS];
__device__ __half g_w[4][CC * CC];
__device__ float  g_k[ELEMS];
__device__ __half g_v[ELEMS];
__device__ __half g_sr[ELEMS];
__device__ __half g_v1[ELEMS];
// WKV segment summaries + carry-in states
__device__ float g_sp[NSEG][LANES];
__device__ float g_sq[NSEG][LANES];
__device__ float g_so[NSEG][LANES];
__device__ float g_cp[NSEG][LANES];
__device__ float g_cq[NSEG][LANES];
__device__ float g_co[NSEG][LANES];

__device__ __forceinline__ int zig(int t) {
    int r = t >> 6, j = t & 63;
    return (r << 6) + ((r & 1) ? (63 - j) : j);
}

__device__ __forceinline__ void store_h4(__half* dst, float4 v) {
    __half2 a = __floats2half2_rn(v.x, v.y);
    __half2 b = __floats2half2_rn(v.z, v.w);
    *(uint2*)dst = make_uint2(*(unsigned*)&a, *(unsigned*)&b);
}

// ---------------------------------------------------------------------------
// 1) shift (mul_shift) + zigzag reorder + f32->f16 convert, fused gather.
// ---------------------------------------------------------------------------
__global__ void shift_gather_kernel(const float* __restrict__ x, __half* __restrict__ xs)
{
    int gid = blockIdx.x * blockDim.x + threadIdx.x;       // over B*T*(C/4)
    const int CV = CC / 4;
    if (gid >= BB * TT * CV) return;
    int cv = gid % CV;
    int bt = gid / CV;
    int t  = bt % TT;
    int b  = bt / TT;
    int c  = cv * 4;

    int r   = t >> 6;
    int j   = t & 63;
    int col = (r & 1) ? (63 - j) : j;                      // order[t] = (r, col)

    int g   = c >> 5;
    int srow = r - c_dy[g];
    int scol = col - c_dx[g];

    float4 val = make_float4(0.f, 0.f, 0.f, 0.f);
    if ((unsigned)srow < (unsigned)HH && (unsigned)scol < (unsigned)WW) {
        val = *(const float4*)&x[((size_t)b * TT + srow * WW + scol) * CC + c];
    }
    store_h4(&xs[((size_t)b * TT + t) * CC + c], val);
}

// ---------------------------------------------------------------------------
// weight convert: 4 weight matrices f32 -> f16 in one launch
// ---------------------------------------------------------------------------
__global__ void wconv4_kernel(const float* __restrict__ w0, const float* __restrict__ w1,
                              const float* __restrict__ w2, const float* __restrict__ w3,
                              __half* __restrict__ wh)
{
    const int n4 = CC * CC / 4;
    int gid = blockIdx.x * blockDim.x + threadIdx.x;
    if (gid >= 4 * n4) return;
    int which = gid / n4;
    int idx   = gid % n4;
    const float* w = (which == 0) ? w0 : (which == 1) ? w1 : (which == 2) ? w2 : w3;
    store_h4(&wh[(size_t)gid * 4], ((const float4*)w)[idx]);
}

// ---------------------------------------------------------------------------
// cp.async helpers
// ---------------------------------------------------------------------------
__device__ __forceinline__ void cp_async16(void* smem, const void* gmem) {
    unsigned int s = (unsigned int)__cvta_generic_to_shared(smem);
    asm volatile("cp.async.cg.shared.global [%0], [%1], 16;\n" :: "r"(s), "l"(gmem));
}
__device__ __forceinline__ void cp_commit() { asm volatile("cp.async.commit_group;\n" ::: "memory"); }
template<int N> __device__ __forceinline__ void cp_wait() { asm volatile("cp.async.wait_group %0;\n" :: "n"(N) : "memory"); }

// ---------------------------------------------------------------------------
// GEMM core (shared by both kernels): 3-stage cp.async, BM=128 BN=128 BK=64,
// 128 threads (4 warps 2x2), warp tile 64x64, f32 accum. 2 CTAs/SM.
// ---------------------------------------------------------------------------
#define G_BM 128
#define G_BN 128
#define G_BK 64
#define G_LD 72
#define G_STAGES 3
#define G_NIT (CC / G_BK)
#define G_ASTG (G_BM * G_LD)
#define G_BSTG (G_BN * G_LD)
#define G_DS (G_STAGES * (G_BM + G_BN) * G_LD * 2)

struct GemmAcc {
    wmma::fragment<wmma::accumulator, 16, 16, 16, float> cf[4][4];
};

// Runs the mainloop: C = A[m0:(m0+128), :] x W[wrow0:(wrow0+128), :]^T
__device__ __forceinline__ void gemm_mainloop(
    const __half* __restrict__ A, const __half* __restrict__ Wt,
    int m0, int wrow0, char* dsm, GemmAcc& acc)
{
    __half* Asb = (__half*)dsm;
    __half* Bsb = (__half*)(dsm + G_STAGES * G_ASTG * 2);
    const int tid = threadIdx.x;
    const int warp = tid >> 5;
    const int wm = warp & 1;
    const int wn = warp >> 1;

#pragma unroll
    for (int i = 0; i < 4; i++)
#pragma unroll
        for (int jn = 0; jn < 4; jn++)
            wmma::fill_fragment(acc.cf[i][jn], 0.f);

    auto issue_loads = [&](int st, int k0) {
        __half* as = Asb + st * G_ASTG;
        __half* bs = Bsb + st * G_BSTG;
#pragma unroll
        for (int i = 0; i < 8; i++) {
            int idx = tid + i * 128;
            int row = idx >> 3;
            int c8  = (idx & 7) * 8;
            cp_async16(as + row * G_LD + c8, &A[(size_t)(m0 + row) * CC + k0 + c8]);
        }
#pragma unroll
        for (int i = 0; i < 8; i++) {
            int idx = tid + i * 128;
            int row = idx >> 3;
            int c8  = (idx & 7) * 8;
            cp_async16(bs + row * G_LD + c8, &Wt[(size_t)(wrow0 + row) * CC + k0 + c8]);
        }
    };

    issue_loads(0, 0);
    cp_commit();
    issue_loads(1, G_BK);
    cp_commit();

    for (int ch = 0; ch < G_NIT; ch++) {
        const int st = ch % G_STAGES;
        if (ch < G_NIT - 1) cp_wait<1>();
        else                cp_wait<0>();
        __syncthreads();

        if (ch + 2 < G_NIT) {
            issue_loads((ch + 2) % G_STAGES, (ch + 2) * G_BK);
            cp_commit();
        }

        const __half* as = Asb + st * G_ASTG;
        const __half* bs = Bsb + st * G_BSTG;
#pragma unroll
        for (int kk = 0; kk < G_BK; kk += 16) {
            wmma::fragment<wmma::matrix_a, 16, 16, 16, __half, wmma::row_major> af[4];
            wmma::fragment<wmma::matrix_b, 16, 16, 16, __half, wmma::col_major> bf[4];
#pragma unroll
            for (int i = 0; i < 4; i++)
                wmma::load_matrix_sync(af[i], as + (wm * 64 + i * 16) * G_LD + kk, G_LD);
#pragma unroll
            for (int jn = 0; jn < 4; jn++)
                wmma::load_matrix_sync(bf[jn], bs + (wn * 64 + jn * 16) * G_LD + kk, G_LD);
#pragma unroll
            for (int i = 0; i < 4; i++)
#pragma unroll
                for (int jn = 0; jn < 4; jn++)
                    wmma::mma_sync(acc.cf[i][jn], af[i], bf[jn], acc.cf[i][jn]);
        }
    }
}

// half epilogue: stage f32 per-warp in smem, convert, wide store. SIG: sigmoid.
template <int SIG>
__device__ __forceinline__ void gemm_epi_half(GemmAcc& acc, __half* Co, int m0, int n0, char* dsm)
{
    constexpr int SLD = 68;
    const int tid = threadIdx.x;
    const int warp = tid >> 5;
    const int lid = tid & 31;
    const int wm = warp & 1;
    const int wn = warp >> 1;

    if (SIG) {
#pragma unroll
        for (int i = 0; i < 4; i++)
#pragma unroll
            for (int jn = 0; jn < 4; jn++)
#pragma unroll
                for (int e = 0; e < acc.cf[i][jn].num_elements; e++)
                    acc.cf[i][jn].x[e] = 1.f / (1.f + __expf(-acc.cf[i][jn].x[e]));
    }
    __syncthreads();
    float* buf = (float*)dsm + warp * 16 * SLD;
#pragma unroll
    for (int i = 0; i < 4; i++) {
#pragma unroll
        for (int jn = 0; jn < 4; jn++)
            wmma::store_matrix_sync(buf + jn * 16, acc.cf[i][jn], SLD, wmma::mem_row_major);
        __syncwarp();
#pragma unroll
        for (int rr = 0; rr < 4; rr++) {
            int row = rr * 4 + (lid >> 3);
            int col = (lid & 7) * 8;
            const float* s = buf + row * SLD + col;
            __half h[8];
#pragma unroll
            for (int e = 0; e < 8; e++) h[e] = __float2half(s[e]);
            *(uint4*)&Co[(size_t)(m0 + wm * 64 + i * 16 + row) * CC + n0 + wn * 64 + col] = *(uint4*)h;
        }
        __syncwarp();
    }
}

__device__ __forceinline__ void gemm_epi_float(GemmAcc& acc, float* Co, int m0, int n0)
{
    const int warp = threadIdx.x >> 5;
    const int wm = warp & 1;
    const int wn = warp >> 1;
#pragma unroll
    for (int i = 0; i < 4; i++)
#pragma unroll
        for (int jn = 0; jn < 4; jn++)
            wmma::store_matrix_sync(
                &Co[(size_t)(m0 + wm * 64 + i * 16) * CC + n0 + wn * 64 + jn * 16],
                acc.cf[i][jn], CC, wmma::mem_row_major);
}

// ---------------------------------------------------------------------------
// 2a) fused k/v/sr GEMM: one launch, N=2304. blockIdx.x: 0-5 -> k (f32),
//     6-11 -> v (f16), 12-17 -> sr (f16 + sigmoid).
// ---------------------------------------------------------------------------
__global__ __launch_bounds__(128, 2)
void gemm_kvsr_kernel(const __half* __restrict__ A, const __half* __restrict__ Wall,
                      float* __restrict__ Ko, __half* __restrict__ Vo, __half* __restrict__ SRo)
{
    extern __shared__ char dsm[];
    const int which = blockIdx.x / 6;
    const int n0 = (blockIdx.x % 6) * G_BN;
    const int m0 = blockIdx.y * G_BM;

    GemmAcc acc;
    gemm_mainloop(A, Wall, m0, which * CC + n0, dsm, acc);

    if (which == 0)      gemm_epi_float(acc, Ko, m0, n0);
    else if (which == 1) gemm_epi_half<0>(acc, Vo, m0, n0, dsm);
    else                 gemm_epi_half<1>(acc, SRo, m0, n0, dsm);
}

// ---------------------------------------------------------------------------
// 2b) output GEMM: out = prod @ ow^T (f32 out)
// ---------------------------------------------------------------------------
__global__ __launch_bounds__(128, 2)
void gemm_out_kernel(const __half* __restrict__ A, const __half* __restrict__ Wt,
                     float* __restrict__ Co)
{
    extern __shared__ char dsm[];
    const int n0 = blockIdx.x * G_BN;
    const int m0 = blockIdx.y * G_BM;
    GemmAcc acc;
    gemm_mainloop(A, Wt, m0, n0, dsm, acc);
    gemm_epi_float(acc, Co, m0, n0);
}

// ---------------------------------------------------------------------------
// 3) WKV, chunked parallel scan. k fp32, v/y fp16.
// ---------------------------------------------------------------------------
template <int PASS>
__global__ __launch_bounds__(128)
void wkv_summary_kernel(const float* __restrict__ kk, const __half* __restrict__ vv,
                        const float* __restrict__ decay)
{
    int lane = blockIdx.x * 128 + threadIdx.x;              // 0..LANES-1
    int seg  = blockIdx.y;
    int b = lane / CC;
    int c = lane % CC;
    const float w = decay[PASS * CC + c] * (1.f / (float)TT);
    const size_t base = (size_t)b * TT * CC + c;

    float p = 0.f, q = 0.f, o = -1e38f;
#pragma unroll 8
    for (int t = 0; t < SEG; t++) {
        int tt = seg * SEG + t;
        int pidx = (PASS == 0) ? tt : zig(tt);
        size_t idx = base + (size_t)pidx * CC;
        float kt = kk[idx];
        float vt = __half2float(vv[idx]);
        float wo  = w + o;
        float no2 = fmaxf(wo, kt);
        float A2  = __expf(wo - no2);
        float B2  = __expf(kt - no2);
        p = A2 * p + B2 * vt;
        q = A2 * q + B2;
        o = no2;
    }
    g_sp[seg][lane] = p;
    g_sq[seg][lane] = q;
    g_so[seg][lane] = o;
}

template <int PASS>
__global__ __launch_bounds__(128)
void wkv_scan_kernel(const float* __restrict__ decay)
{
    int lane = blockIdx.x * 128 + threadIdx.x;
    if (lane >= LANES) return;
    int c = lane % CC;
    const float w  = decay[PASS * CC + c] * (1.f / (float)TT);
    const float wL = w * (float)SEG;

    float p = 0.f, q = 0.f, o = -1e38f;
#pragma unroll
    for (int seg = 0; seg < NSEG; seg++) {
        g_cp[seg][lane] = p;
        g_cq[seg][lane] = q;
        g_co[seg][lane] = o;
        float o1 = o + wL;
        float p2 = g_sp[seg][lane];
        float q2 = g_sq[seg][lane];
        float o2 = g_so[seg][lane];
        float no = fmaxf(o1, o2);
        float e1 = __expf(o1 - no);
        float e2 = __expf(o2 - no);
        p = e1 * p + e2 * p2;
        q = e1 * q + e2 * q2;
        o = no;
    }
}

// PASS 0: plain replay, writes y (f16).
// PASS 1: replay fused with ewmul: writes sr[idx] * y (f16) -> prod.
template <int PASS>
__global__ __launch_bounds__(128)
void wkv_replay_kernel(const float* __restrict__ kk, const __half* __restrict__ vv,
                       const float* __restrict__ decay, const float* __restrict__ first,
                       const __half* __restrict__ srr, __half* __restrict__ yo)
{
    int lane = blockIdx.x * 128 + threadIdx.x;
    int seg  = blockIdx.y;
    int b = lane / CC;
    int c = lane % CC;
    const float invT = 1.f / (float)TT;
    const float w = decay[PASS * CC + c] * invT;
    const float u = first[PASS * CC + c] * invT;
    const size_t base = (size_t)b * TT * CC + c;

    float p = g_cp[seg][lane];
    float q = g_cq[seg][lane];
    float o = g_co[seg][lane];

#pragma unroll 8
    for (int t = 0; t < SEG; t++) {
        int tt = seg * SEG + t;
        int pidx = (PASS == 0) ? tt : zig(tt);
        size_t idx = base + (size_t)pidx * CC;
        float kt = kk[idx];
        float vt = __half2float(vv[idx]);

        float uk = u + kt;
        float no = fmaxf(o, uk);
        float Ac = __expf(o - no);
        float Bc = __expf(uk - no);
        float y  = __fdividef(Ac * p + Bc * vt, Ac * q + Bc);
        if (PASS == 1) y *= __half2float(srr[idx]);
        yo[idx] = __float2half(y);

        float wo  = w + o;
        float no2 = fmaxf(wo, kt);
        float A2  = __expf(wo - no2);
        float B2  = __expf(kt - no2);
        p = A2 * p + B2 * vt;
        q = A2 * q + B2;
        o = no2;
    }
}

// ---------------------------------------------------------------------------
// Launch
// ---------------------------------------------------------------------------
extern "C" void kernel_launch(void* const* d_in, const int* in_sizes, int n_in,
                              void* d_out, int out_size)
{
    const float* x    = (const float*)d_in[0];
    const float* kw   = (const float*)d_in[1];
    const float* vw   = (const float*)d_in[2];
    const float* rw   = (const float*)d_in[3];
    const float* ow   = (const float*)d_in[4];
    const float* sdec = (const float*)d_in[5];
    const float* sfst = (const float*)d_in[6];
    float* out        = (float*)d_out;

    __half *xs, *prod, *wh, *v, *sr, *v1;
    float *k;
    cudaGetSymbolAddress((void**)&xs,   g_xsh);
    cudaGetSymbolAddress((void**)&prod, g_prod);
    cudaGetSymbolAddress((void**)&wh,   g_w);
    cudaGetSymbolAddress((void**)&k,    g_k);
    cudaGetSymbolAddress((void**)&v,    g_v);
    cudaGetSymbolAddress((void**)&sr,   g_sr);
    cudaGetSymbolAddress((void**)&v1,   g_v1);

    cudaFuncSetAttribute(gemm_kvsr_kernel, cudaFuncAttributeMaxDynamicSharedMemorySize, G_DS);
    cudaFuncSetAttribute(gemm_out_kernel,  cudaFuncAttributeMaxDynamicSharedMemorySize, G_DS);

    // 1) shift + zigzag gather with fused f16 convert
    {
        int total = BB * TT * (CC / 4);
        shift_gather_kernel<<<(total + 255) / 256, 256>>>(x, xs);
    }
    // weight converts (single launch)
    {
        int total = CC * CC;           // 4 * CC*CC/4
        wconv4_kernel<<<(total + 255) / 256, 256>>>(kw, vw, rw, ow, wh);
    }

    // 2) fused k/v/sr GEMM (one launch, N=2304)
    {
        dim3 grid(18, MM / G_BM);
        gemm_kvsr_kernel<<<grid, 128, G_DS>>>(xs, wh, k, v, sr);
    }

    // 3) WKV pass 1 (t order) then pass 2 (zigzag involution order).
    //    Pass-2 replay fuses the sr multiply and writes prod directly.
    {
        dim3 gseg(LANES / 128, NSEG);
        int  gscan = LANES / 128;
        wkv_summary_kernel<0><<<gseg, 128>>>(k, v, sdec);
        wkv_scan_kernel<0><<<gscan, 128>>>(sdec);
        wkv_replay_kernel<0><<<gseg, 128>>>(k, v, sdec, sfst, nullptr, v1);

        wkv_summary_kernel<1><<<gseg, 128>>>(k, v1, sdec);
        wkv_scan_kernel<1><<<gscan, 128>>>(sdec);
        wkv_replay_kernel<1><<<gseg, 128>>>(k, v1, sdec, sfst, sr, prod);
    }

    // 4) out = prod @ ow^T
    {
        dim3 grid(CC / G_BN, MM / G_BM);
        gemm_out_kernel<<<grid, 128, G_DS>>>(prod, wh + 3 * (size_t)CC * CC, out);
    }
}

// round 14
// speedup vs baseline: 1.4001x; 1.0158x over previous
#include <cuda_runtime.h>
#include <cuda_bf16.h>
#include <cuda_fp16.h>
#include <mma.h>
#include <cstdint>

using namespace nvcuda;

// Problem constants (fixed by setup_inputs)
#define BB 8
#define HH 64
#define WW 64
#define TT 4096          // HH*WW
#define CC 768
#define MM (BB * TT)     // 32768
#define ELEMS (BB * TT * CC)
#define SEG 64
#define NSEG 64
#define LANES (BB * CC)  // 6144

// Shift table (24 groups of 32 channels)
__constant__ int c_dy[24] = {0, 0, 1, -1, 1, -1, 1, -1, 0, 0, 2, -2, 2, -2, 2, -2, 2, 1, 2, 1, -2, -1, -2, -1};
__constant__ int c_dx[24] = {1, -1, 0, 0, 1, -1, -1, 1, 2, -2, 0, 0, 2, -2, -2, 2, 1, 2, -1, -2, 1, 2, -1, -2};

// Scratch buffers (no cudaMalloc allowed)
__device__ __half g_xsh[ELEMS];
__device__ __half g_prod[ELEMS];
__device__ __half g_w[4][CC * CC];
__device__ __half g_k[ELEMS];
__device__ __half g_v[ELEMS];
__device__ __half g_sr[ELEMS];
__device__ __half g_v1[ELEMS];
// WKV segment summaries + carry-in states
__device__ float g_sp[NSEG][LANES];
__device__ float g_sq[NSEG][LANES];
__device__ float g_so[NSEG][LANES];
__device__ float g_cp[NSEG][LANES];
__device__ float g_cq[NSEG][LANES];
__device__ float g_co[NSEG][LANES];

__device__ __forceinline__ int zig(int t) {
    int r = t >> 6, j = t & 63;
    return (r << 6) + ((r & 1) ? (63 - j) : j);
}

__device__ __forceinline__ void store_h4(__half* dst, float4 v) {
    __half2 a = __floats2half2_rn(v.x, v.y);
    __half2 b = __floats2half2_rn(v.z, v.w);
    *(uint2*)dst = make_uint2(*(unsigned*)&a, *(unsigned*)&b);
}

// ---------------------------------------------------------------------------
// 1) shift (mul_shift) + zigzag reorder + f32->f16 convert, fused gather.
// ---------------------------------------------------------------------------
__global__ void shift_gather_kernel(const float* __restrict__ x, __half* __restrict__ xs)
{
    int gid = blockIdx.x * blockDim.x + threadIdx.x;       // over B*T*(C/4)
    const int CV = CC / 4;
    if (gid >= BB * TT * CV) return;
    int cv = gid % CV;
    int bt = gid / CV;
    int t  = bt % TT;
    int b  = bt / TT;
    int c  = cv * 4;

    int r   = t >> 6;
    int j   = t & 63;
    int col = (r & 1) ? (63 - j) : j;                      // order[t] = (r, col)

    int g   = c >> 5;
    int srow = r - c_dy[g];
    int scol = col - c_dx[g];

    float4 val = make_float4(0.f, 0.f, 0.f, 0.f);
    if ((unsigned)srow < (unsigned)HH && (unsigned)scol < (unsigned)WW) {
        val = *(const float4*)&x[((size_t)b * TT + srow * WW + scol) * CC + c];
    }
    store_h4(&xs[((size_t)b * TT + t) * CC + c], val);
}

// ---------------------------------------------------------------------------
// weight convert: 4 weight matrices f32 -> f16 in one launch
// ---------------------------------------------------------------------------
__global__ void wconv4_kernel(const float* __restrict__ w0, const float* __restrict__ w1,
                              const float* __restrict__ w2, const float* __restrict__ w3,
                              __half* __restrict__ wh)
{
    const int n4 = CC * CC / 4;
    int gid = blockIdx.x * blockDim.x + threadIdx.x;
    if (gid >= 4 * n4) return;
    int which = gid / n4;
    int idx   = gid % n4;
    const float* w = (which == 0) ? w0 : (which == 1) ? w1 : (which == 2) ? w2 : w3;
    store_h4(&wh[(size_t)gid * 4], ((const float4*)w)[idx]);
}

// ---------------------------------------------------------------------------
// cp.async helpers
// ---------------------------------------------------------------------------
__device__ __forceinline__ void cp_async16(void* smem, const void* gmem) {
    unsigned int s = (unsigned int)__cvta_generic_to_shared(smem);
    asm volatile("cp.async.cg.shared.global [%0], [%1], 16;\n" :: "r"(s), "l"(gmem));
}
__device__ __forceinline__ void cp_commit() { asm volatile("cp.async.commit_group;\n" ::: "memory"); }
template<int N> __device__ __forceinline__ void cp_wait() { asm volatile("cp.async.wait_group %0;\n" :: "n"(N) : "memory"); }

// ---------------------------------------------------------------------------
// GEMM core: 3-stage cp.async, BM=128 BN=128 BK=64, 128 threads (4 warps 2x2),
// warp tile 64x64, f32 accum. 2 CTAs/SM.
// ---------------------------------------------------------------------------
#define G_BM 128
#define G_BN 128
#define G_BK 64
#define G_LD 72
#define G_STAGES 3
#define G_NIT (CC / G_BK)
#define G_ASTG (G_BM * G_LD)
#define G_BSTG (G_BN * G_LD)
#define G_DS (G_STAGES * (G_BM + G_BN) * G_LD * 2)

struct GemmAcc {
    wmma::fragment<wmma::accumulator, 16, 16, 16, float> cf[4][4];
};

// Runs the mainloop: C = A[m0:(m0+128), :] x W[wrow0:(wrow0+128), :]^T
__device__ __forceinline__ void gemm_mainloop(
    const __half* __restrict__ A, const __half* __restrict__ Wt,
    int m0, int wrow0, char* dsm, GemmAcc& acc)
{
    __half* Asb = (__half*)dsm;
    __half* Bsb = (__half*)(dsm + G_STAGES * G_ASTG * 2);
    const int tid = threadIdx.x;
    const int warp = tid >> 5;
    const int wm = warp & 1;
    const int wn = warp >> 1;

#pragma unroll
    for (int i = 0; i < 4; i++)
#pragma unroll
        for (int jn = 0; jn < 4; jn++)
            wmma::fill_fragment(acc.cf[i][jn], 0.f);

    auto issue_loads = [&](int st, int k0) {
        __half* as = Asb + st * G_ASTG;
        __half* bs = Bsb + st * G_BSTG;
#pragma unroll
        for (int i = 0; i < 8; i++) {
            int idx = tid + i * 128;
            int row = idx >> 3;
            int c8  = (idx & 7) * 8;
            cp_async16(as + row * G_LD + c8, &A[(size_t)(m0 + row) * CC + k0 + c8]);
        }
#pragma unroll
        for (int i = 0; i < 8; i++) {
            int idx = tid + i * 128;
            int row = idx >> 3;
            int c8  = (idx & 7) * 8;
            cp_async16(bs + row * G_LD + c8, &Wt[(size_t)(wrow0 + row) * CC + k0 + c8]);
        }
    };

    issue_loads(0, 0);
    cp_commit();
    issue_loads(1, G_BK);
    cp_commit();

    for (int ch = 0; ch < G_NIT; ch++) {
        const int st = ch % G_STAGES;
        if (ch < G_NIT - 1) cp_wait<1>();
        else                cp_wait<0>();
        __syncthreads();

        if (ch + 2 < G_NIT) {
            issue_loads((ch + 2) % G_STAGES, (ch + 2) * G_BK);
            cp_commit();
        }

        const __half* as = Asb + st * G_ASTG;
        const __half* bs = Bsb + st * G_BSTG;
#pragma unroll
        for (int kk = 0; kk < G_BK; kk += 16) {
            wmma::fragment<wmma::matrix_a, 16, 16, 16, __half, wmma::row_major> af[4];
            wmma::fragment<wmma::matrix_b, 16, 16, 16, __half, wmma::col_major> bf[4];
#pragma unroll
            for (int i = 0; i < 4; i++)
                wmma::load_matrix_sync(af[i], as + (wm * 64 + i * 16) * G_LD + kk, G_LD);
#pragma unroll
            for (int jn = 0; jn < 4; jn++)
                wmma::load_matrix_sync(bf[jn], bs + (wn * 64 + jn * 16) * G_LD + kk, G_LD);
#pragma unroll
            for (int i = 0; i < 4; i++)
#pragma unroll
                for (int jn = 0; jn < 4; jn++)
                    wmma::mma_sync(acc.cf[i][jn], af[i], bf[jn], acc.cf[i][jn]);
        }
    }
}

// half epilogue: stage f32 per-warp in smem, convert, wide store. SIG: sigmoid.
template <int SIG>
__device__ __forceinline__ void gemm_epi_half(GemmAcc& acc, __half* Co, int m0, int n0, char* dsm)
{
    constexpr int SLD = 68;
    const int tid = threadIdx.x;
    const int warp = tid >> 5;
    const int lid = tid & 31;
    const int wm = warp & 1;
    const int wn = warp >> 1;

    if (SIG) {
#pragma unroll
        for (int i = 0; i < 4; i++)
#pragma unroll
            for (int jn = 0; jn < 4; jn++)
#pragma unroll
                for (int e = 0; e < acc.cf[i][jn].num_elements; e++)
                    acc.cf[i][jn].x[e] = 1.f / (1.f + __expf(-acc.cf[i][jn].x[e]));
    }
    __syncthreads();
    float* buf = (float*)dsm + warp * 16 * SLD;
#pragma unroll
    for (int i = 0; i < 4; i++) {
#pragma unroll
        for (int jn = 0; jn < 4; jn++)
            wmma::store_matrix_sync(buf + jn * 16, acc.cf[i][jn], SLD, wmma::mem_row_major);
        __syncwarp();
#pragma unroll
        for (int rr = 0; rr < 4; rr++) {
            int row = rr * 4 + (lid >> 3);
            int col = (lid & 7) * 8;
            const float* s = buf + row * SLD + col;
            __half h[8];
#pragma unroll
            for (int e = 0; e < 8; e++) h[e] = __float2half(s[e]);
            *(uint4*)&Co[(size_t)(m0 + wm * 64 + i * 16 + row) * CC + n0 + wn * 64 + col] = *(uint4*)h;
        }
        __syncwarp();
    }
}

__device__ __forceinline__ void gemm_epi_float(GemmAcc& acc, float* Co, int m0, int n0)
{
    const int warp = threadIdx.x >> 5;
    const int wm = warp & 1;
    const int wn = warp >> 1;
#pragma unroll
    for (int i = 0; i < 4; i++)
#pragma unroll
        for (int jn = 0; jn < 4; jn++)
            wmma::store_matrix_sync(
                &Co[(size_t)(m0 + wm * 64 + i * 16) * CC + n0 + wn * 64 + jn * 16],
                acc.cf[i][jn], CC, wmma::mem_row_major);
}

// ---------------------------------------------------------------------------
// 2a) fused k/v/sr GEMM: one launch, N=2304. blockIdx.x: 0-5 -> k (f16),
//     6-11 -> v (f16), 12-17 -> sr (f16 + sigmoid).
// ---------------------------------------------------------------------------
__global__ __launch_bounds__(128, 2)
void gemm_kvsr_kernel(const __half* __restrict__ A, const __half* __restrict__ Wall,
                      __half* __restrict__ Ko, __half* __restrict__ Vo, __half* __restrict__ SRo)
{
    extern __shared__ char dsm[];
    const int which = blockIdx.x / 6;
    const int n0 = (blockIdx.x % 6) * G_BN;
    const int m0 = blockIdx.y * G_BM;

    GemmAcc acc;
    gemm_mainloop(A, Wall, m0, which * CC + n0, dsm, acc);

    if (which == 0)      gemm_epi_half<0>(acc, Ko, m0, n0, dsm);
    else if (which == 1) gemm_epi_half<0>(acc, Vo, m0, n0, dsm);
    else                 gemm_epi_half<1>(acc, SRo, m0, n0, dsm);
}

// ---------------------------------------------------------------------------
// 2b) output GEMM: out = prod @ ow^T (f32 out)
// ---------------------------------------------------------------------------
__global__ __launch_bounds__(128, 2)
void gemm_out_kernel(const __half* __restrict__ A, const __half* __restrict__ Wt,
                     float* __restrict__ Co)
{
    extern __shared__ char dsm[];
    const int n0 = blockIdx.x * G_BN;
    const int m0 = blockIdx.y * G_BM;
    GemmAcc acc;
    gemm_mainloop(A, Wt, m0, n0, dsm, acc);
    gemm_epi_float(acc, Co, m0, n0);
}

// ---------------------------------------------------------------------------
// 3) WKV, chunked parallel scan. k/v/y all fp16 in memory, f32 compute.
// ---------------------------------------------------------------------------
template <int PASS>
__global__ __launch_bounds__(128)
void wkv_summary_kernel(const __half* __restrict__ kk, const __half* __restrict__ vv,
                        const float* __restrict__ decay)
{
    int lane = blockIdx.x * 128 + threadIdx.x;              // 0..LANES-1
    int seg  = blockIdx.y;
    int b = lane / CC;
    int c = lane % CC;
    const float w = decay[PASS * CC + c] * (1.f / (float)TT);
    const size_t base = (size_t)b * TT * CC + c;

    float p = 0.f, q = 0.f, o = -1e38f;
#pragma unroll 8
    for (int t = 0; t < SEG; t++) {
        int tt = seg * SEG + t;
        int pidx = (PASS == 0) ? tt : zig(tt);
        size_t idx = base + (size_t)pidx * CC;
        float kt = __half2float(kk[idx]);
        float vt = __half2float(vv[idx]);
        float wo  = w + o;
        float no2 = fmaxf(wo, kt);
        float A2  = __expf(wo - no2);
        float B2  = __expf(kt - no2);
        p = A2 * p + B2 * vt;
        q = A2 * q + B2;
        o = no2;
    }
    g_sp[seg][lane] = p;
    g_sq[seg][lane] = q;
    g_so[seg][lane] = o;
}

template <int PASS>
__global__ __launch_bounds__(128)
void wkv_scan_kernel(const float* __restrict__ decay)
{
    int lane = blockIdx.x * 128 + threadIdx.x;
    if (lane >= LANES) return;
    int c = lane % CC;
    const float w  = decay[PASS * CC + c] * (1.f / (float)TT);
    const float wL = w * (float)SEG;

    float p = 0.f, q = 0.f, o = -1e38f;
#pragma unroll
    for (int seg = 0; seg < NSEG; seg++) {
        g_cp[seg][lane] = p;
        g_cq[seg][lane] = q;
        g_co[seg][lane] = o;
        float o1 = o + wL;
        float p2 = g_sp[seg][lane];
        float q2 = g_sq[seg][lane];
        float o2 = g_so[seg][lane];
        float no = fmaxf(o1, o2);
        float e1 = __expf(o1 - no);
        float e2 = __expf(o2 - no);
        p = e1 * p + e2 * p2;
        q = e1 * q + e2 * q2;
        o = no;
    }
}

// PASS 0: plain replay, writes y (f16).
// PASS 1: replay fused with ewmul: writes sr[idx] * y (f16) -> prod.
template <int PASS>
__global__ __launch_bounds__(128)
void wkv_replay_kernel(const __half* __restrict__ kk, const __half* __restrict__ vv,
                       const float* __restrict__ decay, const float* __restrict__ first,
                       const __half* __restrict__ srr, __half* __restrict__ yo)
{
    int lane = blockIdx.x * 128 + threadIdx.x;
    int seg  = blockIdx.y;
    int b = lane / CC;
    int c = lane % CC;
    const float invT = 1.f / (float)TT;
    const float w = decay[PASS * CC + c] * invT;
    const float u = first[PASS * CC + c] * invT;
    const size_t base = (size_t)b * TT * CC + c;

    float p = g_cp[seg][lane];
    float q = g_cq[seg][lane];
    float o = g_co[seg][lane];

#pragma unroll 8
    for (int t = 0; t < SEG; t++) {
        int tt = seg * SEG + t;
        int pidx = (PASS == 0) ? tt : zig(tt);
        size_t idx = base + (size_t)pidx * CC;
        float kt = __half2float(kk[idx]);
        float vt = __half2float(vv[idx]);

        float uk = u + kt;
        float no = fmaxf(o, uk);
        float Ac = __expf(o - no);
        float Bc = __expf(uk - no);
        float y  = __fdividef(Ac * p + Bc * vt, Ac * q + Bc);
        if (PASS == 1) y *= __half2float(srr[idx]);
        yo[idx] = __float2half(y);

        float wo  = w + o;
        float no2 = fmaxf(wo, kt);
        float A2  = __expf(wo - no2);
        float B2  = __expf(kt - no2);
        p = A2 * p + B2 * vt;
        q = A2 * q + B2;
        o = no2;
    }
}

// ---------------------------------------------------------------------------
// Launch
// ---------------------------------------------------------------------------
extern "C" void kernel_launch(void* const* d_in, const int* in_sizes, int n_in,
                              void* d_out, int out_size)
{
    const float* x    = (const float*)d_in[0];
    const float* kw   = (const float*)d_in[1];
    const float* vw   = (const float*)d_in[2];
    const float* rw   = (const float*)d_in[3];
    const float* ow   = (const float*)d_in[4];
    const float* sdec = (const float*)d_in[5];
    const float* sfst = (const float*)d_in[6];
    float* out        = (float*)d_out;

    __half *xs, *prod, *wh, *k, *v, *sr, *v1;
    cudaGetSymbolAddress((void**)&xs,   g_xsh);
    cudaGetSymbolAddress((void**)&prod, g_prod);
    cudaGetSymbolAddress((void**)&wh,   g_w);
    cudaGetSymbolAddress((void**)&k,    g_k);
    cudaGetSymbolAddress((void**)&v,    g_v);
    cudaGetSymbolAddress((void**)&sr,   g_sr);
    cudaGetSymbolAddress((void**)&v1,   g_v1);

    cudaFuncSetAttribute(gemm_kvsr_kernel, cudaFuncAttributeMaxDynamicSharedMemorySize, G_DS);
    cudaFuncSetAttribute(gemm_out_kernel,  cudaFuncAttributeMaxDynamicSharedMemorySize, G_DS);

    // 1) shift + zigzag gather with fused f16 convert
    {
        int total = BB * TT * (CC / 4);
        shift_gather_kernel<<<(total + 255) / 256, 256>>>(x, xs);
    }
    // weight converts (single launch)
    {
        int total = CC * CC;           // 4 * CC*CC/4
        wconv4_kernel<<<(total + 255) / 256, 256>>>(kw, vw, rw, ow, wh);
    }

    // 2) fused k/v/sr GEMM (one launch, N=2304)
    {
        dim3 grid(18, MM / G_BM);
        gemm_kvsr_kernel<<<grid, 128, G_DS>>>(xs, wh, k, v, sr);
    }

    // 3) WKV pass 1 (t order) then pass 2 (zigzag involution order).
    //    Pass-2 replay fuses the sr multiply and writes prod directly.
    {
        dim3 gseg(LANES / 128, NSEG);
        int  gscan = LANES / 128;
        wkv_summary_kernel<0><<<gseg, 128>>>(k, v, sdec);
        wkv_scan_kernel<0><<<gscan, 128>>>(sdec);
        wkv_replay_kernel<0><<<gseg, 128>>>(k, v, sdec, sfst, nullptr, v1);

        wkv_summary_kernel<1><<<gseg, 128>>>(k, v1, sdec);
        wkv_scan_kernel<1><<<gscan, 128>>>(sdec);
        wkv_replay_kernel<1><<<gseg, 128>>>(k, v1, sdec, sfst, sr, prod);
    }

    // 4) out = prod @ ow^T
    {
        dim3 grid(CC / G_BN, MM / G_BM);
        gemm_out_kernel<<<grid, 128, G_DS>>>(prod, wh + 3 * (size_t)CC * CC, out);
    }
}

// round 15
// speedup vs baseline: 1.4330x; 1.0235x over previous
#include <cuda_runtime.h>
#include <cuda_bf16.h>
#include <cuda_fp16.h>
#include <mma.h>
#include <cstdint>

using namespace nvcuda;

// Problem constants (fixed by setup_inputs)
#define BB 8
#define HH 64
#define WW 64
#define TT 4096          // HH*WW
#define CC 768
#define MM (BB * TT)     // 32768
#define ELEMS (BB * TT * CC)
#define SEG 64
#define NSEG 64
#define LANES (BB * CC)  // 6144
#define LANES2 (LANES / 2)

// Shift table (24 groups of 32 channels)
__constant__ int c_dy[24] = {0, 0, 1, -1, 1, -1, 1, -1, 0, 0, 2, -2, 2, -2, 2, -2, 2, 1, 2, 1, -2, -1, -2, -1};
__constant__ int c_dx[24] = {1, -1, 0, 0, 1, -1, -1, 1, 2, -2, 0, 0, 2, -2, -2, 2, 1, 2, -1, -2, 1, 2, -1, -2};

// Scratch buffers (no cudaMalloc allowed)
__device__ __half g_xsh[ELEMS];
__device__ __half g_prod[ELEMS];
__device__ __half g_w[4][CC * CC];
__device__ __half g_k[ELEMS];
__device__ __half g_v[ELEMS];
__device__ __half g_sr[ELEMS];
__device__ __half g_v1[ELEMS];
// WKV segment summaries + carry-in states
__device__ float g_sp[NSEG][LANES];
__device__ float g_sq[NSEG][LANES];
__device__ float g_so[NSEG][LANES];
__device__ float g_cp[NSEG][LANES];
__device__ float g_cq[NSEG][LANES];
__device__ float g_co[NSEG][LANES];

__device__ __forceinline__ int zig(int t) {
    int r = t >> 6, j = t & 63;
    return (r << 6) + ((r & 1) ? (63 - j) : j);
}

__device__ __forceinline__ void store_h4(__half* dst, float4 v) {
    __half2 a = __floats2half2_rn(v.x, v.y);
    __half2 b = __floats2half2_rn(v.z, v.w);
    *(uint2*)dst = make_uint2(*(unsigned*)&a, *(unsigned*)&b);
}

// ---------------------------------------------------------------------------
// 1) merged prep: shift-gather (f32->f16) + 4x weight convert, one launch.
//    Blocks [0, GATHER_BLKS): gather. Blocks [GATHER_BLKS, +WCONV_BLKS): wconv.
// ---------------------------------------------------------------------------
#define GATHER_TOTAL (BB * TT * (CC / 4))
#define GATHER_BLKS  ((GATHER_TOTAL + 255) / 256)
#define WCONV_TOTAL  (CC * CC)
#define WCONV_BLKS   ((WCONV_TOTAL + 255) / 256)

__global__ void prep_kernel(const float* __restrict__ x, __half* __restrict__ xs,
                            const float* __restrict__ w0, const float* __restrict__ w1,
                            const float* __restrict__ w2, const float* __restrict__ w3,
                            __half* __restrict__ wh)
{
    if (blockIdx.x < GATHER_BLKS) {
        int gid = blockIdx.x * 256 + threadIdx.x;
        const int CV = CC / 4;
        if (gid >= GATHER_TOTAL) return;
        int cv = gid % CV;
        int bt = gid / CV;
        int t  = bt % TT;
        int b  = bt / TT;
        int c  = cv * 4;

        int r   = t >> 6;
        int j   = t & 63;
        int col = (r & 1) ? (63 - j) : j;

        int g   = c >> 5;
        int srow = r - c_dy[g];
        int scol = col - c_dx[g];

        float4 val = make_float4(0.f, 0.f, 0.f, 0.f);
        if ((unsigned)srow < (unsigned)HH && (unsigned)scol < (unsigned)WW) {
            val = *(const float4*)&x[((size_t)b * TT + srow * WW + scol) * CC + c];
        }
        store_h4(&xs[((size_t)b * TT + t) * CC + c], val);
    } else {
        int gid = (blockIdx.x - GATHER_BLKS) * 256 + threadIdx.x;
        const int n4 = CC * CC / 4;
        if (gid >= 4 * n4) return;
        int which = gid / n4;
        int idx   = gid % n4;
        const float* w = (which == 0) ? w0 : (which == 1) ? w1 : (which == 2) ? w2 : w3;
        store_h4(&wh[(size_t)gid * 4], ((const float4*)w)[idx]);
    }
}

// ---------------------------------------------------------------------------
// cp.async helpers
// ---------------------------------------------------------------------------
__device__ __forceinline__ void cp_async16(void* smem, const void* gmem) {
    unsigned int s = (unsigned int)__cvta_generic_to_shared(smem);
    asm volatile("cp.async.cg.shared.global [%0], [%1], 16;\n" :: "r"(s), "l"(gmem));
}
__device__ __forceinline__ void cp_commit() { asm volatile("cp.async.commit_group;\n" ::: "memory"); }
template<int N> __device__ __forceinline__ void cp_wait() { asm volatile("cp.async.wait_group %0;\n" :: "n"(N) : "memory"); }

// ---------------------------------------------------------------------------
// GEMM core: 3-stage cp.async, BM=128 BN=128 BK=64, 128 threads (4 warps 2x2),
// warp tile 64x64, f32 accum. 2 CTAs/SM.
// ---------------------------------------------------------------------------
#define G_BM 128
#define G_BN 128
#define G_BK 64
#define G_LD 72
#define G_STAGES 3
#define G_NIT (CC / G_BK)
#define G_ASTG (G_BM * G_LD)
#define G_BSTG (G_BN * G_LD)
#define G_DS (G_STAGES * (G_BM + G_BN) * G_LD * 2)

struct GemmAcc {
    wmma::fragment<wmma::accumulator, 16, 16, 16, float> cf[4][4];
};

__device__ __forceinline__ void gemm_mainloop(
    const __half* __restrict__ A, const __half* __restrict__ Wt,
    int m0, int wrow0, char* dsm, GemmAcc& acc)
{
    __half* Asb = (__half*)dsm;
    __half* Bsb = (__half*)(dsm + G_STAGES * G_ASTG * 2);
    const int tid = threadIdx.x;
    const int warp = tid >> 5;
    const int wm = warp & 1;
    const int wn = warp >> 1;

#pragma unroll
    for (int i = 0; i < 4; i++)
#pragma unroll
        for (int jn = 0; jn < 4; jn++)
            wmma::fill_fragment(acc.cf[i][jn], 0.f);

    auto issue_loads = [&](int st, int k0) {
        __half* as = Asb + st * G_ASTG;
        __half* bs = Bsb + st * G_BSTG;
#pragma unroll
        for (int i = 0; i < 8; i++) {
            int idx = tid + i * 128;
            int row = idx >> 3;
            int c8  = (idx & 7) * 8;
            cp_async16(as + row * G_LD + c8, &A[(size_t)(m0 + row) * CC + k0 + c8]);
        }
#pragma unroll
        for (int i = 0; i < 8; i++) {
            int idx = tid + i * 128;
            int row = idx >> 3;
            int c8  = (idx & 7) * 8;
            cp_async16(bs + row * G_LD + c8, &Wt[(size_t)(wrow0 + row) * CC + k0 + c8]);
        }
    };

    issue_loads(0, 0);
    cp_commit();
    issue_loads(1, G_BK);
    cp_commit();

    for (int ch = 0; ch < G_NIT; ch++) {
        const int st = ch % G_STAGES;
        if (ch < G_NIT - 1) cp_wait<1>();
        else                cp_wait<0>();
        __syncthreads();

        if (ch + 2 < G_NIT) {
            issue_loads((ch + 2) % G_STAGES, (ch + 2) * G_BK);
            cp_commit();
        }

        const __half* as = Asb + st * G_ASTG;
        const __half* bs = Bsb + st * G_BSTG;
#pragma unroll
        for (int kk = 0; kk < G_BK; kk += 16) {
            wmma::fragment<wmma::matrix_a, 16, 16, 16, __half, wmma::row_major> af[4];
            wmma::fragment<wmma::matrix_b, 16, 16, 16, __half, wmma::col_major> bf[4];
#pragma unroll
            for (int i = 0; i < 4; i++)
                wmma::load_matrix_sync(af[i], as + (wm * 64 + i * 16) * G_LD + kk, G_LD);
#pragma unroll
            for (int jn = 0; jn < 4; jn++)
                wmma::load_matrix_sync(bf[jn], bs + (wn * 64 + jn * 16) * G_LD + kk, G_LD);
#pragma unroll
            for (int i = 0; i < 4; i++)
#pragma unroll
                for (int jn = 0; jn < 4; jn++)
                    wmma::mma_sync(acc.cf[i][jn], af[i], bf[jn], acc.cf[i][jn]);
        }
    }
}

// half epilogue: stage f32 per-warp in smem, convert, wide store. SIG: sigmoid.
template <int SIG>
__device__ __forceinline__ void gemm_epi_half(GemmAcc& acc, __half* Co, int m0, int n0, char* dsm)
{
    constexpr int SLD = 68;
    const int tid = threadIdx.x;
    const int warp = tid >> 5;
    const int lid = tid & 31;
    const int wm = warp & 1;
    const int wn = warp >> 1;

    if (SIG) {
#pragma unroll
        for (int i = 0; i < 4; i++)
#pragma unroll
            for (int jn = 0; jn < 4; jn++)
#pragma unroll
                for (int e = 0; e < acc.cf[i][jn].num_elements; e++)
                    acc.cf[i][jn].x[e] = 1.f / (1.f + __expf(-acc.cf[i][jn].x[e]));
    }
    __syncthreads();
    float* buf = (float*)dsm + warp * 16 * SLD;
#pragma unroll
    for (int i = 0; i < 4; i++) {
#pragma unroll
        for (int jn = 0; jn < 4; jn++)
            wmma::store_matrix_sync(buf + jn * 16, acc.cf[i][jn], SLD, wmma::mem_row_major);
        __syncwarp();
#pragma unroll
        for (int rr = 0; rr < 4; rr++) {
            int row = rr * 4 + (lid >> 3);
            int col = (lid & 7) * 8;
            const float* s = buf + row * SLD + col;
            __half h[8];
#pragma unroll
            for (int e = 0; e < 8; e++) h[e] = __float2half(s[e]);
            *(uint4*)&Co[(size_t)(m0 + wm * 64 + i * 16 + row) * CC + n0 + wn * 64 + col] = *(uint4*)h;
        }
        __syncwarp();
    }
}

__device__ __forceinline__ void gemm_epi_float(GemmAcc& acc, float* Co, int m0, int n0)
{
    const int warp = threadIdx.x >> 5;
    const int wm = warp & 1;
    const int wn = warp >> 1;
#pragma unroll
    for (int i = 0; i < 4; i++)
#pragma unroll
        for (int jn = 0; jn < 4; jn++)
            wmma::store_matrix_sync(
                &Co[(size_t)(m0 + wm * 64 + i * 16) * CC + n0 + wn * 64 + jn * 16],
                acc.cf[i][jn], CC, wmma::mem_row_major);
}

// ---------------------------------------------------------------------------
// 2a) fused k/v/sr GEMM: one launch, N=2304. blockIdx.x: 0-5 -> k (f16),
//     6-11 -> v (f16), 12-17 -> sr (f16 + sigmoid).
// ---------------------------------------------------------------------------
__global__ __launch_bounds__(128, 2)
void gemm_kvsr_kernel(const __half* __restrict__ A, const __half* __restrict__ Wall,
                      __half* __restrict__ Ko, __half* __restrict__ Vo, __half* __restrict__ SRo)
{
    extern __shared__ char dsm[];
    const int which = blockIdx.x / 6;
    const int n0 = (blockIdx.x % 6) * G_BN;
    const int m0 = blockIdx.y * G_BM;

    GemmAcc acc;
    gemm_mainloop(A, Wall, m0, which * CC + n0, dsm, acc);

    if (which == 0)      gemm_epi_half<0>(acc, Ko, m0, n0, dsm);
    else if (which == 1) gemm_epi_half<0>(acc, Vo, m0, n0, dsm);
    else                 gemm_epi_half<1>(acc, SRo, m0, n0, dsm);
}

// ---------------------------------------------------------------------------
// 2b) output GEMM: out = prod @ ow^T (f32 out)
// ---------------------------------------------------------------------------
__global__ __launch_bounds__(128, 2)
void gemm_out_kernel(const __half* __restrict__ A, const __half* __restrict__ Wt,
                     float* __restrict__ Co)
{
    extern __shared__ char dsm[];
    const int n0 = blockIdx.x * G_BN;
    const int m0 = blockIdx.y * G_BM;
    GemmAcc acc;
    gemm_mainloop(A, Wt, m0, n0, dsm, acc);
    gemm_epi_float(acc, Co, m0, n0);
}

// ---------------------------------------------------------------------------
// 3) WKV, chunked parallel scan. 2 adjacent channels per thread (__half2 I/O).
// ---------------------------------------------------------------------------
template <int PASS>
__global__ __launch_bounds__(128)
void wkv_summary_kernel(const __half* __restrict__ kk, const __half* __restrict__ vv,
                        const float* __restrict__ decay)
{
    int lane2 = blockIdx.x * 128 + threadIdx.x;             // 0..LANES2-1
    int seg   = blockIdx.y;
    int lane  = lane2 * 2;
    int b = lane / CC;
    int c = lane % CC;
    const float invT = 1.f / (float)TT;
    float2 wv = *(const float2*)&decay[PASS * CC + c];
    const float w0 = wv.x * invT, w1 = wv.y * invT;
    const size_t base = (size_t)b * TT * CC + c;

    float p0 = 0.f, q0 = 0.f, o0 = -1e38f;
    float p1 = 0.f, q1 = 0.f, o1 = -1e38f;
#pragma unroll 4
    for (int t = 0; t < SEG; t++) {
        int tt = seg * SEG + t;
        int pidx = (PASS == 0) ? tt : zig(tt);
        size_t idx = base + (size_t)pidx * CC;
        float2 kf = __half22float2(*(const __half2*)&kk[idx]);
        float2 vf = __half22float2(*(const __half2*)&vv[idx]);

        float wo0 = w0 + o0;
        float no0 = fmaxf(wo0, kf.x);
        float A0  = __expf(wo0 - no0);
        float B0  = __expf(kf.x - no0);
        p0 = A0 * p0 + B0 * vf.x;
        q0 = A0 * q0 + B0;
        o0 = no0;

        float wo1 = w1 + o1;
        float no1 = fmaxf(wo1, kf.y);
        float A1  = __expf(wo1 - no1);
        float B1  = __expf(kf.y - no1);
        p1 = A1 * p1 + B1 * vf.y;
        q1 = A1 * q1 + B1;
        o1 = no1;
    }
    *(float2*)&g_sp[seg][lane] = make_float2(p0, p1);
    *(float2*)&g_sq[seg][lane] = make_float2(q0, q1);
    *(float2*)&g_so[seg][lane] = make_float2(o0, o1);
}

template <int PASS>
__global__ __launch_bounds__(128)
void wkv_scan_kernel(const float* __restrict__ decay)
{
    int lane = blockIdx.x * 128 + threadIdx.x;
    if (lane >= LANES) return;
    int c = lane % CC;
    const float w  = decay[PASS * CC + c] * (1.f / (float)TT);
    const float wL = w * (float)SEG;

    float p = 0.f, q = 0.f, o = -1e38f;
#pragma unroll
    for (int seg = 0; seg < NSEG; seg++) {
        g_cp[seg][lane] = p;
        g_cq[seg][lane] = q;
        g_co[seg][lane] = o;
        float o1 = o + wL;
        float p2 = g_sp[seg][lane];
        float q2 = g_sq[seg][lane];
        float o2 = g_so[seg][lane];
        float no = fmaxf(o1, o2);
        float e1 = __expf(o1 - no);
        float e2 = __expf(o2 - no);
        p = e1 * p + e2 * p2;
        q = e1 * q + e2 * q2;
        o = no;
    }
}

// PASS 0: plain replay, writes y (f16).
// PASS 1: replay fused with ewmul: writes sr[idx] * y (f16) -> prod.
template <int PASS>
__global__ __launch_bounds__(128)
void wkv_replay_kernel(const __half* __restrict__ kk, const __half* __restrict__ vv,
                       const float* __restrict__ decay, const float* __restrict__ first,
                       const __half* __restrict__ srr, __half* __restrict__ yo)
{
    int lane2 = blockIdx.x * 128 + threadIdx.x;
    int seg   = blockIdx.y;
    int lane  = lane2 * 2;
    int b = lane / CC;
    int c = lane % CC;
    const float invT = 1.f / (float)TT;
    float2 wv = *(const float2*)&decay[PASS * CC + c];
    float2 uv = *(const float2*)&first[PASS * CC + c];
    const float w0 = wv.x * invT, w1 = wv.y * invT;
    const float u0 = uv.x * invT, u1 = uv.y * invT;
    const size_t base = (size_t)b * TT * CC + c;

    float2 pv = *(const float2*)&g_cp[seg][lane];
    float2 qv = *(const float2*)&g_cq[seg][lane];
    float2 ov = *(const float2*)&g_co[seg][lane];
    float p0 = pv.x, q0 = qv.x, o0 = ov.x;
    float p1 = pv.y, q1 = qv.y, o1 = ov.y;

#pragma unroll 4
    for (int t = 0; t < SEG; t++) {
        int tt = seg * SEG + t;
        int pidx = (PASS == 0) ? tt : zig(tt);
        size_t idx = base + (size_t)pidx * CC;
        float2 kf = __half22float2(*(const __half2*)&kk[idx]);
        float2 vf = __half22float2(*(const __half2*)&vv[idx]);

        float uk0 = u0 + kf.x;
        float no0 = fmaxf(o0, uk0);
        float Ac0 = __expf(o0 - no0);
        float Bc0 = __expf(uk0 - no0);
        float y0  = __fdividef(Ac0 * p0 + Bc0 * vf.x, Ac0 * q0 + Bc0);

        float uk1 = u1 + kf.y;
        float no1 = fmaxf(o1, uk1);
        float Ac1 = __expf(o1 - no1);
        float Bc1 = __expf(uk1 - no1);
        float y1  = __fdividef(Ac1 * p1 + Bc1 * vf.y, Ac1 * q1 + Bc1);

        if (PASS == 1) {
            float2 sf = __half22float2(*(const __half2*)&srr[idx]);
            y0 *= sf.x;
            y1 *= sf.y;
        }
        *(__half2*)&yo[idx] = __floats2half2_rn(y0, y1);

        float wo0 = w0 + o0;
        float m0  = fmaxf(wo0, kf.x);
        float A0  = __expf(wo0 - m0);
        float B0  = __expf(kf.x - m0);
        p0 = A0 * p0 + B0 * vf.x;
        q0 = A0 * q0 + B0;
        o0 = m0;

        float wo1 = w1 + o1;
        float m1  = fmaxf(wo1, kf.y);
        float A1  = __expf(wo1 - m1);
        float B1  = __expf(kf.y - m1);
        p1 = A1 * p1 + B1 * vf.y;
        q1 = A1 * q1 + B1;
        o1 = m1;
    }
}

// ---------------------------------------------------------------------------
// Launch
// ---------------------------------------------------------------------------
extern "C" void kernel_launch(void* const* d_in, const int* in_sizes, int n_in,
                              void* d_out, int out_size)
{
    const float* x    = (const float*)d_in[0];
    const float* kw   = (const float*)d_in[1];
    const float* vw   = (const float*)d_in[2];
    const float* rw   = (const float*)d_in[3];
    const float* ow   = (const float*)d_in[4];
    const float* sdec = (const float*)d_in[5];
    const float* sfst = (const float*)d_in[6];
    float* out        = (float*)d_out;

    __half *xs, *prod, *wh, *k, *v, *sr, *v1;
    cudaGetSymbolAddress((void**)&xs,   g_xsh);
    cudaGetSymbolAddress((void**)&prod, g_prod);
    cudaGetSymbolAddress((void**)&wh,   g_w);
    cudaGetSymbolAddress((void**)&k,    g_k);
    cudaGetSymbolAddress((void**)&v,    g_v);
    cudaGetSymbolAddress((void**)&sr,   g_sr);
    cudaGetSymbolAddress((void**)&v1,   g_v1);

    cudaFuncSetAttribute(gemm_kvsr_kernel, cudaFuncAttributeMaxDynamicSharedMemorySize, G_DS);
    cudaFuncSetAttribute(gemm_out_kernel,  cudaFuncAttributeMaxDynamicSharedMemorySize, G_DS);

    // 1) merged prep: gather + weight converts in one launch
    prep_kernel<<<GATHER_BLKS + WCONV_BLKS, 256>>>(x, xs, kw, vw, rw, ow, wh);

    // 2) fused k/v/sr GEMM (one launch, N=2304)
    {
        dim3 grid(18, MM / G_BM);
        gemm_kvsr_kernel<<<grid, 128, G_DS>>>(xs, wh, k, v, sr);
    }

    // 3) WKV pass 1 (t order) then pass 2 (zigzag involution order).
    //    Pass-2 replay fuses the sr multiply and writes prod directly.
    {
        dim3 gseg(LANES2 / 128, NSEG);
        int  gscan = LANES / 128;
        wkv_summary_kernel<0><<<gseg, 128>>>(k, v, sdec);
        wkv_scan_kernel<0><<<gscan, 128>>>(sdec);
        wkv_replay_kernel<0><<<gseg, 128>>>(k, v, sdec, sfst, nullptr, v1);

        wkv_summary_kernel<1><<<gseg, 128>>>(k, v1, sdec);
        wkv_scan_kernel<1><<<gscan, 128>>>(sdec);
        wkv_replay_kernel<1><<<gseg, 128>>>(k, v1, sdec, sfst, sr, prod);
    }

    // 4) out = prod @ ow^T
    {
        dim3 grid(CC / G_BN, MM / G_BM);
        gemm_out_kernel<<<grid, 128, G_DS>>>(prod, wh + 3 * (size_t)CC * CC, out);
    }
}

// round 16
// speedup vs baseline: 1.4990x; 1.0460x over previous
#include <cuda_runtime.h>
#include <cuda_bf16.h>
#include <cuda_fp16.h>
#include <mma.h>
#include <cstdint>

using namespace nvcuda;

// Problem constants (fixed by setup_inputs)
#define BB 8
#define HH 64
#define WW 64
#define TT 4096          // HH*WW
#define CC 768
#define MM (BB * TT)     // 32768
#define ELEMS (BB * TT * CC)
#define SEG 64
#define NSEG 64
#define LANES (BB * CC)  // 6144
#define LANES2 (LANES / 2)

// Shift table (24 groups of 32 channels)
__constant__ int c_dy[24] = {0, 0, 1, -1, 1, -1, 1, -1, 0, 0, 2, -2, 2, -2, 2, -2, 2, 1, 2, 1, -2, -1, -2, -1};
__constant__ int c_dx[24] = {1, -1, 0, 0, 1, -1, -1, 1, 2, -2, 0, 0, 2, -2, -2, 2, 1, 2, -1, -2, 1, 2, -1, -2};

// Scratch buffers (no cudaMalloc allowed)
__device__ __half g_xsh[ELEMS];
__device__ __half g_prod[ELEMS];
__device__ __half g_w[4][CC * CC];
__device__ __half g_k[ELEMS];
__device__ __half g_v[ELEMS];
__device__ __half g_sr[ELEMS];
__device__ __half g_v1[ELEMS];
// WKV segment summaries + carry-in states
__device__ float g_sp[NSEG][LANES];
__device__ float g_sq[NSEG][LANES];
__device__ float g_so[NSEG][LANES];
__device__ float g_cp[NSEG][LANES];
__device__ float g_cq[NSEG][LANES];
__device__ float g_co[NSEG][LANES];

__device__ __forceinline__ int zig(int t) {
    int r = t >> 6, j = t & 63;
    return (r << 6) + ((r & 1) ? (63 - j) : j);
}

__device__ __forceinline__ void store_h4(__half* dst, float4 v) {
    __half2 a = __floats2half2_rn(v.x, v.y);
    __half2 b = __floats2half2_rn(v.z, v.w);
    *(uint2*)dst = make_uint2(*(unsigned*)&a, *(unsigned*)&b);
}

// ---------------------------------------------------------------------------
// 1) merged prep: shift-gather (f32->f16) + 4x weight convert, one launch.
// ---------------------------------------------------------------------------
#define GATHER_TOTAL (BB * TT * (CC / 4))
#define GATHER_BLKS  ((GATHER_TOTAL + 255) / 256)
#define WCONV_TOTAL  (CC * CC)
#define WCONV_BLKS   ((WCONV_TOTAL + 255) / 256)

__global__ void prep_kernel(const float* __restrict__ x, __half* __restrict__ xs,
                            const float* __restrict__ w0, const float* __restrict__ w1,
                            const float* __restrict__ w2, const float* __restrict__ w3,
                            __half* __restrict__ wh)
{
    if (blockIdx.x < GATHER_BLKS) {
        int gid = blockIdx.x * 256 + threadIdx.x;
        const int CV = CC / 4;
        if (gid >= GATHER_TOTAL) return;
        int cv = gid % CV;
        int bt = gid / CV;
        int t  = bt % TT;
        int b  = bt / TT;
        int c  = cv * 4;

        int r   = t >> 6;
        int j   = t & 63;
        int col = (r & 1) ? (63 - j) : j;

        int g   = c >> 5;
        int srow = r - c_dy[g];
        int scol = col - c_dx[g];

        float4 val = make_float4(0.f, 0.f, 0.f, 0.f);
        if ((unsigned)srow < (unsigned)HH && (unsigned)scol < (unsigned)WW) {
            val = *(const float4*)&x[((size_t)b * TT + srow * WW + scol) * CC + c];
        }
        store_h4(&xs[((size_t)b * TT + t) * CC + c], val);
    } else {
        int gid = (blockIdx.x - GATHER_BLKS) * 256 + threadIdx.x;
        const int n4 = CC * CC / 4;
        if (gid >= 4 * n4) return;
        int which = gid / n4;
        int idx   = gid % n4;
        const float* w = (which == 0) ? w0 : (which == 1) ? w1 : (which == 2) ? w2 : w3;
        store_h4(&wh[(size_t)gid * 4], ((const float4*)w)[idx]);
    }
}

// ---------------------------------------------------------------------------
// cp.async helpers
// ---------------------------------------------------------------------------
__device__ __forceinline__ void cp_async16(void* smem, const void* gmem) {
    unsigned int s = (unsigned int)__cvta_generic_to_shared(smem);
    asm volatile("cp.async.cg.shared.global [%0], [%1], 16;\n" :: "r"(s), "l"(gmem));
}
__device__ __forceinline__ void cp_commit() { asm volatile("cp.async.commit_group;\n" ::: "memory"); }
template<int N> __device__ __forceinline__ void cp_wait() { asm volatile("cp.async.wait_group %0;\n" :: "n"(N) : "memory"); }

// ---------------------------------------------------------------------------
// GEMM core: 3-stage cp.async, BM=128 BN=128 BK=64, 128 threads (4 warps 2x2),
// warp tile 64x64, f32 accum. 2 CTAs/SM.
// ---------------------------------------------------------------------------
#define G_BM 128
#define G_BN 128
#define G_BK 64
#define G_LD 72
#define G_STAGES 3
#define G_NIT (CC / G_BK)
#define G_ASTG (G_BM * G_LD)
#define G_BSTG (G_BN * G_LD)
#define G_DS (G_STAGES * (G_BM + G_BN) * G_LD * 2)

struct GemmAcc {
    wmma::fragment<wmma::accumulator, 16, 16, 16, float> cf[4][4];
};

__device__ __forceinline__ void gemm_mainloop(
    const __half* __restrict__ A, const __half* __restrict__ Wt,
    int m0, int wrow0, char* dsm, GemmAcc& acc)
{
    __half* Asb = (__half*)dsm;
    __half* Bsb = (__half*)(dsm + G_STAGES * G_ASTG * 2);
    const int tid = threadIdx.x;
    const int warp = tid >> 5;
    const int wm = warp & 1;
    const int wn = warp >> 1;

#pragma unroll
    for (int i = 0; i < 4; i++)
#pragma unroll
        for (int jn = 0; jn < 4; jn++)
            wmma::fill_fragment(acc.cf[i][jn], 0.f);

    auto issue_loads = [&](int st, int k0) {
        __half* as = Asb + st * G_ASTG;
        __half* bs = Bsb + st * G_BSTG;
#pragma unroll
        for (int i = 0; i < 8; i++) {
            int idx = tid + i * 128;
            int row = idx >> 3;
            int c8  = (idx & 7) * 8;
            cp_async16(as + row * G_LD + c8, &A[(size_t)(m0 + row) * CC + k0 + c8]);
        }
#pragma unroll
        for (int i = 0; i < 8; i++) {
            int idx = tid + i * 128;
            int row = idx >> 3;
            int c8  = (idx & 7) * 8;
            cp_async16(bs + row * G_LD + c8, &Wt[(size_t)(wrow0 + row) * CC + k0 + c8]);
        }
    };

    issue_loads(0, 0);
    cp_commit();
    issue_loads(1, G_BK);
    cp_commit();

    for (int ch = 0; ch < G_NIT; ch++) {
        const int st = ch % G_STAGES;
        if (ch < G_NIT - 1) cp_wait<1>();
        else                cp_wait<0>();
        __syncthreads();

        if (ch + 2 < G_NIT) {
            issue_loads((ch + 2) % G_STAGES, (ch + 2) * G_BK);
            cp_commit();
        }

        const __half* as = Asb + st * G_ASTG;
        const __half* bs = Bsb + st * G_BSTG;
#pragma unroll
        for (int kk = 0; kk < G_BK; kk += 16) {
            wmma::fragment<wmma::matrix_a, 16, 16, 16, __half, wmma::row_major> af[4];
            wmma::fragment<wmma::matrix_b, 16, 16, 16, __half, wmma::col_major> bf[4];
#pragma unroll
            for (int i = 0; i < 4; i++)
                wmma::load_matrix_sync(af[i], as + (wm * 64 + i * 16) * G_LD + kk, G_LD);
#pragma unroll
            for (int jn = 0; jn < 4; jn++)
                wmma::load_matrix_sync(bf[jn], bs + (wn * 64 + jn * 16) * G_LD + kk, G_LD);
#pragma unroll
            for (int i = 0; i < 4; i++)
#pragma unroll
                for (int jn = 0; jn < 4; jn++)
                    wmma::mma_sync(acc.cf[i][jn], af[i], bf[jn], acc.cf[i][jn]);
        }
    }
}

// half epilogue: stage f32 per-warp in smem, convert, wide store. SIG: sigmoid.
template <int SIG>
__device__ __forceinline__ void gemm_epi_half(GemmAcc& acc, __half* Co, int m0, int n0, char* dsm)
{
    constexpr int SLD = 68;
    const int tid = threadIdx.x;
    const int warp = tid >> 5;
    const int lid = tid & 31;
    const int wm = warp & 1;
    const int wn = warp >> 1;

    if (SIG) {
#pragma unroll
        for (int i = 0; i < 4; i++)
#pragma unroll
            for (int jn = 0; jn < 4; jn++)
#pragma unroll
                for (int e = 0; e < acc.cf[i][jn].num_elements; e++)
                    acc.cf[i][jn].x[e] = 1.f / (1.f + __expf(-acc.cf[i][jn].x[e]));
    }
    __syncthreads();
    float* buf = (float*)dsm + warp * 16 * SLD;
#pragma unroll
    for (int i = 0; i < 4; i++) {
#pragma unroll
        for (int jn = 0; jn < 4; jn++)
            wmma::store_matrix_sync(buf + jn * 16, acc.cf[i][jn], SLD, wmma::mem_row_major);
        __syncwarp();
#pragma unroll
        for (int rr = 0; rr < 4; rr++) {
            int row = rr * 4 + (lid >> 3);
            int col = (lid & 7) * 8;
            const float* s = buf + row * SLD + col;
            __half h[8];
#pragma unroll
            for (int e = 0; e < 8; e++) h[e] = __float2half(s[e]);
            *(uint4*)&Co[(size_t)(m0 + wm * 64 + i * 16 + row) * CC + n0 + wn * 64 + col] = *(uint4*)h;
        }
        __syncwarp();
    }
}

__device__ __forceinline__ void gemm_epi_float(GemmAcc& acc, float* Co, int m0, int n0)
{
    const int warp = threadIdx.x >> 5;
    const int wm = warp & 1;
    const int wn = warp >> 1;
#pragma unroll
    for (int i = 0; i < 4; i++)
#pragma unroll
        for (int jn = 0; jn < 4; jn++)
            wmma::store_matrix_sync(
                &Co[(size_t)(m0 + wm * 64 + i * 16) * CC + n0 + wn * 64 + jn * 16],
                acc.cf[i][jn], CC, wmma::mem_row_major);
}

// ---------------------------------------------------------------------------
// 2a) fused k/v/sr GEMM: one launch, N=2304. blockIdx.x: 0-5 -> k (f16),
//     6-11 -> v (f16), 12-17 -> sr (f16 + sigmoid).
// ---------------------------------------------------------------------------
__global__ __launch_bounds__(128, 2)
void gemm_kvsr_kernel(const __half* __restrict__ A, const __half* __restrict__ Wall,
                      __half* __restrict__ Ko, __half* __restrict__ Vo, __half* __restrict__ SRo)
{
    extern __shared__ char dsm[];
    const int which = blockIdx.x / 6;
    const int n0 = (blockIdx.x % 6) * G_BN;
    const int m0 = blockIdx.y * G_BM;

    GemmAcc acc;
    gemm_mainloop(A, Wall, m0, which * CC + n0, dsm, acc);

    if (which == 0)      gemm_epi_half<0>(acc, Ko, m0, n0, dsm);
    else if (which == 1) gemm_epi_half<0>(acc, Vo, m0, n0, dsm);
    else                 gemm_epi_half<1>(acc, SRo, m0, n0, dsm);
}

// ---------------------------------------------------------------------------
// 2b) output GEMM: out = prod @ ow^T (f32 out)
// ---------------------------------------------------------------------------
__global__ __launch_bounds__(128, 2)
void gemm_out_kernel(const __half* __restrict__ A, const __half* __restrict__ Wt,
                     float* __restrict__ Co)
{
    extern __shared__ char dsm[];
    const int n0 = blockIdx.x * G_BN;
    const int m0 = blockIdx.y * G_BM;
    GemmAcc acc;
    gemm_mainloop(A, Wt, m0, n0, dsm, acc);
    gemm_epi_float(acc, Co, m0, n0);
}

// ---------------------------------------------------------------------------
// 3) WKV, chunked parallel scan. 2 adjacent channels per thread (__half2 I/O).
// ---------------------------------------------------------------------------
template <int PASS>
__global__ __launch_bounds__(128)
void wkv_summary_kernel(const __half* __restrict__ kk, const __half* __restrict__ vv,
                        const float* __restrict__ decay)
{
    int lane2 = blockIdx.x * 128 + threadIdx.x;             // 0..LANES2-1
    int seg   = blockIdx.y;
    int lane  = lane2 * 2;
    int b = lane / CC;
    int c = lane % CC;
    const float invT = 1.f / (float)TT;
    float2 wv = *(const float2*)&decay[PASS * CC + c];
    const float w0 = wv.x * invT, w1 = wv.y * invT;
    const size_t base = (size_t)b * TT * CC + c;

    float p0 = 0.f, q0 = 0.f, o0 = -1e38f;
    float p1 = 0.f, q1 = 0.f, o1 = -1e38f;
#pragma unroll 4
    for (int t = 0; t < SEG; t++) {
        int tt = seg * SEG + t;
        int pidx = (PASS == 0) ? tt : zig(tt);
        size_t idx = base + (size_t)pidx * CC;
        float2 kf = __half22float2(*(const __half2*)&kk[idx]);
        float2 vf = __half22float2(*(const __half2*)&vv[idx]);

        float wo0 = w0 + o0;
        float no0 = fmaxf(wo0, kf.x);
        float A0  = __expf(wo0 - no0);
        float B0  = __expf(kf.x - no0);
        p0 = A0 * p0 + B0 * vf.x;
        q0 = A0 * q0 + B0;
        o0 = no0;

        float wo1 = w1 + o1;
        float no1 = fmaxf(wo1, kf.y);
        float A1  = __expf(wo1 - no1);
        float B1  = __expf(kf.y - no1);
        p1 = A1 * p1 + B1 * vf.y;
        q1 = A1 * q1 + B1;
        o1 = no1;
    }
    *(float2*)&g_sp[seg][lane] = make_float2(p0, p1);
    *(float2*)&g_sq[seg][lane] = make_float2(q0, q1);
    *(float2*)&g_so[seg][lane] = make_float2(o0, o1);
}

// Scan with explicit register-ring software prefetch (MLP ~= PF instead of 1).
template <int PASS>
__global__ __launch_bounds__(128)
void wkv_scan_kernel(const float* __restrict__ decay)
{
    int lane = blockIdx.x * 128 + threadIdx.x;
    if (lane >= LANES) return;
    int c = lane % CC;
    const float w  = decay[PASS * CC + c] * (1.f / (float)TT);
    const float wL = w * (float)SEG;

    constexpr int PF = 16;
    float bp[PF], bq[PF], bo[PF];
#pragma unroll
    for (int i = 0; i < PF; i++) {
        bp[i] = g_sp[i][lane];
        bq[i] = g_sq[i][lane];
        bo[i] = g_so[i][lane];
    }

    float p = 0.f, q = 0.f, o = -1e38f;
#pragma unroll
    for (int seg = 0; seg < NSEG; seg++) {
        g_cp[seg][lane] = p;
        g_cq[seg][lane] = q;
        g_co[seg][lane] = o;

        const int slot = seg % PF;
        float p2 = bp[slot];
        float q2 = bq[slot];
        float o2 = bo[slot];
        if (seg + PF < NSEG) {
            bp[slot] = g_sp[seg + PF][lane];
            bq[slot] = g_sq[seg + PF][lane];
            bo[slot] = g_so[seg + PF][lane];
        }

        float o1 = o + wL;
        float no = fmaxf(o1, o2);
        float e1 = __expf(o1 - no);
        float e2 = __expf(o2 - no);
        p = e1 * p + e2 * p2;
        q = e1 * q + e2 * q2;
        o = no;
    }
}

// PASS 0: plain replay, writes y (f16).
// PASS 1: replay fused with ewmul: writes sr[idx] * y (f16) -> prod.
template <int PASS>
__global__ __launch_bounds__(128)
void wkv_replay_kernel(const __half* __restrict__ kk, const __half* __restrict__ vv,
                       const float* __restrict__ decay, const float* __restrict__ first,
                       const __half* __restrict__ srr, __half* __restrict__ yo)
{
    int lane2 = blockIdx.x * 128 + threadIdx.x;
    int seg   = blockIdx.y;
    int lane  = lane2 * 2;
    int b = lane / CC;
    int c = lane % CC;
    const float invT = 1.f / (float)TT;
    float2 wv = *(const float2*)&decay[PASS * CC + c];
    float2 uv = *(const float2*)&first[PASS * CC + c];
    const float w0 = wv.x * invT, w1 = wv.y * invT;
    const float u0 = uv.x * invT, u1 = uv.y * invT;
    const size_t base = (size_t)b * TT * CC + c;

    float2 pv = *(const float2*)&g_cp[seg][lane];
    float2 qv = *(const float2*)&g_cq[seg][lane];
    float2 ov = *(const float2*)&g_co[seg][lane];
    float p0 = pv.x, q0 = qv.x, o0 = ov.x;
    float p1 = pv.y, q1 = qv.y, o1 = ov.y;

#pragma unroll 4
    for (int t = 0; t < SEG; t++) {
        int tt = seg * SEG + t;
        int pidx = (PASS == 0) ? tt : zig(tt);
        size_t idx = base + (size_t)pidx * CC;
        float2 kf = __half22float2(*(const __half2*)&kk[idx]);
        float2 vf = __half22float2(*(const __half2*)&vv[idx]);

        float uk0 = u0 + kf.x;
        float no0 = fmaxf(o0, uk0);
        float Ac0 = __expf(o0 - no0);
        float Bc0 = __expf(uk0 - no0);
        float y0  = __fdividef(Ac0 * p0 + Bc0 * vf.x, Ac0 * q0 + Bc0);

        float uk1 = u1 + kf.y;
        float no1 = fmaxf(o1, uk1);
        float Ac1 = __expf(o1 - no1);
        float Bc1 = __expf(uk1 - no1);
        float y1  = __fdividef(Ac1 * p1 + Bc1 * vf.y, Ac1 * q1 + Bc1);

        if (PASS == 1) {
            float2 sf = __half22float2(*(const __half2*)&srr[idx]);
            y0 *= sf.x;
            y1 *= sf.y;
        }
        *(__half2*)&yo[idx] = __floats2half2_rn(y0, y1);

        float wo0 = w0 + o0;
        float m0  = fmaxf(wo0, kf.x);
        float A0  = __expf(wo0 - m0);
        float B0  = __expf(kf.x - m0);
        p0 = A0 * p0 + B0 * vf.x;
        q0 = A0 * q0 + B0;
        o0 = m0;

        float wo1 = w1 + o1;
        float m1  = fmaxf(wo1, kf.y);
        float A1  = __expf(wo1 - m1);
        float B1  = __expf(kf.y - m1);
        p1 = A1 * p1 + B1 * vf.y;
        q1 = A1 * q1 + B1;
        o1 = m1;
    }
}

// ---------------------------------------------------------------------------
// Launch
// ---------------------------------------------------------------------------
extern "C" void kernel_launch(void* const* d_in, const int* in_sizes, int n_in,
                              void* d_out, int out_size)
{
    const float* x    = (const float*)d_in[0];
    const float* kw   = (const float*)d_in[1];
    const float* vw   = (const float*)d_in[2];
    const float* rw   = (const float*)d_in[3];
    const float* ow   = (const float*)d_in[4];
    const float* sdec = (const float*)d_in[5];
    const float* sfst = (const float*)d_in[6];
    float* out        = (float*)d_out;

    __half *xs, *prod, *wh, *k, *v, *sr, *v1;
    cudaGetSymbolAddress((void**)&xs,   g_xsh);
    cudaGetSymbolAddress((void**)&prod, g_prod);
    cudaGetSymbolAddress((void**)&wh,   g_w);
    cudaGetSymbolAddress((void**)&k,    g_k);
    cudaGetSymbolAddress((void**)&v,    g_v);
    cudaGetSymbolAddress((void**)&sr,   g_sr);
    cudaGetSymbolAddress((void**)&v1,   g_v1);

    cudaFuncSetAttribute(gemm_kvsr_kernel, cudaFuncAttributeMaxDynamicSharedMemorySize, G_DS);
    cudaFuncSetAttribute(gemm_out_kernel,  cudaFuncAttributeMaxDynamicSharedMemorySize, G_DS);

    // 1) merged prep: gather + weight converts in one launch
    prep_kernel<<<GATHER_BLKS + WCONV_BLKS, 256>>>(x, xs, kw, vw, rw, ow, wh);

    // 2) fused k/v/sr GEMM (one launch, N=2304)
    {
        dim3 grid(18, MM / G_BM);
        gemm_kvsr_kernel<<<grid, 128, G_DS>>>(xs, wh, k, v, sr);
    }

    // 3) WKV pass 1 (t order) then pass 2 (zigzag involution order).
    //    Pass-2 replay fuses the sr multiply and writes prod directly.
    {
        dim3 gseg(LANES2 / 128, NSEG);
        int  gscan = LANES / 128;
        wkv_summary_kernel<0><<<gseg, 128>>>(k, v, sdec);
        wkv_scan_kernel<0><<<gscan, 128>>>(sdec);
        wkv_replay_kernel<0><<<gseg, 128>>>(k, v, sdec, sfst, nullptr, v1);

        wkv_summary_kernel<1><<<gseg, 128>>>(k, v1, sdec);
        wkv_scan_kernel<1><<<gscan, 128>>>(sdec);
        wkv_replay_kernel<1><<<gseg, 128>>>(k, v1, sdec, sfst, sr, prod);
    }

    // 4) out = prod @ ow^T
    {
        dim3 grid(CC / G_BN, MM / G_BM);
        gemm_out_kernel<<<grid, 128, G_DS>>>(prod, wh + 3 * (size_t)CC * CC, out);
    }
}

// round 17
// speedup vs baseline: 1.5190x; 1.0134x over previous
#include <cuda_runtime.h>
#include <cuda_bf16.h>
#include <cuda_fp16.h>
#include <mma.h>
#include <cstdint>

using namespace nvcuda;

// Problem constants (fixed by setup_inputs)
#define BB 8
#define HH 64
#define WW 64
#define TT 4096          // HH*WW
#define CC 768
#define MM (BB * TT)     // 32768
#define ELEMS (BB * TT * CC)
#define SEG 64
#define NSEG 64
#define LANES (BB * CC)  // 6144
#define LANES2 (LANES / 2)

// Shift table (24 groups of 32 channels)
__constant__ int c_dy[24] = {0, 0, 1, -1, 1, -1, 1, -1, 0, 0, 2, -2, 2, -2, 2, -2, 2, 1, 2, 1, -2, -1, -2, -1};
__constant__ int c_dx[24] = {1, -1, 0, 0, 1, -1, -1, 1, 2, -2, 0, 0, 2, -2, -2, 2, 1, 2, -1, -2, 1, 2, -1, -2};

// Scratch buffers (no cudaMalloc allowed)
__device__ __half g_xsh[ELEMS];
__device__ __half g_prod[ELEMS];
__device__ __half g_w[4][CC * CC];
__device__ __half g_k[ELEMS];
__device__ __half g_v[ELEMS];
__device__ __half g_sr[ELEMS];
__device__ __half g_v1[ELEMS];
// WKV segment summaries + carry-in states
__device__ float g_sp[NSEG][LANES];
__device__ float g_sq[NSEG][LANES];
__device__ float g_so[NSEG][LANES];
__device__ float g_cp[NSEG][LANES];
__device__ float g_cq[NSEG][LANES];
__device__ float g_co[NSEG][LANES];

__device__ __forceinline__ int zig(int t) {
    int r = t >> 6, j = t & 63;
    return (r << 6) + ((r & 1) ? (63 - j) : j);
}

__device__ __forceinline__ void store_h4(__half* dst, float4 v) {
    __half2 a = __floats2half2_rn(v.x, v.y);
    __half2 b = __floats2half2_rn(v.z, v.w);
    *(uint2*)dst = make_uint2(*(unsigned*)&a, *(unsigned*)&b);
}

// ---------------------------------------------------------------------------
// 1) merged prep: shift-gather (f32->f16) + 4x weight convert, one launch.
// ---------------------------------------------------------------------------
#define GATHER_TOTAL (BB * TT * (CC / 4))
#define GATHER_BLKS  ((GATHER_TOTAL + 255) / 256)
#define WCONV_TOTAL  (CC * CC)
#define WCONV_BLKS   ((WCONV_TOTAL + 255) / 256)

__global__ void prep_kernel(const float* __restrict__ x, __half* __restrict__ xs,
                            const float* __restrict__ w0, const float* __restrict__ w1,
                            const float* __restrict__ w2, const float* __restrict__ w3,
                            __half* __restrict__ wh)
{
    if (blockIdx.x < GATHER_BLKS) {
        int gid = blockIdx.x * 256 + threadIdx.x;
        const int CV = CC / 4;
        if (gid >= GATHER_TOTAL) return;
        int cv = gid % CV;
        int bt = gid / CV;
        int t  = bt % TT;
        int b  = bt / TT;
        int c  = cv * 4;

        int r   = t >> 6;
        int j   = t & 63;
        int col = (r & 1) ? (63 - j) : j;

        int g   = c >> 5;
        int srow = r - c_dy[g];
        int scol = col - c_dx[g];

        float4 val = make_float4(0.f, 0.f, 0.f, 0.f);
        if ((unsigned)srow < (unsigned)HH && (unsigned)scol < (unsigned)WW) {
            val = *(const float4*)&x[((size_t)b * TT + srow * WW + scol) * CC + c];
        }
        store_h4(&xs[((size_t)b * TT + t) * CC + c], val);
    } else {
        int gid = (blockIdx.x - GATHER_BLKS) * 256 + threadIdx.x;
        const int n4 = CC * CC / 4;
        if (gid >= 4 * n4) return;
        int which = gid / n4;
        int idx   = gid % n4;
        const float* w = (which == 0) ? w0 : (which == 1) ? w1 : (which == 2) ? w2 : w3;
        store_h4(&wh[(size_t)gid * 4], ((const float4*)w)[idx]);
    }
}

// ---------------------------------------------------------------------------
// cp.async helpers
// ---------------------------------------------------------------------------
__device__ __forceinline__ void cp_async16(void* smem, const void* gmem) {
    unsigned int s = (unsigned int)__cvta_generic_to_shared(smem);
    asm volatile("cp.async.cg.shared.global [%0], [%1], 16;\n" :: "r"(s), "l"(gmem));
}
__device__ __forceinline__ void cp_commit() { asm volatile("cp.async.commit_group;\n" ::: "memory"); }
template<int N> __device__ __forceinline__ void cp_wait() { asm volatile("cp.async.wait_group %0;\n" :: "n"(N) : "memory"); }

// ---------------------------------------------------------------------------
// GEMM core: 3-stage cp.async, BM=128 BN=128 BK=64, 128 threads (4 warps 2x2),
// warp tile 64x64, f32 accum. 2 CTAs/SM.
// ---------------------------------------------------------------------------
#define G_BM 128
#define G_BN 128
#define G_BK 64
#define G_LD 72
#define G_STAGES 3
#define G_NIT (CC / G_BK)
#define G_ASTG (G_BM * G_LD)
#define G_BSTG (G_BN * G_LD)
#define G_DS (G_STAGES * (G_BM + G_BN) * G_LD * 2)

struct GemmAcc {
    wmma::fragment<wmma::accumulator, 16, 16, 16, float> cf[4][4];
};

__device__ __forceinline__ void gemm_mainloop(
    const __half* __restrict__ A, const __half* __restrict__ Wt,
    int m0, int wrow0, char* dsm, GemmAcc& acc)
{
    __half* Asb = (__half*)dsm;
    __half* Bsb = (__half*)(dsm + G_STAGES * G_ASTG * 2);
    const int tid = threadIdx.x;
    const int warp = tid >> 5;
    const int wm = warp & 1;
    const int wn = warp >> 1;

#pragma unroll
    for (int i = 0; i < 4; i++)
#pragma unroll
        for (int jn = 0; jn < 4; jn++)
            wmma::fill_fragment(acc.cf[i][jn], 0.f);

    auto issue_loads = [&](int st, int k0) {
        __half* as = Asb + st * G_ASTG;
        __half* bs = Bsb + st * G_BSTG;
#pragma unroll
        for (int i = 0; i < 8; i++) {
            int idx = tid + i * 128;
            int row = idx >> 3;
            int c8  = (idx & 7) * 8;
            cp_async16(as + row * G_LD + c8, &A[(size_t)(m0 + row) * CC + k0 + c8]);
        }
#pragma unroll
        for (int i = 0; i < 8; i++) {
            int idx = tid + i * 128;
            int row = idx >> 3;
            int c8  = (idx & 7) * 8;
            cp_async16(bs + row * G_LD + c8, &Wt[(size_t)(wrow0 + row) * CC + k0 + c8]);
        }
    };

    issue_loads(0, 0);
    cp_commit();
    issue_loads(1, G_BK);
    cp_commit();

    for (int ch = 0; ch < G_NIT; ch++) {
        const int st = ch % G_STAGES;
        if (ch < G_NIT - 1) cp_wait<1>();
        else                cp_wait<0>();
        __syncthreads();

        if (ch + 2 < G_NIT) {
            issue_loads((ch + 2) % G_STAGES, (ch + 2) * G_BK);
            cp_commit();
        }

        const __half* as = Asb + st * G_ASTG;
        const __half* bs = Bsb + st * G_BSTG;
#pragma unroll
        for (int kk = 0; kk < G_BK; kk += 16) {
            wmma::fragment<wmma::matrix_a, 16, 16, 16, __half, wmma::row_major> af[4];
            wmma::fragment<wmma::matrix_b, 16, 16, 16, __half, wmma::col_major> bf[4];
#pragma unroll
            for (int i = 0; i < 4; i++)
                wmma::load_matrix_sync(af[i], as + (wm * 64 + i * 16) * G_LD + kk, G_LD);
#pragma unroll
            for (int jn = 0; jn < 4; jn++)
                wmma::load_matrix_sync(bf[jn], bs + (wn * 64 + jn * 16) * G_LD + kk, G_LD);
#pragma unroll
            for (int i = 0; i < 4; i++)
#pragma unroll
                for (int jn = 0; jn < 4; jn++)
                    wmma::mma_sync(acc.cf[i][jn], af[i], bf[jn], acc.cf[i][jn]);
        }
    }
}

// half epilogue: stage f32 per-warp in smem, convert, wide store. SIG: sigmoid.
template <int SIG>
__device__ __forceinline__ void gemm_epi_half(GemmAcc& acc, __half* Co, int m0, int n0, char* dsm)
{
    constexpr int SLD = 68;
    const int tid = threadIdx.x;
    const int warp = tid >> 5;
    const int lid = tid & 31;
    const int wm = warp & 1;
    const int wn = warp >> 1;

    if (SIG) {
#pragma unroll
        for (int i = 0; i < 4; i++)
#pragma unroll
            for (int jn = 0; jn < 4; jn++)
#pragma unroll
                for (int e = 0; e < acc.cf[i][jn].num_elements; e++)
                    acc.cf[i][jn].x[e] = 1.f / (1.f + __expf(-acc.cf[i][jn].x[e]));
    }
    __syncthreads();
    float* buf = (float*)dsm + warp * 16 * SLD;
#pragma unroll
    for (int i = 0; i < 4; i++) {
#pragma unroll
        for (int jn = 0; jn < 4; jn++)
            wmma::store_matrix_sync(buf + jn * 16, acc.cf[i][jn], SLD, wmma::mem_row_major);
        __syncwarp();
#pragma unroll
        for (int rr = 0; rr < 4; rr++) {
            int row = rr * 4 + (lid >> 3);
            int col = (lid & 7) * 8;
            const float* s = buf + row * SLD + col;
            __half h[8];
#pragma unroll
            for (int e = 0; e < 8; e++) h[e] = __float2half(s[e]);
            *(uint4*)&Co[(size_t)(m0 + wm * 64 + i * 16 + row) * CC + n0 + wn * 64 + col] = *(uint4*)h;
        }
        __syncwarp();
    }
}

__device__ __forceinline__ void gemm_epi_float(GemmAcc& acc, float* Co, int m0, int n0)
{
    const int warp = threadIdx.x >> 5;
    const int wm = warp & 1;
    const int wn = warp >> 1;
#pragma unroll
    for (int i = 0; i < 4; i++)
#pragma unroll
        for (int jn = 0; jn < 4; jn++)
            wmma::store_matrix_sync(
                &Co[(size_t)(m0 + wm * 64 + i * 16) * CC + n0 + wn * 64 + jn * 16],
                acc.cf[i][jn], CC, wmma::mem_row_major);
}

// ---------------------------------------------------------------------------
// 2a) fused k/v/sr GEMM: one launch, N=2304. blockIdx.x: 0-5 -> k (f16),
//     6-11 -> v (f16), 12-17 -> sr (f16 + sigmoid).
// ---------------------------------------------------------------------------
__global__ __launch_bounds__(128, 2)
void gemm_kvsr_kernel(const __half* __restrict__ A, const __half* __restrict__ Wall,
                      __half* __restrict__ Ko, __half* __restrict__ Vo, __half* __restrict__ SRo)
{
    extern __shared__ char dsm[];
    const int which = blockIdx.x / 6;
    const int n0 = (blockIdx.x % 6) * G_BN;
    const int m0 = blockIdx.y * G_BM;

    GemmAcc acc;
    gemm_mainloop(A, Wall, m0, which * CC + n0, dsm, acc);

    if (which == 0)      gemm_epi_half<0>(acc, Ko, m0, n0, dsm);
    else if (which == 1) gemm_epi_half<0>(acc, Vo, m0, n0, dsm);
    else                 gemm_epi_half<1>(acc, SRo, m0, n0, dsm);
}

// ---------------------------------------------------------------------------
// 2b) output GEMM: out = prod @ ow^T (f32 out)
// ---------------------------------------------------------------------------
__global__ __launch_bounds__(128, 2)
void gemm_out_kernel(const __half* __restrict__ A, const __half* __restrict__ Wt,
                     float* __restrict__ Co)
{
    extern __shared__ char dsm[];
    const int n0 = blockIdx.x * G_BN;
    const int m0 = blockIdx.y * G_BM;
    GemmAcc acc;
    gemm_mainloop(A, Wt, m0, n0, dsm, acc);
    gemm_epi_float(acc, Co, m0, n0);
}

// ---------------------------------------------------------------------------
// 3) WKV, chunked parallel scan. 2 adjacent channels per thread (__half2 I/O).
// ---------------------------------------------------------------------------
template <int PASS>
__global__ __launch_bounds__(128)
void wkv_summary_kernel(const __half* __restrict__ kk, const __half* __restrict__ vv,
                        const float* __restrict__ decay)
{
    int lane2 = blockIdx.x * 128 + threadIdx.x;             // 0..LANES2-1
    int seg   = blockIdx.y;
    int lane  = lane2 * 2;
    int b = lane / CC;
    int c = lane % CC;
    const float invT = 1.f / (float)TT;
    float2 wv = *(const float2*)&decay[PASS * CC + c];
    const float w0 = wv.x * invT, w1 = wv.y * invT;
    const size_t base = (size_t)b * TT * CC + c;

    float p0 = 0.f, q0 = 0.f, o0 = -1e38f;
    float p1 = 0.f, q1 = 0.f, o1 = -1e38f;
#pragma unroll 4
    for (int t = 0; t < SEG; t++) {
        int tt = seg * SEG + t;
        int pidx = (PASS == 0) ? tt : zig(tt);
        size_t idx = base + (size_t)pidx * CC;
        float2 kf = __half22float2(*(const __half2*)&kk[idx]);
        float2 vf = __half22float2(*(const __half2*)&vv[idx]);

        float wo0 = w0 + o0;
        float no0 = fmaxf(wo0, kf.x);
        float A0  = __expf(wo0 - no0);
        float B0  = __expf(kf.x - no0);
        p0 = A0 * p0 + B0 * vf.x;
        q0 = A0 * q0 + B0;
        o0 = no0;

        float wo1 = w1 + o1;
        float no1 = fmaxf(wo1, kf.y);
        float A1  = __expf(wo1 - no1);
        float B1  = __expf(kf.y - no1);
        p1 = A1 * p1 + B1 * vf.y;
        q1 = A1 * q1 + B1;
        o1 = no1;
    }
    *(float2*)&g_sp[seg][lane] = make_float2(p0, p1);
    *(float2*)&g_sq[seg][lane] = make_float2(q0, q1);
    *(float2*)&g_so[seg][lane] = make_float2(o0, o1);
}

// Scan with explicit register-ring software prefetch (MLP ~= PF instead of 1).
template <int PASS>
__global__ __launch_bounds__(128)
void wkv_scan_kernel(const float* __restrict__ decay)
{
    int lane = blockIdx.x * 128 + threadIdx.x;
    if (lane >= LANES) return;
    int c = lane % CC;
    const float w  = decay[PASS * CC + c] * (1.f / (float)TT);
    const float wL = w * (float)SEG;

    constexpr int PF = 16;
    float bp[PF], bq[PF], bo[PF];
#pragma unroll
    for (int i = 0; i < PF; i++) {
        bp[i] = g_sp[i][lane];
        bq[i] = g_sq[i][lane];
        bo[i] = g_so[i][lane];
    }

    float p = 0.f, q = 0.f, o = -1e38f;
#pragma unroll
    for (int seg = 0; seg < NSEG; seg++) {
        g_cp[seg][lane] = p;
        g_cq[seg][lane] = q;
        g_co[seg][lane] = o;

        const int slot = seg % PF;
        float p2 = bp[slot];
        float q2 = bq[slot];
        float o2 = bo[slot];
        if (seg + PF < NSEG) {
            bp[slot] = g_sp[seg + PF][lane];
            bq[slot] = g_sq[seg + PF][lane];
            bo[slot] = g_so[seg + PF][lane];
        }

        float o1 = o + wL;
        float no = fmaxf(o1, o2);
        float e1 = __expf(o1 - no);
        float e2 = __expf(o2 - no);
        p = e1 * p + e2 * p2;
        q = e1 * q + e2 * q2;
        o = no;
    }
}

// ---------------------------------------------------------------------------
// Fused pass-1 replay + pass-2 summary. Segment == image row; zigzag is
// row-local (even rows forward, odd rows reversed), so the pass-2 summary of
// segment seg consumes exactly the y values this kernel generates for seg.
// Even rows: append recurrence. Odd rows: prepend via block-operator form
//   O' = max(k + m*w2, O); P' = e^{k+m*w2-O'}*y + e^{O-O'}*P  (m = count).
// Writes y (f16) to v1 AND the pass-2 segment summary to g_sp/sq/so.
// ---------------------------------------------------------------------------
__global__ __launch_bounds__(128)
void wkv_mid_kernel(const __half* __restrict__ kk, const __half* __restrict__ vv,
                    const float* __restrict__ decay, const float* __restrict__ first,
                    __half* __restrict__ yo)
{
    int lane2 = blockIdx.x * 128 + threadIdx.x;
    int seg   = blockIdx.y;
    int lane  = lane2 * 2;
    int b = lane / CC;
    int c = lane % CC;
    const float invT = 1.f / (float)TT;
    float2 wv  = *(const float2*)&decay[0 * CC + c];
    float2 uv  = *(const float2*)&first[0 * CC + c];
    float2 w2v = *(const float2*)&decay[1 * CC + c];
    const float w0 = wv.x * invT,  w1 = wv.y * invT;
    const float u0 = uv.x * invT,  u1 = uv.y * invT;
    const float s0 = w2v.x * invT, s1 = w2v.y * invT;   // pass-2 decay
    const size_t base = (size_t)b * TT * CC + c;
    const bool odd = (seg & 1);

    // pass-1 replay carry
    float2 pv = *(const float2*)&g_cp[seg][lane];
    float2 qv = *(const float2*)&g_cq[seg][lane];
    float2 ov = *(const float2*)&g_co[seg][lane];
    float p0 = pv.x, q0 = qv.x, o0 = ov.x;
    float p1 = pv.y, q1 = qv.y, o1 = ov.y;

    // pass-2 segment summary accumulators
    float P0 = 0.f, Q0 = 0.f, O0 = -1e38f;
    float P1 = 0.f, Q1 = 0.f, O1 = -1e38f;

#pragma unroll 4
    for (int t = 0; t < SEG; t++) {
        size_t idx = base + (size_t)(seg * SEG + t) * CC;   // pass-1: t-order
        float2 kf = __half22float2(*(const __half2*)&kk[idx]);
        float2 vf = __half22float2(*(const __half2*)&vv[idx]);

        float uk0 = u0 + kf.x;
        float no0 = fmaxf(o0, uk0);
        float Ac0 = __expf(o0 - no0);
        float Bc0 = __expf(uk0 - no0);
        float y0  = __fdividef(Ac0 * p0 + Bc0 * vf.x, Ac0 * q0 + Bc0);

        float uk1 = u1 + kf.y;
        float no1 = fmaxf(o1, uk1);
        float Ac1 = __expf(o1 - no1);
        float Bc1 = __expf(uk1 - no1);
        float y1  = __fdividef(Ac1 * p1 + Bc1 * vf.y, Ac1 * q1 + Bc1);

        __half2 yh = __floats2half2_rn(y0, y1);
        *(__half2*)&yo[idx] = yh;

        // f16-rounded y for the summary (matches what replay<1> will read)
        float2 ys = __half22float2(yh);

        if (!odd) {
            // append (zig order == forward)
            float a0 = s0 + O0;
            float n0s = fmaxf(a0, kf.x);
            P0 = __expf(a0 - n0s) * P0 + __expf(kf.x - n0s) * ys.x;
            Q0 = __expf(a0 - n0s) * Q0 + __expf(kf.x - n0s);
            O0 = n0s;
            float a1 = s1 + O1;
            float n1s = fmaxf(a1, kf.y);
            P1 = __expf(a1 - n1s) * P1 + __expf(kf.y - n1s) * ys.y;
            Q1 = __expf(a1 - n1s) * Q1 + __expf(kf.y - n1s);
            O1 = n1s;
        } else {
            // prepend (zig order == reverse); m = t elements already in block
            float e0 = kf.x + (float)t * s0;
            float n0s = fmaxf(e0, O0);
            P0 = __expf(e0 - n0s) * ys.x + __expf(O0 - n0s) * P0;
            Q0 = __expf(e0 - n0s)        + __expf(O0 - n0s) * Q0;
            O0 = n0s;
            float e1 = kf.y + (float)t * s1;
            float n1s = fmaxf(e1, O1);
            P1 = __expf(e1 - n1s) * ys.y + __expf(O1 - n1s) * P1;
            Q1 = __expf(e1 - n1s)        + __expf(O1 - n1s) * Q1;
            O1 = n1s;
        }

        // pass-1 state update
        float wo0 = w0 + o0;
        float m0  = fmaxf(wo0, kf.x);
        float A0  = __expf(wo0 - m0);
        float B0  = __expf(kf.x - m0);
        p0 = A0 * p0 + B0 * vf.x;
        q0 = A0 * q0 + B0;
        o0 = m0;

        float wo1 = w1 + o1;
        float m1  = fmaxf(wo1, kf.y);
        float A1  = __expf(wo1 - m1);
        float B1  = __expf(kf.y - m1);
        p1 = A1 * p1 + B1 * vf.y;
        q1 = A1 * q1 + B1;
        o1 = m1;
    }

    *(float2*)&g_sp[seg][lane] = make_float2(P0, P1);
    *(float2*)&g_sq[seg][lane] = make_float2(Q0, Q1);
    *(float2*)&g_so[seg][lane] = make_float2(O0, O1);
}

// Pass-2 replay fused with ewmul: writes sr[idx] * y (f16) -> prod.
__global__ __launch_bounds__(128)
void wkv_replay2_kernel(const __half* __restrict__ kk, const __half* __restrict__ vv,
                        const float* __restrict__ decay, const float* __restrict__ first,
                        const __half* __restrict__ srr, __half* __restrict__ yo)
{
    int lane2 = blockIdx.x * 128 + threadIdx.x;
    int seg   = blockIdx.y;
    int lane  = lane2 * 2;
    int b = lane / CC;
    int c = lane % CC;
    const float invT = 1.f / (float)TT;
    float2 wv = *(const float2*)&decay[1 * CC + c];
    float2 uv = *(const float2*)&first[1 * CC + c];
    const float w0 = wv.x * invT, w1 = wv.y * invT;
    const float u0 = uv.x * invT, u1 = uv.y * invT;
    const size_t base = (size_t)b * TT * CC + c;

    float2 pv = *(const float2*)&g_cp[seg][lane];
    float2 qv = *(const float2*)&g_cq[seg][lane];
    float2 ov = *(const float2*)&g_co[seg][lane];
    float p0 = pv.x, q0 = qv.x, o0 = ov.x;
    float p1 = pv.y, q1 = qv.y, o1 = ov.y;

#pragma unroll 4
    for (int t = 0; t < SEG; t++) {
        int pidx = zig(seg * SEG + t);
        size_t idx = base + (size_t)pidx * CC;
        float2 kf = __half22float2(*(const __half2*)&kk[idx]);
        float2 vf = __half22float2(*(const __half2*)&vv[idx]);

        float uk0 = u0 + kf.x;
        float no0 = fmaxf(o0, uk0);
        float Ac0 = __expf(o0 - no0);
        float Bc0 = __expf(uk0 - no0);
        float y0  = __fdividef(Ac0 * p0 + Bc0 * vf.x, Ac0 * q0 + Bc0);

        float uk1 = u1 + kf.y;
        float no1 = fmaxf(o1, uk1);
        float Ac1 = __expf(o1 - no1);
        float Bc1 = __expf(uk1 - no1);
        float y1  = __fdividef(Ac1 * p1 + Bc1 * vf.y, Ac1 * q1 + Bc1);

        float2 sf = __half22float2(*(const __half2*)&srr[idx]);
        y0 *= sf.x;
        y1 *= sf.y;
        *(__half2*)&yo[idx] = __floats2half2_rn(y0, y1);

        float wo0 = w0 + o0;
        float m0  = fmaxf(wo0, kf.x);
        float A0  = __expf(wo0 - m0);
        float B0  = __expf(kf.x - m0);
        p0 = A0 * p0 + B0 * vf.x;
        q0 = A0 * q0 + B0;
        o0 = m0;

        float wo1 = w1 + o1;
        float m1  = fmaxf(wo1, kf.y);
        float A1  = __expf(wo1 - m1);
        float B1  = __expf(kf.y - m1);
        p1 = A1 * p1 + B1 * vf.y;
        q1 = A1 * q1 + B1;
        o1 = m1;
    }
}

// ---------------------------------------------------------------------------
// Launch
// ---------------------------------------------------------------------------
extern "C" void kernel_launch(void* const* d_in, const int* in_sizes, int n_in,
                              void* d_out, int out_size)
{
    const float* x    = (const float*)d_in[0];
    const float* kw   = (const float*)d_in[1];
    const float* vw   = (const float*)d_in[2];
    const float* rw   = (const float*)d_in[3];
    const float* ow   = (const float*)d_in[4];
    const float* sdec = (const float*)d_in[5];
    const float* sfst = (const float*)d_in[6];
    float* out        = (float*)d_out;

    __half *xs, *prod, *wh, *k, *v, *sr, *v1;
    cudaGetSymbolAddress((void**)&xs,   g_xsh);
    cudaGetSymbolAddress((void**)&prod, g_prod);
    cudaGetSymbolAddress((void**)&wh,   g_w);
    cudaGetSymbolAddress((void**)&k,    g_k);
    cudaGetSymbolAddress((void**)&v,    g_v);
    cudaGetSymbolAddress((void**)&sr,   g_sr);
    cudaGetSymbolAddress((void**)&v1,   g_v1);

    cudaFuncSetAttribute(gemm_kvsr_kernel, cudaFuncAttributeMaxDynamicSharedMemorySize, G_DS);
    cudaFuncSetAttribute(gemm_out_kernel,  cudaFuncAttributeMaxDynamicSharedMemorySize, G_DS);

    // 1) merged prep: gather + weight converts in one launch
    prep_kernel<<<GATHER_BLKS + WCONV_BLKS, 256>>>(x, xs, kw, vw, rw, ow, wh);

    // 2) fused k/v/sr GEMM (one launch, N=2304)
    {
        dim3 grid(18, MM / G_BM);
        gemm_kvsr_kernel<<<grid, 128, G_DS>>>(xs, wh, k, v, sr);
    }

    // 3) WKV: summary1 -> scan1 -> mid (replay1 + summary2 fused) -> scan2 ->
    //    replay2 (+ sr multiply, writes prod).
    {
        dim3 gseg(LANES2 / 128, NSEG);
        int  gscan = LANES / 128;
        wkv_summary_kernel<0><<<gseg, 128>>>(k, v, sdec);
        wkv_scan_kernel<0><<<gscan, 128>>>(sdec);
        wkv_mid_kernel<<<gseg, 128>>>(k, v, sdec, sfst, v1);
        wkv_scan_kernel<1><<<gscan, 128>>>(sdec);
        wkv_replay2_kernel<<<gseg, 128>>>(k, v1, sdec, sfst, sr, prod);
    }

    // 4) out = prod @ ow^T
    {
        dim3 grid(CC / G_BN, MM / G_BM);
        gemm_out_kernel<<<grid, 128, G_DS>>>(prod, wh + 3 * (size_t)CC * CC, out);
    }
}